// round 1
// baseline (speedup 1.0000x reference)
#include <cuda_runtime.h>
#include <math.h>
#include <float.h>

#define SEQ   2048
#define HID   4096
#define NH    32
#define HD    128
#define QKVN  12288   // 3*HID

// ---------------- scratch (no cudaMalloc allowed) ----------------
__device__ float g_qkv[SEQ * QKVN];           // ~100 MB
__device__ float g_scores[(size_t)NH * SEQ * SEQ]; // ~537 MB (probs in-place)
__device__ float g_attn[SEQ * HID];           // ~33 MB

// ---------------- generic NN SGEMM + bias: C = A@B + bias ----------------
// A: [M,K] row-major, B: [K,N] row-major, C: [M,N]. M,N mult of 128, K mult of 8.
__global__ __launch_bounds__(256)
void sgemm_bias(const float* __restrict__ A, const float* __restrict__ B,
                const float* __restrict__ bias, float* __restrict__ C,
                int M, int N, int K) {
    __shared__ float As[8][128];
    __shared__ float Bs[8][128];
    const int bx = blockIdx.x, by = blockIdx.y;
    const int tid = threadIdx.x;
    const int tx = tid % 16, ty = tid / 16;

    const float* Ap = A + (size_t)by * 128 * K;
    const float* Bp = B + bx * 128;

    const int a_row = tid >> 1;          // 0..127
    const int a_col = (tid & 1) * 4;     // 0 or 4
    const int b_row = tid >> 5;          // 0..7
    const int b_col = (tid & 31) * 4;    // 0..124

    float acc[8][8] = {};
    for (int k0 = 0; k0 < K; k0 += 8) {
        float4 av = *(const float4*)(Ap + (size_t)a_row * K + k0 + a_col);
        As[a_col + 0][a_row] = av.x;
        As[a_col + 1][a_row] = av.y;
        As[a_col + 2][a_row] = av.z;
        As[a_col + 3][a_row] = av.w;
        float4 bv = *(const float4*)(Bp + (size_t)(k0 + b_row) * N + b_col);
        *(float4*)&Bs[b_row][b_col] = bv;
        __syncthreads();
#pragma unroll
        for (int kk = 0; kk < 8; kk++) {
            float af[8], bf[8];
#pragma unroll
            for (int i = 0; i < 8; i++) af[i] = As[kk][ty * 8 + i];
#pragma unroll
            for (int j = 0; j < 8; j++) bf[j] = Bs[kk][tx * 8 + j];
#pragma unroll
            for (int i = 0; i < 8; i++)
#pragma unroll
                for (int j = 0; j < 8; j++) acc[i][j] += af[i] * bf[j];
        }
        __syncthreads();
    }
#pragma unroll
    for (int i = 0; i < 8; i++) {
        int row = by * 128 + ty * 8 + i;
#pragma unroll
        for (int j = 0; j < 8; j++) {
            int col = bx * 128 + tx * 8 + j;
            C[(size_t)row * N + col] = acc[i][j] + bias[col];
        }
    }
}

// ---------------- RoPE in place on q and k halves of g_qkv ----------------
__global__ __launch_bounds__(256)
void rope_kernel(float* __restrict__ qkv) {
    int idx = blockIdx.x * blockDim.x + threadIdx.x;   // SEQ*NH*64 threads
    if (idx >= SEQ * NH * 64) return;
    int i = idx & 63;
    int h = (idx >> 6) & 31;
    int s = idx >> 11;
    // inv_freq computed in double -> correctly-rounded fp32 (tracks jax fp32 pow)
    double invf = exp(-log(10000.0) * (double)(2 * i) / 128.0);
    double f = (double)s * invf;
    float c = (float)cos(f);
    float sn = (float)sin(f);
    size_t base = (size_t)s * QKVN + h * HD;
    float* q = qkv + base;
    float* k = qkv + base + HID;
    float q1 = q[i], q2 = q[i + 64];
    q[i]      = q1 * c - q2 * sn;
    q[i + 64] = q2 * c + q1 * sn;
    float k1 = k[i], k2 = k[i + 64];
    k[i]      = k1 * c - k2 * sn;
    k[i + 64] = k2 * c + k1 * sn;
}

// ---------------- scores = scale * Q @ K^T (per head, causal skip) -------
// q rows at stride QKVN (offset h*HD), k rows at stride QKVN (offset HID + h*HD).
__global__ __launch_bounds__(256)
void scores_kernel(const float* __restrict__ qkv, float* __restrict__ scores) {
    const int bx = blockIdx.x;   // key tile
    const int by = blockIdx.y;   // query tile
    const int h  = blockIdx.z;
    if (bx > by) return;         // fully above diagonal -> never read
    const float scale = 0.08838834764831843f;  // 1/sqrt(128)

    __shared__ float As[8][128];
    __shared__ float Bs[8][128];
    const int tid = threadIdx.x;
    const int tx = tid % 16, ty = tid / 16;
    const int l_row = tid >> 1;
    const int l_col = (tid & 1) * 4;

    const float* Aq = qkv + (size_t)h * HD;             // q
    const float* Bk = qkv + HID + (size_t)h * HD;       // k

    float acc[8][8] = {};
    for (int k0 = 0; k0 < HD; k0 += 8) {
        float4 av = *(const float4*)(Aq + (size_t)(by * 128 + l_row) * QKVN + k0 + l_col);
        As[l_col + 0][l_row] = av.x;
        As[l_col + 1][l_row] = av.y;
        As[l_col + 2][l_row] = av.z;
        As[l_col + 3][l_row] = av.w;
        float4 bv = *(const float4*)(Bk + (size_t)(bx * 128 + l_row) * QKVN + k0 + l_col);
        Bs[l_col + 0][l_row] = bv.x;
        Bs[l_col + 1][l_row] = bv.y;
        Bs[l_col + 2][l_row] = bv.z;
        Bs[l_col + 3][l_row] = bv.w;
        __syncthreads();
#pragma unroll
        for (int kk = 0; kk < 8; kk++) {
            float af[8], bf[8];
#pragma unroll
            for (int i = 0; i < 8; i++) af[i] = As[kk][ty * 8 + i];
#pragma unroll
            for (int j = 0; j < 8; j++) bf[j] = Bs[kk][tx * 8 + j];
#pragma unroll
            for (int i = 0; i < 8; i++)
#pragma unroll
                for (int j = 0; j < 8; j++) acc[i][j] += af[i] * bf[j];
        }
        __syncthreads();
    }
    float* out = scores + (size_t)h * SEQ * SEQ;
#pragma unroll
    for (int i = 0; i < 8; i++) {
        int row = by * 128 + ty * 8 + i;
#pragma unroll
        for (int j = 0; j < 8; j++) {
            int col = bx * 128 + tx * 8 + j;
            if (col <= row) out[(size_t)row * SEQ + col] = acc[i][j] * scale;
        }
    }
}

// ---------------- softmax per (head,row), in place; zeros beyond i -------
__global__ __launch_bounds__(256)
void softmax_kernel(float* __restrict__ scores) {
    const int i = blockIdx.x;
    const int h = blockIdx.y;
    float* row = scores + (size_t)h * SEQ * SEQ + (size_t)i * SEQ;
    const int n = i + 1;
    const int tid = threadIdx.x;
    __shared__ float red[256];

    float m = -FLT_MAX;
    for (int j = tid; j < n; j += 256) m = fmaxf(m, row[j]);
    red[tid] = m; __syncthreads();
    for (int s2 = 128; s2 > 0; s2 >>= 1) {
        if (tid < s2) red[tid] = fmaxf(red[tid], red[tid + s2]);
        __syncthreads();
    }
    m = red[0]; __syncthreads();

    float sum = 0.f;
    for (int j = tid; j < n; j += 256) sum += expf(row[j] - m);
    red[tid] = sum; __syncthreads();
    for (int s2 = 128; s2 > 0; s2 >>= 1) {
        if (tid < s2) red[tid] += red[tid + s2];
        __syncthreads();
    }
    float inv = 1.0f / red[0];

    for (int j = tid; j < n; j += 256) row[j] = expf(row[j] - m) * inv;
    for (int j = n + tid; j < SEQ; j += 256) row[j] = 0.f;
}

// ---------------- out = P @ V per head (K truncated by causality) --------
__global__ __launch_bounds__(256)
void pv_kernel(const float* __restrict__ scores, const float* __restrict__ qkv,
               float* __restrict__ attn) {
    const int by = blockIdx.y;   // query tile (M)
    const int h  = blockIdx.z;
    __shared__ float As[8][128];
    __shared__ float Bs[8][128];
    const int tid = threadIdx.x;
    const int tx = tid % 16, ty = tid / 16;
    const int a_row = tid >> 1;
    const int a_col = (tid & 1) * 4;
    const int b_row = tid >> 5;
    const int b_col = (tid & 31) * 4;

    const float* P = scores + (size_t)h * SEQ * SEQ;           // [SEQ, SEQ]
    const float* V = qkv + 2 * HID + (size_t)h * HD;           // rows stride QKVN

    const int kmax = (by + 1) * 128;   // P is zero beyond the diagonal
    float acc[8][8] = {};
    for (int k0 = 0; k0 < kmax; k0 += 8) {
        float4 av = *(const float4*)(P + (size_t)(by * 128 + a_row) * SEQ + k0 + a_col);
        As[a_col + 0][a_row] = av.x;
        As[a_col + 1][a_row] = av.y;
        As[a_col + 2][a_row] = av.z;
        As[a_col + 3][a_row] = av.w;
        float4 bv = *(const float4*)(V + (size_t)(k0 + b_row) * QKVN + b_col);
        *(float4*)&Bs[b_row][b_col] = bv;
        __syncthreads();
#pragma unroll
        for (int kk = 0; kk < 8; kk++) {
            float af[8], bf[8];
#pragma unroll
            for (int i = 0; i < 8; i++) af[i] = As[kk][ty * 8 + i];
#pragma unroll
            for (int j = 0; j < 8; j++) bf[j] = Bs[kk][tx * 8 + j];
#pragma unroll
            for (int i = 0; i < 8; i++)
#pragma unroll
                for (int j = 0; j < 8; j++) acc[i][j] += af[i] * bf[j];
        }
        __syncthreads();
    }
#pragma unroll
    for (int i = 0; i < 8; i++) {
        int row = by * 128 + ty * 8 + i;
#pragma unroll
        for (int j = 0; j < 8; j++) {
            int col = tx * 8 + j;   // < 128 = HD
            attn[(size_t)row * HID + h * HD + col] = acc[i][j];
        }
    }
}

// ---------------- launch ----------------
extern "C" void kernel_launch(void* const* d_in, const int* in_sizes, int n_in,
                              void* d_out, int out_size) {
    const float* hs   = (const float*)d_in[1];
    const float* Wqkv = (const float*)d_in[2];
    const float* bqkv = (const float*)d_in[3];
    const float* Wo   = (const float*)d_in[4];
    const float* bo   = (const float*)d_in[5];
    float* out = (float*)d_out;

    float *qkv, *scores, *attn;
    cudaGetSymbolAddress((void**)&qkv,    g_qkv);
    cudaGetSymbolAddress((void**)&scores, g_scores);
    cudaGetSymbolAddress((void**)&attn,   g_attn);

    // 1) QKV = hs @ Wqkv + bqkv
    sgemm_bias<<<dim3(QKVN / 128, SEQ / 128), 256>>>(hs, Wqkv, bqkv, qkv, SEQ, QKVN, HID);
    // 2) RoPE on q,k
    rope_kernel<<<(SEQ * NH * 64 + 255) / 256, 256>>>(qkv);
    // 3) scores = scale * Q K^T (causal)
    scores_kernel<<<dim3(SEQ / 128, SEQ / 128, NH), 256>>>(qkv, scores);
    // 4) softmax rows in place
    softmax_kernel<<<dim3(SEQ, NH), 256>>>(scores);
    // 5) attn = P @ V
    pv_kernel<<<dim3(1, SEQ / 128, NH), 256>>>(scores, qkv, attn);
    // 6) out = attn @ Wo + bo
    sgemm_bias<<<dim3(HID / 128, SEQ / 128), 256>>>(attn, Wo, bo, out, SEQ, HID, HID);
}

// round 2
// speedup vs baseline: 1.4991x; 1.4991x over previous
#include <cuda_runtime.h>
#include <mma.h>
#include <math.h>
#include <float.h>

using namespace nvcuda;

#define SEQ   2048
#define HID   4096
#define NH    32
#define HD    128
#define QKVN  12288   // 3*HID

// ---------------- scratch (no cudaMalloc allowed) ----------------
__device__ float g_qkv[SEQ * QKVN];                 // ~100 MB
__device__ float g_scores[(size_t)NH * SEQ * SEQ];  // ~537 MB (probs in-place)
__device__ float g_attn[SEQ * HID];                 // ~33 MB

// ================= tf32 tensor-core GEMM + bias =================
// C = A@B + bias. A:[M,K] rm, B:[K,N] rm, C:[M,N]. M,N mult 128, K mult 16.
#define BM 128
#define BN 128
#define BK 16
#define A_LD (BK + 8)    // 24 floats -> 96B row stride (16B aligned)
#define B_LD (BN + 4)    // 132 floats -> 528B row stride (16B aligned)

__device__ __forceinline__ void cp_async16(void* smem_dst, const void* gsrc) {
    unsigned s = (unsigned)__cvta_generic_to_shared(smem_dst);
    asm volatile("cp.async.cg.shared.global [%0], [%1], 16;\n" :: "r"(s), "l"(gsrc));
}
__device__ __forceinline__ void cp_commit() {
    asm volatile("cp.async.commit_group;\n");
}
template <int N> __device__ __forceinline__ void cp_wait() {
    asm volatile("cp.async.wait_group %0;\n" :: "n"(N));
}

__global__ __launch_bounds__(256)
void gemm_tf32_bias(const float* __restrict__ A, const float* __restrict__ B,
                    const float* __restrict__ bias, float* __restrict__ C,
                    int M, int N, int K) {
    __shared__ __align__(16) float As[2][BM][A_LD];   // 24576 B
    __shared__ __align__(16) float Bs[2][BK][B_LD];   // 16896 B

    const int tid  = threadIdx.x;
    const int wid  = tid >> 5;
    const int lane = tid & 31;
    const int warp_m = (wid >> 1) * 32;   // 0,32,64,96
    const int warp_n = (wid & 1) * 64;    // 0,64

    const int bx = blockIdx.x, by = blockIdx.y;

    // global-load mapping
    const int a_row = tid >> 2;            // 0..63 (+64 second pass)
    const int a_col = (tid & 3) * 4;       // 0,4,8,12
    const int b_row = tid >> 5;            // 0..7 (+8 second pass)
    const int b_col = (tid & 31) * 4;      // 0..124

    const float* Ag = A + (size_t)(by * BM) * K;
    const float* Bg = B + bx * BN;

    wmma::fragment<wmma::accumulator, 16, 16, 8, float> acc[2][4];
#pragma unroll
    for (int i = 0; i < 2; i++)
#pragma unroll
        for (int j = 0; j < 4; j++) wmma::fill_fragment(acc[i][j], 0.0f);

    const int T = K / BK;

    // prefetch tile 0 -> buf 0
    {
        const int k0 = 0;
#pragma unroll
        for (int p = 0; p < 2; p++) {
            int r = a_row + p * 64;
            cp_async16(&As[0][r][a_col], Ag + (size_t)r * K + k0 + a_col);
        }
#pragma unroll
        for (int p = 0; p < 2; p++) {
            int r = b_row + p * 8;
            cp_async16(&Bs[0][r][b_col], Bg + (size_t)(k0 + r) * N + b_col);
        }
        cp_commit();
    }

    for (int t = 0; t < T; t++) {
        const int cur = t & 1;
        if (t + 1 < T) {
            const int k0 = (t + 1) * BK;
            const int nxt = cur ^ 1;
#pragma unroll
            for (int p = 0; p < 2; p++) {
                int r = a_row + p * 64;
                cp_async16(&As[nxt][r][a_col], Ag + (size_t)r * K + k0 + a_col);
            }
#pragma unroll
            for (int p = 0; p < 2; p++) {
                int r = b_row + p * 8;
                cp_async16(&Bs[nxt][r][b_col], Bg + (size_t)(k0 + r) * N + b_col);
            }
            cp_commit();
            cp_wait<1>();
        } else {
            cp_wait<0>();
        }
        __syncthreads();

#pragma unroll
        for (int kk = 0; kk < BK; kk += 8) {
            wmma::fragment<wmma::matrix_a, 16, 16, 8, wmma::precision::tf32, wmma::row_major> af[2];
#pragma unroll
            for (int i = 0; i < 2; i++) {
                wmma::load_matrix_sync(af[i], &As[cur][warp_m + i * 16][kk], A_LD);
#pragma unroll
                for (int e = 0; e < af[i].num_elements; e++)
                    af[i].x[e] = wmma::__float_to_tf32(af[i].x[e]);
            }
            wmma::fragment<wmma::matrix_b, 16, 16, 8, wmma::precision::tf32, wmma::row_major> bf[4];
#pragma unroll
            for (int j = 0; j < 4; j++) {
                wmma::load_matrix_sync(bf[j], &Bs[cur][kk][warp_n + j * 16], B_LD);
#pragma unroll
                for (int e = 0; e < bf[j].num_elements; e++)
                    bf[j].x[e] = wmma::__float_to_tf32(bf[j].x[e]);
            }
#pragma unroll
            for (int i = 0; i < 2; i++)
#pragma unroll
                for (int j = 0; j < 4; j++)
                    wmma::mma_sync(acc[i][j], af[i], bf[j], acc[i][j]);
        }
        __syncthreads();
    }

    // epilogue: stage each 16x16 accum patch through smem (aliased on As), add bias
    float* epi = &As[0][0][0] + wid * 256;   // 256 floats per warp, 1KB aligned
#pragma unroll
    for (int i = 0; i < 2; i++) {
#pragma unroll
        for (int j = 0; j < 4; j++) {
            wmma::store_matrix_sync(epi, acc[i][j], 16, wmma::mem_row_major);
            __syncwarp();
            int r = lane >> 1;
            int c = (lane & 1) * 8;
            int grow = by * BM + warp_m + i * 16 + r;
            int gcol = bx * BN + warp_n + j * 16 + c;
            float4 v0 = *(float4*)&epi[r * 16 + c];
            float4 v1 = *(float4*)&epi[r * 16 + c + 4];
            const float* bp = bias + gcol;
            v0.x += bp[0]; v0.y += bp[1]; v0.z += bp[2]; v0.w += bp[3];
            v1.x += bp[4]; v1.y += bp[5]; v1.z += bp[6]; v1.w += bp[7];
            float* cp = C + (size_t)grow * N + gcol;
            *(float4*)cp = v0;
            *(float4*)(cp + 4) = v1;
            __syncwarp();
        }
    }
}

// ---------------- RoPE in place on q and k halves of g_qkv ----------------
__global__ __launch_bounds__(256)
void rope_kernel(float* __restrict__ qkv) {
    int idx = blockIdx.x * blockDim.x + threadIdx.x;
    if (idx >= SEQ * NH * 64) return;
    int i = idx & 63;
    int h = (idx >> 6) & 31;
    int s = idx >> 11;
    double invf = exp(-log(10000.0) * (double)(2 * i) / 128.0);
    double f = (double)s * invf;
    float c  = (float)cos(f);
    float sn = (float)sin(f);
    size_t base = (size_t)s * QKVN + h * HD;
    float* q = qkv + base;
    float* k = qkv + base + HID;
    float q1 = q[i], q2 = q[i + 64];
    q[i]      = q1 * c - q2 * sn;
    q[i + 64] = q2 * c + q1 * sn;
    float k1 = k[i], k2 = k[i + 64];
    k[i]      = k1 * c - k2 * sn;
    k[i + 64] = k2 * c + k1 * sn;
}

// ---------------- scores = scale * Q @ K^T (per head, causal skip) -------
__global__ __launch_bounds__(256)
void scores_kernel(const float* __restrict__ qkv, float* __restrict__ scores) {
    const int bx = blockIdx.x;
    const int by = blockIdx.y;
    const int h  = blockIdx.z;
    if (bx > by) return;
    const float scale = 0.08838834764831843f;

    __shared__ float As2[8][128];
    __shared__ float Bs2[8][128];
    const int tid = threadIdx.x;
    const int tx = tid % 16, ty = tid / 16;
    const int l_row = tid >> 1;
    const int l_col = (tid & 1) * 4;

    const float* Aq = qkv + (size_t)h * HD;
    const float* Bk = qkv + HID + (size_t)h * HD;

    float acc[8][8] = {};
    for (int k0 = 0; k0 < HD; k0 += 8) {
        float4 av = *(const float4*)(Aq + (size_t)(by * 128 + l_row) * QKVN + k0 + l_col);
        As2[l_col + 0][l_row] = av.x;
        As2[l_col + 1][l_row] = av.y;
        As2[l_col + 2][l_row] = av.z;
        As2[l_col + 3][l_row] = av.w;
        float4 bv = *(const float4*)(Bk + (size_t)(bx * 128 + l_row) * QKVN + k0 + l_col);
        Bs2[l_col + 0][l_row] = bv.x;
        Bs2[l_col + 1][l_row] = bv.y;
        Bs2[l_col + 2][l_row] = bv.z;
        Bs2[l_col + 3][l_row] = bv.w;
        __syncthreads();
#pragma unroll
        for (int kk = 0; kk < 8; kk++) {
            float af[8], bf[8];
#pragma unroll
            for (int i = 0; i < 8; i++) af[i] = As2[kk][ty * 8 + i];
#pragma unroll
            for (int j = 0; j < 8; j++) bf[j] = Bs2[kk][tx * 8 + j];
#pragma unroll
            for (int i = 0; i < 8; i++)
#pragma unroll
                for (int j = 0; j < 8; j++) acc[i][j] += af[i] * bf[j];
        }
        __syncthreads();
    }
    float* out = scores + (size_t)h * SEQ * SEQ;
#pragma unroll
    for (int i = 0; i < 8; i++) {
        int row = by * 128 + ty * 8 + i;
#pragma unroll
        for (int j = 0; j < 8; j++) {
            int col = bx * 128 + tx * 8 + j;
            if (col <= row) out[(size_t)row * SEQ + col] = acc[i][j] * scale;
        }
    }
}

// ---------------- softmax per (head,row), in place; zeros beyond i -------
__global__ __launch_bounds__(256)
void softmax_kernel(float* __restrict__ scores) {
    const int i = blockIdx.x;
    const int h = blockIdx.y;
    float* row = scores + (size_t)h * SEQ * SEQ + (size_t)i * SEQ;
    const int n = i + 1;
    const int tid = threadIdx.x;
    __shared__ float red[256];

    float m = -FLT_MAX;
    for (int j = tid; j < n; j += 256) m = fmaxf(m, row[j]);
    red[tid] = m; __syncthreads();
    for (int s2 = 128; s2 > 0; s2 >>= 1) {
        if (tid < s2) red[tid] = fmaxf(red[tid], red[tid + s2]);
        __syncthreads();
    }
    m = red[0]; __syncthreads();

    float sum = 0.f;
    for (int j = tid; j < n; j += 256) sum += expf(row[j] - m);
    red[tid] = sum; __syncthreads();
    for (int s2 = 128; s2 > 0; s2 >>= 1) {
        if (tid < s2) red[tid] += red[tid + s2];
        __syncthreads();
    }
    float inv = 1.0f / red[0];

    for (int j = tid; j < n; j += 256) row[j] = expf(row[j] - m) * inv;
    for (int j = n + tid; j < SEQ; j += 256) row[j] = 0.f;
}

// ---------------- out = P @ V per head (K truncated by causality) --------
__global__ __launch_bounds__(256)
void pv_kernel(const float* __restrict__ scores, const float* __restrict__ qkv,
               float* __restrict__ attn) {
    const int by = blockIdx.y;
    const int h  = blockIdx.z;
    __shared__ float As2[8][128];
    __shared__ float Bs2[8][128];
    const int tid = threadIdx.x;
    const int tx = tid % 16, ty = tid / 16;
    const int a_row = tid >> 1;
    const int a_col = (tid & 1) * 4;
    const int b_row = tid >> 5;
    const int b_col = (tid & 31) * 4;

    const float* P = scores + (size_t)h * SEQ * SEQ;
    const float* V = qkv + 2 * HID + (size_t)h * HD;

    const int kmax = (by + 1) * 128;
    float acc[8][8] = {};
    for (int k0 = 0; k0 < kmax; k0 += 8) {
        float4 av = *(const float4*)(P + (size_t)(by * 128 + a_row) * SEQ + k0 + a_col);
        As2[a_col + 0][a_row] = av.x;
        As2[a_col + 1][a_row] = av.y;
        As2[a_col + 2][a_row] = av.z;
        As2[a_col + 3][a_row] = av.w;
        float4 bv = *(const float4*)(V + (size_t)(k0 + b_row) * QKVN + b_col);
        *(float4*)&Bs2[b_row][b_col] = bv;
        __syncthreads();
#pragma unroll
        for (int kk = 0; kk < 8; kk++) {
            float af[8], bf[8];
#pragma unroll
            for (int i = 0; i < 8; i++) af[i] = As2[kk][ty * 8 + i];
#pragma unroll
            for (int j = 0; j < 8; j++) bf[j] = Bs2[kk][tx * 8 + j];
#pragma unroll
            for (int i = 0; i < 8; i++)
#pragma unroll
                for (int j = 0; j < 8; j++) acc[i][j] += af[i] * bf[j];
        }
        __syncthreads();
    }
#pragma unroll
    for (int i = 0; i < 8; i++) {
        int row = by * 128 + ty * 8 + i;
#pragma unroll
        for (int j = 0; j < 8; j++) {
            int col = tx * 8 + j;
            attn[(size_t)row * HID + h * HD + col] = acc[i][j];
        }
    }
}

// ---------------- launch ----------------
extern "C" void kernel_launch(void* const* d_in, const int* in_sizes, int n_in,
                              void* d_out, int out_size) {
    const float* hs   = (const float*)d_in[1];
    const float* Wqkv = (const float*)d_in[2];
    const float* bqkv = (const float*)d_in[3];
    const float* Wo   = (const float*)d_in[4];
    const float* bo   = (const float*)d_in[5];
    float* out = (float*)d_out;

    float *qkv, *scores, *attn;
    cudaGetSymbolAddress((void**)&qkv,    g_qkv);
    cudaGetSymbolAddress((void**)&scores, g_scores);
    cudaGetSymbolAddress((void**)&attn,   g_attn);

    // 1) QKV = hs @ Wqkv + bqkv   (tf32 tensor cores)
    gemm_tf32_bias<<<dim3(QKVN / BN, SEQ / BM), 256>>>(hs, Wqkv, bqkv, qkv, SEQ, QKVN, HID);
    // 2) RoPE on q,k
    rope_kernel<<<(SEQ * NH * 64 + 255) / 256, 256>>>(qkv);
    // 3) scores = scale * Q K^T (causal, fp32)
    scores_kernel<<<dim3(SEQ / 128, SEQ / 128, NH), 256>>>(qkv, scores);
    // 4) softmax rows in place
    softmax_kernel<<<dim3(SEQ, NH), 256>>>(scores);
    // 5) attn = P @ V (fp32)
    pv_kernel<<<dim3(1, SEQ / 128, NH), 256>>>(scores, qkv, attn);
    // 6) out = attn @ Wo + bo   (tf32 tensor cores)
    gemm_tf32_bias<<<dim3(HID / BN, SEQ / BM), 256>>>(attn, Wo, bo, out, SEQ, HID, HID);
}

// round 3
// speedup vs baseline: 1.7977x; 1.1992x over previous
#include <cuda_runtime.h>
#include <mma.h>
#include <math.h>
#include <float.h>

using namespace nvcuda;

#define SEQ   2048
#define HID   4096
#define NH    32
#define HD    128
#define QKVN  12288   // 3*HID

// ---------------- scratch (no cudaMalloc allowed) ----------------
__device__ float g_qkv[SEQ * QKVN];    // ~100 MB
__device__ float g_attn[SEQ * HID];    // ~33 MB

// ================= tf32 tensor-core GEMM + bias =================
#define BM 128
#define BN 128
#define BK 16
#define A_LD (BK + 8)
#define B_LD (BN + 4)

__device__ __forceinline__ void cp_async16(void* smem_dst, const void* gsrc) {
    unsigned s = (unsigned)__cvta_generic_to_shared(smem_dst);
    asm volatile("cp.async.cg.shared.global [%0], [%1], 16;\n" :: "r"(s), "l"(gsrc));
}
__device__ __forceinline__ void cp_commit() {
    asm volatile("cp.async.commit_group;\n");
}
template <int N> __device__ __forceinline__ void cp_wait() {
    asm volatile("cp.async.wait_group %0;\n" :: "n"(N));
}

__global__ __launch_bounds__(256)
void gemm_tf32_bias(const float* __restrict__ A, const float* __restrict__ B,
                    const float* __restrict__ bias, float* __restrict__ C,
                    int M, int N, int K) {
    __shared__ __align__(16) float As[2][BM][A_LD];
    __shared__ __align__(16) float Bs[2][BK][B_LD];

    const int tid  = threadIdx.x;
    const int wid  = tid >> 5;
    const int lane = tid & 31;
    const int warp_m = (wid >> 1) * 32;
    const int warp_n = (wid & 1) * 64;

    const int bx = blockIdx.x, by = blockIdx.y;

    const int a_row = tid >> 2;
    const int a_col = (tid & 3) * 4;
    const int b_row = tid >> 5;
    const int b_col = (tid & 31) * 4;

    const float* Ag = A + (size_t)(by * BM) * K;
    const float* Bg = B + bx * BN;

    wmma::fragment<wmma::accumulator, 16, 16, 8, float> acc[2][4];
#pragma unroll
    for (int i = 0; i < 2; i++)
#pragma unroll
        for (int j = 0; j < 4; j++) wmma::fill_fragment(acc[i][j], 0.0f);

    const int T = K / BK;
    {
#pragma unroll
        for (int p = 0; p < 2; p++) {
            int r = a_row + p * 64;
            cp_async16(&As[0][r][a_col], Ag + (size_t)r * K + a_col);
        }
#pragma unroll
        for (int p = 0; p < 2; p++) {
            int r = b_row + p * 8;
            cp_async16(&Bs[0][r][b_col], Bg + (size_t)r * N + b_col);
        }
        cp_commit();
    }

    for (int t = 0; t < T; t++) {
        const int cur = t & 1;
        if (t + 1 < T) {
            const int k0 = (t + 1) * BK;
            const int nxt = cur ^ 1;
#pragma unroll
            for (int p = 0; p < 2; p++) {
                int r = a_row + p * 64;
                cp_async16(&As[nxt][r][a_col], Ag + (size_t)r * K + k0 + a_col);
            }
#pragma unroll
            for (int p = 0; p < 2; p++) {
                int r = b_row + p * 8;
                cp_async16(&Bs[nxt][r][b_col], Bg + (size_t)(k0 + r) * N + b_col);
            }
            cp_commit();
            cp_wait<1>();
        } else {
            cp_wait<0>();
        }
        __syncthreads();

#pragma unroll
        for (int kk = 0; kk < BK; kk += 8) {
            wmma::fragment<wmma::matrix_a, 16, 16, 8, wmma::precision::tf32, wmma::row_major> af[2];
#pragma unroll
            for (int i = 0; i < 2; i++) {
                wmma::load_matrix_sync(af[i], &As[cur][warp_m + i * 16][kk], A_LD);
#pragma unroll
                for (int e = 0; e < af[i].num_elements; e++)
                    af[i].x[e] = wmma::__float_to_tf32(af[i].x[e]);
            }
            wmma::fragment<wmma::matrix_b, 16, 16, 8, wmma::precision::tf32, wmma::row_major> bf[4];
#pragma unroll
            for (int j = 0; j < 4; j++) {
                wmma::load_matrix_sync(bf[j], &Bs[cur][kk][warp_n + j * 16], B_LD);
#pragma unroll
                for (int e = 0; e < bf[j].num_elements; e++)
                    bf[j].x[e] = wmma::__float_to_tf32(bf[j].x[e]);
            }
#pragma unroll
            for (int i = 0; i < 2; i++)
#pragma unroll
                for (int j = 0; j < 4; j++)
                    wmma::mma_sync(acc[i][j], af[i], bf[j], acc[i][j]);
        }
        __syncthreads();
    }

    float* epi = &As[0][0][0] + wid * 256;
#pragma unroll
    for (int i = 0; i < 2; i++) {
#pragma unroll
        for (int j = 0; j < 4; j++) {
            wmma::store_matrix_sync(epi, acc[i][j], 16, wmma::mem_row_major);
            __syncwarp();
            int r = lane >> 1;
            int c = (lane & 1) * 8;
            int grow = by * BM + warp_m + i * 16 + r;
            int gcol = bx * BN + warp_n + j * 16 + c;
            float4 v0 = *(float4*)&epi[r * 16 + c];
            float4 v1 = *(float4*)&epi[r * 16 + c + 4];
            const float* bp = bias + gcol;
            v0.x += bp[0]; v0.y += bp[1]; v0.z += bp[2]; v0.w += bp[3];
            v1.x += bp[4]; v1.y += bp[5]; v1.z += bp[6]; v1.w += bp[7];
            float* cp = C + (size_t)grow * N + gcol;
            *(float4*)cp = v0;
            *(float4*)(cp + 4) = v1;
            __syncwarp();
        }
    }
}

// ---------------- RoPE in place on q and k halves of g_qkv ----------------
__global__ __launch_bounds__(256)
void rope_kernel(float* __restrict__ qkv) {
    int idx = blockIdx.x * blockDim.x + threadIdx.x;
    if (idx >= SEQ * NH * 64) return;
    int i = idx & 63;
    int h = (idx >> 6) & 31;
    int s = idx >> 11;
    double invf = exp(-log(10000.0) * (double)(2 * i) / 128.0);
    double f = (double)s * invf;
    float c  = (float)cos(f);
    float sn = (float)sin(f);
    size_t base = (size_t)s * QKVN + h * HD;
    float* q = qkv + base;
    float* k = qkv + base + HID;
    float q1 = q[i], q2 = q[i + 64];
    q[i]      = q1 * c - q2 * sn;
    q[i + 64] = q2 * c + q1 * sn;
    float k1 = k[i], k2 = k[i + 64];
    k[i]      = k1 * c - k2 * sn;
    k[i + 64] = k2 * c + k1 * sn;
}

// ================== fused flash attention (tf32 mma) ==================
// Block: 128 query rows x 1 head. 8 warps, each owns 16 query rows.
// Iterate 64-key tiles up to causal diagonal. Online softmax in fp32.
// Smem layouts use a column-pair permutation so MMA operand loads are 64-bit:
//   within each 8-col group, col c -> pos 2*(c&3) + (c>>2)  (c, c+4 adjacent)

#define Q_LD 132
#define K_LD 132
#define V_LD 136
#define P_LD 68
#define SM_Q 0
#define SM_K (128 * Q_LD)
#define SM_V (SM_K + 64 * K_LD)
#define SM_P (SM_V + 64 * V_LD)
#define FA_SMEM_FLOATS (SM_P + 8 * 16 * P_LD)
#define FA_SMEM_BYTES (FA_SMEM_FLOATS * 4)   // 171008

__device__ __forceinline__ float t32(float x) { return wmma::__float_to_tf32(x); }

__device__ __forceinline__ void mma_tf32(float* d, unsigned a0, unsigned a1,
                                         unsigned a2, unsigned a3,
                                         unsigned b0, unsigned b1) {
    asm volatile(
        "mma.sync.aligned.m16n8k8.row.col.f32.tf32.tf32.f32 "
        "{%0,%1,%2,%3}, {%4,%5,%6,%7}, {%8,%9}, {%0,%1,%2,%3};\n"
        : "+f"(d[0]), "+f"(d[1]), "+f"(d[2]), "+f"(d[3])
        : "r"(a0), "r"(a1), "r"(a2), "r"(a3), "r"(b0), "r"(b1));
}

__global__ __launch_bounds__(256, 1)
void flash_kernel(const float* __restrict__ qkv, float* __restrict__ attn) {
    extern __shared__ float sm[];
    const int h  = blockIdx.y;
    const int by = (gridDim.x - 1) - blockIdx.x;   // heavy tiles first
    const int tid  = threadIdx.x;
    const int wid  = tid >> 5;
    const int lane = tid & 31;
    const int g = lane >> 2;     // row group within mma
    const int c = lane & 3;      // col group within mma

    float* Qs = sm + SM_Q;
    float* Ks = sm + SM_K;
    float* Vs = sm + SM_V;
    float* Ps = sm + SM_P + wid * 16 * P_LD;   // warp-private

    const float scale = 0.08838834764831843f;  // 1/sqrt(128)
    const float* Qg = qkv + (size_t)h * HD;
    const float* Kg = qkv + HID + (size_t)h * HD;
    const float* Vg = qkv + 2 * HID + (size_t)h * HD;

    // ---- load Q tile once (scaled, tf32-rounded, permuted cols) ----
    for (int i = tid; i < 128 * 32; i += 256) {
        int r  = i >> 5;
        int c4 = (i & 31) << 2;
        float4 v = *(const float4*)(Qg + (size_t)(by * 128 + r) * QKVN + c4);
        int base = c4 & ~7;
        int off  = (c4 >> 2) & 1;
        float* dst = Qs + r * Q_LD + base + off;
        dst[0] = t32(v.x * scale);
        dst[2] = t32(v.y * scale);
        dst[4] = t32(v.z * scale);
        dst[6] = t32(v.w * scale);
    }

    float o[16][4];
#pragma unroll
    for (int i = 0; i < 16; i++)
#pragma unroll
        for (int j = 0; j < 4; j++) o[i][j] = 0.0f;
    float m0 = -1e30f, m1 = -1e30f, l0 = 0.0f, l1 = 0.0f;

    const int row0 = by * 128 + wid * 16 + g;
    const int row1 = row0 + 8;

    const int ktmax = 2 * by + 2;
    for (int kt = 0; kt < ktmax; kt++) {
        __syncthreads();
        // ---- load K (permuted) and V (plain) tiles, tf32-rounded ----
        const int key0 = kt * 64;
        for (int i = tid; i < 64 * 32; i += 256) {
            int r  = i >> 5;
            int c4 = (i & 31) << 2;
            float4 kv = *(const float4*)(Kg + (size_t)(key0 + r) * QKVN + c4);
            int base = c4 & ~7;
            int off  = (c4 >> 2) & 1;
            float* dst = Ks + r * K_LD + base + off;
            dst[0] = t32(kv.x); dst[2] = t32(kv.y);
            dst[4] = t32(kv.z); dst[6] = t32(kv.w);
            float4 vv = *(const float4*)(Vg + (size_t)(key0 + r) * QKVN + c4);
            float* vdst = Vs + r * V_LD + c4;
            vdst[0] = t32(vv.x); vdst[1] = t32(vv.y);
            vdst[2] = t32(vv.z); vdst[3] = t32(vv.w);
        }
        __syncthreads();

        // ---- S = Q K^T (warp: 16 rows x 64 keys) ----
        float s[8][4];
#pragma unroll
        for (int i = 0; i < 8; i++)
#pragma unroll
            for (int j = 0; j < 4; j++) s[i][j] = 0.0f;

        const unsigned* Qr0 = (const unsigned*)(Qs + (wid * 16 + g) * Q_LD);
        const unsigned* Qr1 = Qr0 + 8 * Q_LD;
        const unsigned* Ku  = (const unsigned*)Ks;
#pragma unroll
        for (int ks = 0; ks < 16; ks++) {
            uint2 a02 = *(const uint2*)(Qr0 + ks * 8 + 2 * c);
            uint2 a13 = *(const uint2*)(Qr1 + ks * 8 + 2 * c);
#pragma unroll
            for (int nt = 0; nt < 8; nt++) {
                uint2 b = *(const uint2*)(Ku + (nt * 8 + g) * K_LD + ks * 8 + 2 * c);
                mma_tf32(s[nt], a02.x, a13.x, a02.y, a13.y, b.x, b.y);
            }
        }

        // ---- causal mask (only for the last two tiles) ----
        if (kt >= 2 * by) {
#pragma unroll
            for (int nt = 0; nt < 8; nt++) {
                int col = key0 + nt * 8 + 2 * c;
                if (col     > row0) s[nt][0] = -1e30f;
                if (col + 1 > row0) s[nt][1] = -1e30f;
                if (col     > row1) s[nt][2] = -1e30f;
                if (col + 1 > row1) s[nt][3] = -1e30f;
            }
        }

        // ---- online softmax ----
        float tm0 = -1e30f, tm1 = -1e30f;
#pragma unroll
        for (int nt = 0; nt < 8; nt++) {
            tm0 = fmaxf(tm0, fmaxf(s[nt][0], s[nt][1]));
            tm1 = fmaxf(tm1, fmaxf(s[nt][2], s[nt][3]));
        }
        tm0 = fmaxf(tm0, __shfl_xor_sync(0xffffffffu, tm0, 1));
        tm0 = fmaxf(tm0, __shfl_xor_sync(0xffffffffu, tm0, 2));
        tm1 = fmaxf(tm1, __shfl_xor_sync(0xffffffffu, tm1, 1));
        tm1 = fmaxf(tm1, __shfl_xor_sync(0xffffffffu, tm1, 2));

        float mn0 = fmaxf(m0, tm0), mn1 = fmaxf(m1, tm1);
        float al0 = __expf(m0 - mn0), al1 = __expf(m1 - mn1);
        m0 = mn0; m1 = mn1;

        const int pos0 = (c & 1) * 4 + (c >> 1);   // permuted pos of col 2c
        const int pos1 = pos0 + 2;                 // permuted pos of col 2c+1
        float sum0 = 0.0f, sum1 = 0.0f;
#pragma unroll
        for (int nt = 0; nt < 8; nt++) {
            float p0 = __expf(s[nt][0] - mn0);
            float p1 = __expf(s[nt][1] - mn0);
            float p2 = __expf(s[nt][2] - mn1);
            float p3 = __expf(s[nt][3] - mn1);
            sum0 += p0 + p1;
            sum1 += p2 + p3;
            Ps[g * P_LD + nt * 8 + pos0]       = t32(p0);
            Ps[g * P_LD + nt * 8 + pos1]       = t32(p1);
            Ps[(g + 8) * P_LD + nt * 8 + pos0] = t32(p2);
            Ps[(g + 8) * P_LD + nt * 8 + pos1] = t32(p3);
        }
        sum0 += __shfl_xor_sync(0xffffffffu, sum0, 1);
        sum0 += __shfl_xor_sync(0xffffffffu, sum0, 2);
        sum1 += __shfl_xor_sync(0xffffffffu, sum1, 1);
        sum1 += __shfl_xor_sync(0xffffffffu, sum1, 2);
        l0 = l0 * al0 + sum0;
        l1 = l1 * al1 + sum1;

#pragma unroll
        for (int nt = 0; nt < 16; nt++) {
            o[nt][0] *= al0; o[nt][1] *= al0;
            o[nt][2] *= al1; o[nt][3] *= al1;
        }
        __syncwarp();

        // ---- O += P V ----
        const unsigned* Pr0 = (const unsigned*)(Ps + g * P_LD);
        const unsigned* Pr1 = Pr0 + 8 * P_LD;
        const unsigned* Vu  = (const unsigned*)Vs;
#pragma unroll
        for (int ks = 0; ks < 8; ks++) {
            uint2 a02 = *(const uint2*)(Pr0 + ks * 8 + 2 * c);
            uint2 a13 = *(const uint2*)(Pr1 + ks * 8 + 2 * c);
            const unsigned* Vb0 = Vu + (ks * 8 + c) * V_LD + g;
            const unsigned* Vb1 = Vb0 + 4 * V_LD;
#pragma unroll
            for (int nt = 0; nt < 16; nt++) {
                mma_tf32(o[nt], a02.x, a13.x, a02.y, a13.y, Vb0[nt * 8], Vb1[nt * 8]);
            }
        }
        __syncwarp();
    }

    // ---- epilogue: normalize and store ----
    float inv0 = 1.0f / l0;
    float inv1 = 1.0f / l1;
    float* out0 = attn + (size_t)row0 * HID + h * HD;
    float* out1 = attn + (size_t)row1 * HID + h * HD;
#pragma unroll
    for (int nt = 0; nt < 16; nt++) {
        float2 v0 = make_float2(o[nt][0] * inv0, o[nt][1] * inv0);
        float2 v1 = make_float2(o[nt][2] * inv1, o[nt][3] * inv1);
        *(float2*)(out0 + nt * 8 + 2 * c) = v0;
        *(float2*)(out1 + nt * 8 + 2 * c) = v1;
    }
}

// ---------------- launch ----------------
extern "C" void kernel_launch(void* const* d_in, const int* in_sizes, int n_in,
                              void* d_out, int out_size) {
    const float* hs   = (const float*)d_in[1];
    const float* Wqkv = (const float*)d_in[2];
    const float* bqkv = (const float*)d_in[3];
    const float* Wo   = (const float*)d_in[4];
    const float* bo   = (const float*)d_in[5];
    float* out = (float*)d_out;

    float *qkv, *attn;
    cudaGetSymbolAddress((void**)&qkv,  g_qkv);
    cudaGetSymbolAddress((void**)&attn, g_attn);

    cudaFuncSetAttribute(flash_kernel, cudaFuncAttributeMaxDynamicSharedMemorySize,
                         FA_SMEM_BYTES);

    // 1) QKV = hs @ Wqkv + bqkv   (tf32 tensor cores)
    gemm_tf32_bias<<<dim3(QKVN / BN, SEQ / BM), 256>>>(hs, Wqkv, bqkv, qkv, SEQ, QKVN, HID);
    // 2) RoPE on q,k
    rope_kernel<<<(SEQ * NH * 64 + 255) / 256, 256>>>(qkv);
    // 3) fused flash attention -> g_attn
    flash_kernel<<<dim3(SEQ / 128, NH), 256, FA_SMEM_BYTES>>>(qkv, attn);
    // 4) out = attn @ Wo + bo   (tf32 tensor cores)
    gemm_tf32_bias<<<dim3(HID / BN, SEQ / BM), 256>>>(attn, Wo, bo, out, SEQ, HID, HID);
}

// round 4
// speedup vs baseline: 1.8960x; 1.0546x over previous
#include <cuda_runtime.h>
#include <mma.h>
#include <math.h>
#include <float.h>

using namespace nvcuda;

#define SEQ   2048
#define HID   4096
#define NH    32
#define HD    128
#define QKVN  12288   // 3*HID

// ---------------- scratch (no cudaMalloc allowed) ----------------
__device__ float g_qkv[SEQ * QKVN];      // 100 MB
__device__ float g_attn[SEQ * HID];      // 33 MB  (tf32-rounded by flash)
__device__ float g_hs32[SEQ * HID];      // 33 MB  tf32(hs)
__device__ float g_wq32[HID * QKVN];     // 201 MB tf32(Wqkv)
__device__ float g_wo32[HID * HID];      // 67 MB  tf32(Wo)

__device__ __forceinline__ float t32(float x) { return wmma::__float_to_tf32(x); }

// ---------------- cp.async helpers ----------------
__device__ __forceinline__ void cp_async16(void* smem_dst, const void* gsrc) {
    unsigned s = (unsigned)__cvta_generic_to_shared(smem_dst);
    asm volatile("cp.async.cg.shared.global [%0], [%1], 16;\n" :: "r"(s), "l"(gsrc));
}
__device__ __forceinline__ void cp_commit() {
    asm volatile("cp.async.commit_group;\n");
}
template <int N> __device__ __forceinline__ void cp_wait() {
    asm volatile("cp.async.wait_group %0;\n" :: "n"(N));
}

// ---------------- tf32 RN pre-convert ----------------
__global__ __launch_bounds__(256)
void cvt_tf32(const float* __restrict__ in, float* __restrict__ out, int n4) {
    int i = blockIdx.x * blockDim.x + threadIdx.x;
    if (i < n4) {
        float4 v = ((const float4*)in)[i];
        v.x = t32(v.x); v.y = t32(v.y); v.z = t32(v.z); v.w = t32(v.w);
        ((float4*)out)[i] = v;
    }
}

// ================= tf32 tensor-core GEMM + bias (3-stage pipeline) =======
// Inputs must already be tf32-rounded. C = A@B + bias (bias fp32).
#define BM 128
#define BN 128
#define BK 16
#define A_LD (BK + 8)    // 24
#define B_LD (BN + 4)    // 132
#define STG 3
#define GEMM_SMEM_FLOATS (STG * (BM * A_LD + BK * B_LD))
#define GEMM_SMEM_BYTES (GEMM_SMEM_FLOATS * 4)   // 62208

__global__ __launch_bounds__(256)
void gemm_tf32_bias(const float* __restrict__ A, const float* __restrict__ B,
                    const float* __restrict__ bias, float* __restrict__ C,
                    int M, int N, int K) {
    extern __shared__ float gsm[];
    float* Asm = gsm;                         // [STG][BM][A_LD]
    float* Bsm = gsm + STG * BM * A_LD;       // [STG][BK][B_LD]

    const int tid  = threadIdx.x;
    const int wid  = tid >> 5;
    const int lane = tid & 31;
    const int warp_m = (wid >> 1) * 32;
    const int warp_n = (wid & 1) * 64;

    const int bx = blockIdx.x, by = blockIdx.y;

    const int a_row = tid >> 2;
    const int a_col = (tid & 3) * 4;
    const int b_row = tid >> 5;
    const int b_col = (tid & 31) * 4;

    const float* Ag = A + (size_t)(by * BM) * K;
    const float* Bg = B + bx * BN;

    wmma::fragment<wmma::accumulator, 16, 16, 8, float> acc[2][4];
#pragma unroll
    for (int i = 0; i < 2; i++)
#pragma unroll
        for (int j = 0; j < 4; j++) wmma::fill_fragment(acc[i][j], 0.0f);

    const int T = K / BK;

    // prologue: stages 0 and 1
#pragma unroll
    for (int pt = 0; pt < 2; pt++) {
        const int k0 = pt * BK;
        float* As_s = Asm + pt * BM * A_LD;
        float* Bs_s = Bsm + pt * BK * B_LD;
#pragma unroll
        for (int p = 0; p < 2; p++) {
            int r = a_row + p * 64;
            cp_async16(&As_s[r * A_LD + a_col], Ag + (size_t)r * K + k0 + a_col);
        }
#pragma unroll
        for (int p = 0; p < 2; p++) {
            int r = b_row + p * 8;
            cp_async16(&Bs_s[r * B_LD + b_col], Bg + (size_t)(k0 + r) * N + b_col);
        }
        cp_commit();
    }

    for (int t = 0; t < T; t++) {
        if (t + 2 < T) {
            const int s  = (t + 2) % 3;
            const int k0 = (t + 2) * BK;
            float* As_s = Asm + s * BM * A_LD;
            float* Bs_s = Bsm + s * BK * B_LD;
#pragma unroll
            for (int p = 0; p < 2; p++) {
                int r = a_row + p * 64;
                cp_async16(&As_s[r * A_LD + a_col], Ag + (size_t)r * K + k0 + a_col);
            }
#pragma unroll
            for (int p = 0; p < 2; p++) {
                int r = b_row + p * 8;
                cp_async16(&Bs_s[r * B_LD + b_col], Bg + (size_t)(k0 + r) * N + b_col);
            }
        }
        cp_commit();
        cp_wait<2>();
        __syncthreads();

        const int cur = t % 3;
        const float* At = Asm + cur * BM * A_LD;
        const float* Bt = Bsm + cur * BK * B_LD;
#pragma unroll
        for (int kk = 0; kk < BK; kk += 8) {
            wmma::fragment<wmma::matrix_a, 16, 16, 8, wmma::precision::tf32, wmma::row_major> af[2];
#pragma unroll
            for (int i = 0; i < 2; i++)
                wmma::load_matrix_sync(af[i], At + (warp_m + i * 16) * A_LD + kk, A_LD);
            wmma::fragment<wmma::matrix_b, 16, 16, 8, wmma::precision::tf32, wmma::row_major> bf[4];
#pragma unroll
            for (int j = 0; j < 4; j++)
                wmma::load_matrix_sync(bf[j], Bt + kk * B_LD + warp_n + j * 16, B_LD);
#pragma unroll
            for (int i = 0; i < 2; i++)
#pragma unroll
                for (int j = 0; j < 4; j++)
                    wmma::mma_sync(acc[i][j], af[i], bf[j], acc[i][j]);
        }
        __syncthreads();
    }

    // epilogue: stage each 16x16 patch through smem, add fp32 bias
    float* epi = gsm + wid * 256;
#pragma unroll
    for (int i = 0; i < 2; i++) {
#pragma unroll
        for (int j = 0; j < 4; j++) {
            wmma::store_matrix_sync(epi, acc[i][j], 16, wmma::mem_row_major);
            __syncwarp();
            int r = lane >> 1;
            int c = (lane & 1) * 8;
            int grow = by * BM + warp_m + i * 16 + r;
            int gcol = bx * BN + warp_n + j * 16 + c;
            float4 v0 = *(float4*)&epi[r * 16 + c];
            float4 v1 = *(float4*)&epi[r * 16 + c + 4];
            const float* bp = bias + gcol;
            v0.x += bp[0]; v0.y += bp[1]; v0.z += bp[2]; v0.w += bp[3];
            v1.x += bp[4]; v1.y += bp[5]; v1.z += bp[6]; v1.w += bp[7];
            float* cp = C + (size_t)grow * N + gcol;
            *(float4*)cp = v0;
            *(float4*)(cp + 4) = v1;
            __syncwarp();
        }
    }
}

// ---------------- RoPE in place; emits tf32 values; scales Q; converts V --
__global__ __launch_bounds__(256)
void rope_kernel(float* __restrict__ qkv) {
    int idx = blockIdx.x * blockDim.x + threadIdx.x;
    if (idx >= SEQ * NH * 64) return;
    int i = idx & 63;
    int h = (idx >> 6) & 31;
    int s = idx >> 11;
    double invf = exp(-log(10000.0) * (double)(2 * i) / 128.0);
    double f = (double)s * invf;
    float c  = (float)cos(f);
    float sn = (float)sin(f);
    const float scale = 0.08838834764831843f;  // 1/sqrt(128)
    size_t base = (size_t)s * QKVN + h * HD;
    float* q = qkv + base;
    float* k = qkv + base + HID;
    float* v = qkv + base + 2 * HID;
    float q1 = q[i], q2 = q[i + 64];
    q[i]      = t32((q1 * c - q2 * sn) * scale);
    q[i + 64] = t32((q2 * c + q1 * sn) * scale);
    float k1 = k[i], k2 = k[i + 64];
    k[i]      = t32(k1 * c - k2 * sn);
    k[i + 64] = t32(k2 * c + k1 * sn);
    v[i]      = t32(v[i]);
    v[i + 64] = t32(v[i + 64]);
}

// ================== fused flash attention (tf32 mma, pipelined K/V) ======
// Block: 128 query rows x 1 head, 8 warps x 16 rows. Key tile = 32,
// double-buffered via cp.async. Q permuted in smem (uint2 A-frag loads);
// K/V plain layout (B-frags via 2x conflict-free LDS.32). Online softmax fp32.

#define KT 32
#define Q_LD 132
#define K_LD 132
#define V_LD 136
#define P_LD 36
#define SM_Q 0
#define SM_K (128 * Q_LD)
#define SM_V (SM_K + 2 * KT * K_LD)
#define SM_P (SM_V + 2 * KT * V_LD)
#define FA_SMEM_FLOATS (SM_P + 8 * 16 * P_LD)
#define FA_SMEM_BYTES (FA_SMEM_FLOATS * 4)   // 154624

__device__ __forceinline__ void mma_tf32(float* d, unsigned a0, unsigned a1,
                                         unsigned a2, unsigned a3,
                                         unsigned b0, unsigned b1) {
    asm volatile(
        "mma.sync.aligned.m16n8k8.row.col.f32.tf32.tf32.f32 "
        "{%0,%1,%2,%3}, {%4,%5,%6,%7}, {%8,%9}, {%0,%1,%2,%3};\n"
        : "+f"(d[0]), "+f"(d[1]), "+f"(d[2]), "+f"(d[3])
        : "r"(a0), "r"(a1), "r"(a2), "r"(a3), "r"(b0), "r"(b1));
}

__global__ __launch_bounds__(256, 1)
void flash_kernel(const float* __restrict__ qkv, float* __restrict__ attn) {
    extern __shared__ float sm[];
    const int h  = blockIdx.y;
    const int by = (gridDim.x - 1) - blockIdx.x;   // heavy tiles first
    const int tid  = threadIdx.x;
    const int wid  = tid >> 5;
    const int lane = tid & 31;
    const int g = lane >> 2;
    const int c = lane & 3;

    float* Qs = sm + SM_Q;
    float* Ks = sm + SM_K;
    float* Vs = sm + SM_V;
    float* Ps = sm + SM_P + wid * 16 * P_LD;   // warp-private

    const float* Qg = qkv + (size_t)h * HD;
    const float* Kg = qkv + HID + (size_t)h * HD;
    const float* Vg = qkv + 2 * HID + (size_t)h * HD;

    const int ktmax = 4 * by + 4;

    // ---- prefetch K/V tile 0 into buffer 0 ----
    {
        for (int i = tid; i < KT * 32; i += 256) {
            int r  = i >> 5;
            int c4 = (i & 31) << 2;
            cp_async16(&Ks[r * K_LD + c4], Kg + (size_t)r * QKVN + c4);
            cp_async16(&Vs[r * V_LD + c4], Vg + (size_t)r * QKVN + c4);
        }
        cp_commit();
    }

    // ---- load Q tile (already tf32+scaled); permute cols so uint2 = (c,c+4) ----
    for (int i = tid; i < 128 * 32; i += 256) {
        int r  = i >> 5;
        int c4 = (i & 31) << 2;
        float4 v = *(const float4*)(Qg + (size_t)(by * 128 + r) * QKVN + c4);
        int base = c4 & ~7;
        int off  = (c4 >> 2) & 1;
        float* dst = Qs + r * Q_LD + base + off;
        dst[0] = v.x; dst[2] = v.y; dst[4] = v.z; dst[6] = v.w;
    }

    float o[16][4];
#pragma unroll
    for (int i = 0; i < 16; i++)
#pragma unroll
        for (int j = 0; j < 4; j++) o[i][j] = 0.0f;
    float m0 = -1e30f, m1 = -1e30f, l0 = 0.0f, l1 = 0.0f;

    const int row0 = by * 128 + wid * 16 + g;
    const int row1 = row0 + 8;

    for (int kt = 0; kt < ktmax; kt++) {
        // prefetch next tile into the other buffer
        if (kt + 1 < ktmax) {
            const int nb   = (kt + 1) & 1;
            const int key0 = (kt + 1) * KT;
            for (int i = tid; i < KT * 32; i += 256) {
                int r  = i >> 5;
                int c4 = (i & 31) << 2;
                cp_async16(&Ks[nb * KT * K_LD + r * K_LD + c4],
                           Kg + (size_t)(key0 + r) * QKVN + c4);
                cp_async16(&Vs[nb * KT * V_LD + r * V_LD + c4],
                           Vg + (size_t)(key0 + r) * QKVN + c4);
            }
        }
        cp_commit();
        cp_wait<1>();
        __syncthreads();

        const float* Kbuf = Ks + (kt & 1) * KT * K_LD;
        const float* Vbuf = Vs + (kt & 1) * KT * V_LD;
        const int key0 = kt * KT;

        // ---- S = Q K^T (warp: 16 rows x 32 keys) ----
        float s[4][4];
#pragma unroll
        for (int i = 0; i < 4; i++)
#pragma unroll
            for (int j = 0; j < 4; j++) s[i][j] = 0.0f;

        const unsigned* Qr0 = (const unsigned*)(Qs + (wid * 16 + g) * Q_LD);
        const unsigned* Qr1 = Qr0 + 8 * Q_LD;
#pragma unroll
        for (int ks = 0; ks < 16; ks++) {
            uint2 a02 = *(const uint2*)(Qr0 + ks * 8 + 2 * c);
            uint2 a13 = *(const uint2*)(Qr1 + ks * 8 + 2 * c);
#pragma unroll
            for (int nt = 0; nt < 4; nt++) {
                const float* kb = Kbuf + (nt * 8 + g) * K_LD + ks * 8 + c;
                mma_tf32(s[nt], a02.x, a13.x, a02.y, a13.y,
                         __float_as_uint(kb[0]), __float_as_uint(kb[4]));
            }
        }

        // ---- causal mask (last 4 tiles of this block row) ----
        if (kt >= 4 * by) {
#pragma unroll
            for (int nt = 0; nt < 4; nt++) {
                int col = key0 + nt * 8 + 2 * c;
                if (col     > row0) s[nt][0] = -1e30f;
                if (col + 1 > row0) s[nt][1] = -1e30f;
                if (col     > row1) s[nt][2] = -1e30f;
                if (col + 1 > row1) s[nt][3] = -1e30f;
            }
        }

        // ---- online softmax ----
        float tm0 = -1e30f, tm1 = -1e30f;
#pragma unroll
        for (int nt = 0; nt < 4; nt++) {
            tm0 = fmaxf(tm0, fmaxf(s[nt][0], s[nt][1]));
            tm1 = fmaxf(tm1, fmaxf(s[nt][2], s[nt][3]));
        }
        tm0 = fmaxf(tm0, __shfl_xor_sync(0xffffffffu, tm0, 1));
        tm0 = fmaxf(tm0, __shfl_xor_sync(0xffffffffu, tm0, 2));
        tm1 = fmaxf(tm1, __shfl_xor_sync(0xffffffffu, tm1, 1));
        tm1 = fmaxf(tm1, __shfl_xor_sync(0xffffffffu, tm1, 2));

        float mn0 = fmaxf(m0, tm0), mn1 = fmaxf(m1, tm1);
        float al0 = __expf(m0 - mn0), al1 = __expf(m1 - mn1);
        m0 = mn0; m1 = mn1;

        const int pos0 = (c & 1) * 4 + (c >> 1);
        const int pos1 = pos0 + 2;
        float sum0 = 0.0f, sum1 = 0.0f;
#pragma unroll
        for (int nt = 0; nt < 4; nt++) {
            float p0 = __expf(s[nt][0] - mn0);
            float p1 = __expf(s[nt][1] - mn0);
            float p2 = __expf(s[nt][2] - mn1);
            float p3 = __expf(s[nt][3] - mn1);
            sum0 += p0 + p1;
            sum1 += p2 + p3;
            Ps[g * P_LD + nt * 8 + pos0]       = t32(p0);
            Ps[g * P_LD + nt * 8 + pos1]       = t32(p1);
            Ps[(g + 8) * P_LD + nt * 8 + pos0] = t32(p2);
            Ps[(g + 8) * P_LD + nt * 8 + pos1] = t32(p3);
        }
        sum0 += __shfl_xor_sync(0xffffffffu, sum0, 1);
        sum0 += __shfl_xor_sync(0xffffffffu, sum0, 2);
        sum1 += __shfl_xor_sync(0xffffffffu, sum1, 1);
        sum1 += __shfl_xor_sync(0xffffffffu, sum1, 2);
        l0 = l0 * al0 + sum0;
        l1 = l1 * al1 + sum1;

#pragma unroll
        for (int nt = 0; nt < 16; nt++) {
            o[nt][0] *= al0; o[nt][1] *= al0;
            o[nt][2] *= al1; o[nt][3] *= al1;
        }
        __syncwarp();

        // ---- O += P V ----
        const unsigned* Pr0 = (const unsigned*)(Ps + g * P_LD);
        const unsigned* Pr1 = Pr0 + 8 * P_LD;
#pragma unroll
        for (int ks = 0; ks < 4; ks++) {
            uint2 a02 = *(const uint2*)(Pr0 + ks * 8 + 2 * c);
            uint2 a13 = *(const uint2*)(Pr1 + ks * 8 + 2 * c);
            const float* vb0 = Vbuf + (ks * 8 + c) * V_LD + g;
            const float* vb1 = vb0 + 4 * V_LD;
#pragma unroll
            for (int nt = 0; nt < 16; nt++) {
                mma_tf32(o[nt], a02.x, a13.x, a02.y, a13.y,
                         __float_as_uint(vb0[nt * 8]), __float_as_uint(vb1[nt * 8]));
            }
        }
        __syncwarp();
        __syncthreads();
    }

    // ---- epilogue: normalize, tf32-round (O-proj consumes this), store ----
    float inv0 = 1.0f / l0;
    float inv1 = 1.0f / l1;
    float* out0 = attn + (size_t)row0 * HID + h * HD;
    float* out1 = attn + (size_t)row1 * HID + h * HD;
#pragma unroll
    for (int nt = 0; nt < 16; nt++) {
        float2 v0 = make_float2(t32(o[nt][0] * inv0), t32(o[nt][1] * inv0));
        float2 v1 = make_float2(t32(o[nt][2] * inv1), t32(o[nt][3] * inv1));
        *(float2*)(out0 + nt * 8 + 2 * c) = v0;
        *(float2*)(out1 + nt * 8 + 2 * c) = v1;
    }
}

// ---------------- launch ----------------
extern "C" void kernel_launch(void* const* d_in, const int* in_sizes, int n_in,
                              void* d_out, int out_size) {
    const float* hs   = (const float*)d_in[1];
    const float* Wqkv = (const float*)d_in[2];
    const float* bqkv = (const float*)d_in[3];
    const float* Wo   = (const float*)d_in[4];
    const float* bo   = (const float*)d_in[5];
    float* out = (float*)d_out;

    float *qkv, *attn, *hs32, *wq32, *wo32;
    cudaGetSymbolAddress((void**)&qkv,  g_qkv);
    cudaGetSymbolAddress((void**)&attn, g_attn);
    cudaGetSymbolAddress((void**)&hs32, g_hs32);
    cudaGetSymbolAddress((void**)&wq32, g_wq32);
    cudaGetSymbolAddress((void**)&wo32, g_wo32);

    cudaFuncSetAttribute(flash_kernel, cudaFuncAttributeMaxDynamicSharedMemorySize,
                         FA_SMEM_BYTES);
    cudaFuncSetAttribute(gemm_tf32_bias, cudaFuncAttributeMaxDynamicSharedMemorySize,
                         GEMM_SMEM_BYTES);

    // 0) RN tf32 pre-conversion of GEMM operands
    cvt_tf32<<<(SEQ * HID / 4 + 255) / 256, 256>>>(hs, hs32, SEQ * HID / 4);
    cvt_tf32<<<(HID * QKVN / 4 + 255) / 256, 256>>>(Wqkv, wq32, HID * QKVN / 4);
    cvt_tf32<<<(HID * HID / 4 + 255) / 256, 256>>>(Wo, wo32, HID * HID / 4);

    // 1) QKV = hs @ Wqkv + bqkv
    gemm_tf32_bias<<<dim3(QKVN / BN, SEQ / BM), 256, GEMM_SMEM_BYTES>>>(
        hs32, wq32, bqkv, qkv, SEQ, QKVN, HID);
    // 2) RoPE (+ tf32 rounding of q,k,v; q pre-scaled)
    rope_kernel<<<(SEQ * NH * 64 + 255) / 256, 256>>>(qkv);
    // 3) fused flash attention -> g_attn (tf32-rounded)
    flash_kernel<<<dim3(SEQ / 128, NH), 256, FA_SMEM_BYTES>>>(qkv, attn);
    // 4) out = attn @ Wo + bo
    gemm_tf32_bias<<<dim3(HID / BN, SEQ / BM), 256, GEMM_SMEM_BYTES>>>(
        attn, wo32, bo, out, SEQ, HID, HID);
}

// round 7
// speedup vs baseline: 4.1792x; 2.2042x over previous
#include <cuda_runtime.h>
#include <cuda_fp16.h>
#include <cstdint>
#include <mma.h>
#include <math.h>
#include <float.h>

using namespace nvcuda;

#define SEQ   2048
#define HID   4096
#define NH    32
#define HD    128
#define QKVN  12288   // 3*HID

// ---------------- scratch (no cudaMalloc allowed) ----------------
__device__ float  g_qkv[SEQ * QKVN];            // 100 MB (fp32; rope needs precision)
__device__ __half g_attn16[SEQ * HID];          // 17 MB  (flash output, O-proj input)
__device__ __half g_hs16[SEQ * HID];            // 17 MB  fp16(hs)
__device__ __half g_wq16[(size_t)HID * QKVN];   // 100 MB fp16(Wqkv) row-major
__device__ __half g_wo16[(size_t)HID * HID];    // 34 MB  fp16(Wo)   row-major

__device__ __forceinline__ float t32(float x) { return wmma::__float_to_tf32(x); }

// ---------------- cp.async helpers ----------------
__device__ __forceinline__ void cp_async16(void* smem_dst, const void* gsrc) {
    unsigned s = (unsigned)__cvta_generic_to_shared(smem_dst);
    asm volatile("cp.async.cg.shared.global [%0], [%1], 16;\n" :: "r"(s), "l"(gsrc));
}
__device__ __forceinline__ void cp_commit() {
    asm volatile("cp.async.commit_group;\n");
}
template <int N> __device__ __forceinline__ void cp_wait() {
    asm volatile("cp.async.wait_group %0;\n" :: "n"(N));
}

// ---------------- fp16 pre-convert ----------------
__global__ __launch_bounds__(256)
void cvt_f16(const float* __restrict__ in, __half* __restrict__ out, int n4) {
    int i = blockIdx.x * blockDim.x + threadIdx.x;
    if (i < n4) {
        float4 v = ((const float4*)in)[i];
        __half2 h0 = __floats2half2_rn(v.x, v.y);
        __half2 h1 = __floats2half2_rn(v.z, v.w);
        uint2 pk;
        pk.x = *(unsigned*)&h0;
        pk.y = *(unsigned*)&h1;
        ((uint2*)out)[i] = pk;
    }
}

// ================= fp16 tensor-core GEMM + bias (3-stage pipeline) =======
// A: [M][K] row-major fp16. B: [K][N] row-major fp16. C = A@B + bias (fp32).
#define BM 128
#define BN 128
#define BK 32
#define A_LD 40      // halves (80B rows)
#define B_LD 136     // halves (272B rows)
#define STG 3
#define GEMM_SMEM_BYTES (STG * (BM * A_LD + BK * B_LD) * 2)   // 56832

__global__ __launch_bounds__(256)
void gemm_f16_bias(const __half* __restrict__ A, const __half* __restrict__ B,
                   const float* __restrict__ bias, float* __restrict__ C,
                   int K, int N) {
    extern __shared__ __half gsm[];
    __half* Asm = gsm;                        // [STG][BM][A_LD]
    __half* Bsm = gsm + STG * BM * A_LD;      // [STG][BK][B_LD]

    const int tid  = threadIdx.x;
    const int wid  = tid >> 5;
    const int lane = tid & 31;
    const int warp_m = (wid >> 1) * 32;   // 0,32,64,96
    const int warp_n = (wid & 1) * 64;    // 0,64

    const int bx = blockIdx.x, by = blockIdx.y;

    // global-load mapping (16B = 8-half chunks)
    const int a_row = tid >> 1;           // 0..127
    const int a_ck  = (tid & 1) * 16;     // halves: 0 or 16 (two chunks per row half)
    const int b_row = tid >> 4;           // 0..15 (+16 second pass)
    const int b_ck  = (tid & 15) * 8;     // halves 0..120

    const __half* Ag = A + (size_t)(by * BM) * K;
    const __half* Bg = B + bx * BN;

    wmma::fragment<wmma::accumulator, 16, 16, 16, float> acc[2][4];
#pragma unroll
    for (int i = 0; i < 2; i++)
#pragma unroll
        for (int j = 0; j < 4; j++) wmma::fill_fragment(acc[i][j], 0.0f);

    const int T = K / BK;

    // prologue: stages 0 and 1
#pragma unroll
    for (int pt = 0; pt < 2; pt++) {
        const int k0 = pt * BK;
        __half* As_s = Asm + pt * BM * A_LD;
        __half* Bs_s = Bsm + pt * BK * B_LD;
        // A: 128 rows x 32 halves = 2 chunks/row; this thread does 2 chunks
        cp_async16(&As_s[a_row * A_LD + a_ck],     Ag + (size_t)a_row * K + k0 + a_ck);
        cp_async16(&As_s[a_row * A_LD + a_ck + 8], Ag + (size_t)a_row * K + k0 + a_ck + 8);
        // B: 32 rows x 128 halves = 16 chunks/row; thread does rows b_row, b_row+16
#pragma unroll
        for (int p = 0; p < 2; p++) {
            int r = b_row + p * 16;
            cp_async16(&Bs_s[r * B_LD + b_ck], Bg + (size_t)(k0 + r) * N + b_ck);
        }
        cp_commit();
    }

    for (int t = 0; t < T; t++) {
        if (t + 2 < T) {
            const int s  = (t + 2) % 3;
            const int k0 = (t + 2) * BK;
            __half* As_s = Asm + s * BM * A_LD;
            __half* Bs_s = Bsm + s * BK * B_LD;
            cp_async16(&As_s[a_row * A_LD + a_ck],     Ag + (size_t)a_row * K + k0 + a_ck);
            cp_async16(&As_s[a_row * A_LD + a_ck + 8], Ag + (size_t)a_row * K + k0 + a_ck + 8);
#pragma unroll
            for (int p = 0; p < 2; p++) {
                int r = b_row + p * 16;
                cp_async16(&Bs_s[r * B_LD + b_ck], Bg + (size_t)(k0 + r) * N + b_ck);
            }
        }
        cp_commit();
        cp_wait<2>();
        __syncthreads();

        const int cur = t % 3;
        const __half* At = Asm + cur * BM * A_LD;
        const __half* Bt = Bsm + cur * BK * B_LD;
#pragma unroll
        for (int kk = 0; kk < BK; kk += 16) {
            wmma::fragment<wmma::matrix_a, 16, 16, 16, __half, wmma::row_major> af[2];
#pragma unroll
            for (int i = 0; i < 2; i++)
                wmma::load_matrix_sync(af[i], At + (warp_m + i * 16) * A_LD + kk, A_LD);
            wmma::fragment<wmma::matrix_b, 16, 16, 16, __half, wmma::row_major> bf[4];
#pragma unroll
            for (int j = 0; j < 4; j++)
                wmma::load_matrix_sync(bf[j], Bt + kk * B_LD + warp_n + j * 16, B_LD);
#pragma unroll
            for (int i = 0; i < 2; i++)
#pragma unroll
                for (int j = 0; j < 4; j++)
                    wmma::mma_sync(acc[i][j], af[i], bf[j], acc[i][j]);
        }
        __syncthreads();
    }
    __syncthreads();

    // epilogue: stage each 16x16 patch through smem (as float), add fp32 bias
    float* epi = (float*)gsm + wid * 256;
#pragma unroll
    for (int i = 0; i < 2; i++) {
#pragma unroll
        for (int j = 0; j < 4; j++) {
            wmma::store_matrix_sync(epi, acc[i][j], 16, wmma::mem_row_major);
            __syncwarp();
            int r = lane >> 1;
            int c = (lane & 1) * 8;
            int grow = by * BM + warp_m + i * 16 + r;
            int gcol = bx * BN + warp_n + j * 16 + c;
            float4 v0 = *(float4*)&epi[r * 16 + c];
            float4 v1 = *(float4*)&epi[r * 16 + c + 4];
            const float* bp = bias + gcol;
            v0.x += bp[0]; v0.y += bp[1]; v0.z += bp[2]; v0.w += bp[3];
            v1.x += bp[4]; v1.y += bp[5]; v1.z += bp[6]; v1.w += bp[7];
            float* cp = C + (size_t)grow * N + gcol;
            *(float4*)cp = v0;
            *(float4*)(cp + 4) = v1;
            __syncwarp();
        }
    }
}

// ---------------- RoPE in place; emits tf32 values; scales Q; converts V --
__global__ __launch_bounds__(256)
void rope_kernel(float* __restrict__ qkv) {
    int idx = blockIdx.x * blockDim.x + threadIdx.x;
    if (idx >= SEQ * NH * 64) return;
    int i = idx & 63;
    int h = (idx >> 6) & 31;
    int s = idx >> 11;
    double invf = exp(-log(10000.0) * (double)(2 * i) / 128.0);
    double f = (double)s * invf;
    float c  = (float)cos(f);
    float sn = (float)sin(f);
    const float scale = 0.08838834764831843f;  // 1/sqrt(128)
    size_t base = (size_t)s * QKVN + h * HD;
    float* q = qkv + base;
    float* k = qkv + base + HID;
    float* v = qkv + base + 2 * HID;
    float q1 = q[i], q2 = q[i + 64];
    q[i]      = t32((q1 * c - q2 * sn) * scale);
    q[i + 64] = t32((q2 * c + q1 * sn) * scale);
    float k1 = k[i], k2 = k[i + 64];
    k[i]      = t32(k1 * c - k2 * sn);
    k[i + 64] = t32(k2 * c + k1 * sn);
    v[i]      = t32(v[i]);
    v[i + 64] = t32(v[i + 64]);
}

// ================== fused flash attention (tf32 mma, pipelined K/V) ======
#define KT 32
#define Q_LD 132
#define K_LD 132
#define V_LD 136
#define P_LD 36
#define SM_Q 0
#define SM_K (128 * Q_LD)
#define SM_V (SM_K + 2 * KT * K_LD)
#define SM_P (SM_V + 2 * KT * V_LD)
#define FA_SMEM_FLOATS (SM_P + 8 * 16 * P_LD)
#define FA_SMEM_BYTES (FA_SMEM_FLOATS * 4)

__device__ __forceinline__ void mma_tf32(float* d, unsigned a0, unsigned a1,
                                         unsigned a2, unsigned a3,
                                         unsigned b0, unsigned b1) {
    asm volatile(
        "mma.sync.aligned.m16n8k8.row.col.f32.tf32.tf32.f32 "
        "{%0,%1,%2,%3}, {%4,%5,%6,%7}, {%8,%9}, {%0,%1,%2,%3};\n"
        : "+f"(d[0]), "+f"(d[1]), "+f"(d[2]), "+f"(d[3])
        : "r"(a0), "r"(a1), "r"(a2), "r"(a3), "r"(b0), "r"(b1));
}

__global__ __launch_bounds__(256, 1)
void flash_kernel(const float* __restrict__ qkv, __half* __restrict__ attn) {
    extern __shared__ float sm[];
    const int h  = blockIdx.y;
    const int by = (gridDim.x - 1) - blockIdx.x;   // heavy tiles first
    const int tid  = threadIdx.x;
    const int wid  = tid >> 5;
    const int lane = tid & 31;
    const int g = lane >> 2;
    const int c = lane & 3;

    float* Qs = sm + SM_Q;
    float* Ks = sm + SM_K;
    float* Vs = sm + SM_V;
    float* Ps = sm + SM_P + wid * 16 * P_LD;

    const float* Qg = qkv + (size_t)h * HD;
    const float* Kg = qkv + HID + (size_t)h * HD;
    const float* Vg = qkv + 2 * HID + (size_t)h * HD;

    const int ktmax = 4 * by + 4;

    {
        for (int i = tid; i < KT * 32; i += 256) {
            int r  = i >> 5;
            int c4 = (i & 31) << 2;
            cp_async16(&Ks[r * K_LD + c4], Kg + (size_t)r * QKVN + c4);
            cp_async16(&Vs[r * V_LD + c4], Vg + (size_t)r * QKVN + c4);
        }
        cp_commit();
    }

    for (int i = tid; i < 128 * 32; i += 256) {
        int r  = i >> 5;
        int c4 = (i & 31) << 2;
        float4 v = *(const float4*)(Qg + (size_t)(by * 128 + r) * QKVN + c4);
        int base = c4 & ~7;
        int off  = (c4 >> 2) & 1;
        float* dst = Qs + r * Q_LD + base + off;
        dst[0] = v.x; dst[2] = v.y; dst[4] = v.z; dst[6] = v.w;
    }

    float o[16][4];
#pragma unroll
    for (int i = 0; i < 16; i++)
#pragma unroll
        for (int j = 0; j < 4; j++) o[i][j] = 0.0f;
    float m0 = -1e30f, m1 = -1e30f, l0 = 0.0f, l1 = 0.0f;

    const int row0 = by * 128 + wid * 16 + g;
    const int row1 = row0 + 8;

    for (int kt = 0; kt < ktmax; kt++) {
        if (kt + 1 < ktmax) {
            const int nb   = (kt + 1) & 1;
            const int key0 = (kt + 1) * KT;
            for (int i = tid; i < KT * 32; i += 256) {
                int r  = i >> 5;
                int c4 = (i & 31) << 2;
                cp_async16(&Ks[nb * KT * K_LD + r * K_LD + c4],
                           Kg + (size_t)(key0 + r) * QKVN + c4);
                cp_async16(&Vs[nb * KT * V_LD + r * V_LD + c4],
                           Vg + (size_t)(key0 + r) * QKVN + c4);
            }
        }
        cp_commit();
        cp_wait<1>();
        __syncthreads();

        const float* Kbuf = Ks + (kt & 1) * KT * K_LD;
        const float* Vbuf = Vs + (kt & 1) * KT * V_LD;
        const int key0 = kt * KT;

        float s[4][4];
#pragma unroll
        for (int i = 0; i < 4; i++)
#pragma unroll
            for (int j = 0; j < 4; j++) s[i][j] = 0.0f;

        const unsigned* Qr0 = (const unsigned*)(Qs + (wid * 16 + g) * Q_LD);
        const unsigned* Qr1 = Qr0 + 8 * Q_LD;
#pragma unroll
        for (int ks = 0; ks < 16; ks++) {
            uint2 a02 = *(const uint2*)(Qr0 + ks * 8 + 2 * c);
            uint2 a13 = *(const uint2*)(Qr1 + ks * 8 + 2 * c);
#pragma unroll
            for (int nt = 0; nt < 4; nt++) {
                const float* kb = Kbuf + (nt * 8 + g) * K_LD + ks * 8 + c;
                mma_tf32(s[nt], a02.x, a13.x, a02.y, a13.y,
                         __float_as_uint(kb[0]), __float_as_uint(kb[4]));
            }
        }

        if (kt >= 4 * by) {
#pragma unroll
            for (int nt = 0; nt < 4; nt++) {
                int col = key0 + nt * 8 + 2 * c;
                if (col     > row0) s[nt][0] = -1e30f;
                if (col + 1 > row0) s[nt][1] = -1e30f;
                if (col     > row1) s[nt][2] = -1e30f;
                if (col + 1 > row1) s[nt][3] = -1e30f;
            }
        }

        float tm0 = -1e30f, tm1 = -1e30f;
#pragma unroll
        for (int nt = 0; nt < 4; nt++) {
            tm0 = fmaxf(tm0, fmaxf(s[nt][0], s[nt][1]));
            tm1 = fmaxf(tm1, fmaxf(s[nt][2], s[nt][3]));
        }
        tm0 = fmaxf(tm0, __shfl_xor_sync(0xffffffffu, tm0, 1));
        tm0 = fmaxf(tm0, __shfl_xor_sync(0xffffffffu, tm0, 2));
        tm1 = fmaxf(tm1, __shfl_xor_sync(0xffffffffu, tm1, 1));
        tm1 = fmaxf(tm1, __shfl_xor_sync(0xffffffffu, tm1, 2));

        float mn0 = fmaxf(m0, tm0), mn1 = fmaxf(m1, tm1);
        float al0 = __expf(m0 - mn0), al1 = __expf(m1 - mn1);
        m0 = mn0; m1 = mn1;

        const int pos0 = (c & 1) * 4 + (c >> 1);
        const int pos1 = pos0 + 2;
        float sum0 = 0.0f, sum1 = 0.0f;
#pragma unroll
        for (int nt = 0; nt < 4; nt++) {
            float p0 = __expf(s[nt][0] - mn0);
            float p1 = __expf(s[nt][1] - mn0);
            float p2 = __expf(s[nt][2] - mn1);
            float p3 = __expf(s[nt][3] - mn1);
            sum0 += p0 + p1;
            sum1 += p2 + p3;
            Ps[g * P_LD + nt * 8 + pos0]       = t32(p0);
            Ps[g * P_LD + nt * 8 + pos1]       = t32(p1);
            Ps[(g + 8) * P_LD + nt * 8 + pos0] = t32(p2);
            Ps[(g + 8) * P_LD + nt * 8 + pos1] = t32(p3);
        }
        sum0 += __shfl_xor_sync(0xffffffffu, sum0, 1);
        sum0 += __shfl_xor_sync(0xffffffffu, sum0, 2);
        sum1 += __shfl_xor_sync(0xffffffffu, sum1, 1);
        sum1 += __shfl_xor_sync(0xffffffffu, sum1, 2);
        l0 = l0 * al0 + sum0;
        l1 = l1 * al1 + sum1;

#pragma unroll
        for (int nt = 0; nt < 16; nt++) {
            o[nt][0] *= al0; o[nt][1] *= al0;
            o[nt][2] *= al1; o[nt][3] *= al1;
        }
        __syncwarp();

        const unsigned* Pr0 = (const unsigned*)(Ps + g * P_LD);
        const unsigned* Pr1 = Pr0 + 8 * P_LD;
#pragma unroll
        for (int ks = 0; ks < 4; ks++) {
            uint2 a02 = *(const uint2*)(Pr0 + ks * 8 + 2 * c);
            uint2 a13 = *(const uint2*)(Pr1 + ks * 8 + 2 * c);
            const float* vb0 = Vbuf + (ks * 8 + c) * V_LD + g;
            const float* vb1 = vb0 + 4 * V_LD;
#pragma unroll
            for (int nt = 0; nt < 16; nt++) {
                mma_tf32(o[nt], a02.x, a13.x, a02.y, a13.y,
                         __float_as_uint(vb0[nt * 8]), __float_as_uint(vb1[nt * 8]));
            }
        }
        __syncwarp();
        __syncthreads();
    }

    // ---- epilogue: normalize, emit fp16 for O-projection ----
    float inv0 = 1.0f / l0;
    float inv1 = 1.0f / l1;
    __half* out0 = attn + (size_t)row0 * HID + h * HD;
    __half* out1 = attn + (size_t)row1 * HID + h * HD;
#pragma unroll
    for (int nt = 0; nt < 16; nt++) {
        __half2 v0 = __floats2half2_rn(o[nt][0] * inv0, o[nt][1] * inv0);
        __half2 v1 = __floats2half2_rn(o[nt][2] * inv1, o[nt][3] * inv1);
        *(__half2*)(out0 + nt * 8 + 2 * c) = v0;
        *(__half2*)(out1 + nt * 8 + 2 * c) = v1;
    }
}

// ---------------- launch ----------------
extern "C" void kernel_launch(void* const* d_in, const int* in_sizes, int n_in,
                              void* d_out, int out_size) {
    const float* hs   = (const float*)d_in[1];
    const float* Wqkv = (const float*)d_in[2];
    const float* bqkv = (const float*)d_in[3];
    const float* Wo   = (const float*)d_in[4];
    const float* bo   = (const float*)d_in[5];
    float* out = (float*)d_out;

    float* qkv;
    __half *attn16, *hs16, *wq16, *wo16;
    cudaGetSymbolAddress((void**)&qkv,    g_qkv);
    cudaGetSymbolAddress((void**)&attn16, g_attn16);
    cudaGetSymbolAddress((void**)&hs16,   g_hs16);
    cudaGetSymbolAddress((void**)&wq16,   g_wq16);
    cudaGetSymbolAddress((void**)&wo16,   g_wo16);

    cudaFuncSetAttribute(flash_kernel, cudaFuncAttributeMaxDynamicSharedMemorySize,
                         FA_SMEM_BYTES);
    cudaFuncSetAttribute(gemm_f16_bias, cudaFuncAttributeMaxDynamicSharedMemorySize,
                         GEMM_SMEM_BYTES);

    // 0) fp16 pre-conversion of GEMM operands (row-major, no transpose)
    cvt_f16<<<(SEQ * HID / 4 + 255) / 256, 256>>>(hs, hs16, SEQ * HID / 4);
    cvt_f16<<<(int)(((size_t)HID * QKVN / 4 + 255) / 256), 256>>>(Wqkv, wq16,
                                                                  HID * QKVN / 4);
    cvt_f16<<<(HID * HID / 4 + 255) / 256, 256>>>(Wo, wo16, HID * HID / 4);

    // 1) QKV = hs @ Wqkv + bqkv   (fp16 tensor cores, fp32 accum)
    gemm_f16_bias<<<dim3(QKVN / BN, SEQ / BM), 256, GEMM_SMEM_BYTES>>>(
        hs16, wq16, bqkv, qkv, HID, QKVN);
    // 2) RoPE (+ tf32 rounding of q,k,v; q pre-scaled)
    rope_kernel<<<(SEQ * NH * 64 + 255) / 256, 256>>>(qkv);
    // 3) fused flash attention -> g_attn16 (fp16)
    flash_kernel<<<dim3(SEQ / 128, NH), 256, FA_SMEM_BYTES>>>(qkv, attn16);
    // 4) out = attn @ Wo + bo   (fp16 tensor cores, fp32 accum)
    gemm_f16_bias<<<dim3(HID / BN, SEQ / BM), 256, GEMM_SMEM_BYTES>>>(
        attn16, wo16, bo, out, HID, HID);
}

// round 8
// speedup vs baseline: 4.6267x; 1.1071x over previous
#include <cuda_runtime.h>
#include <cuda_fp16.h>
#include <cstdint>
#include <mma.h>
#include <math.h>
#include <float.h>

using namespace nvcuda;

#define SEQ   2048
#define HID   4096
#define NH    32
#define HD    128
#define QKVN  12288   // 3*HID

// ---------------- scratch (no cudaMalloc allowed) ----------------
__device__ float  g_qkv[SEQ * QKVN];            // 100 MB (QKV GEMM out, fp32)
__device__ __half g_attn16[SEQ * HID];          // 17 MB  (flash out, O-proj in)
__device__ __half g_hs16[SEQ * HID];            // 17 MB  fp16(hs)
__device__ __half g_wq16[(size_t)HID * QKVN];   // 100 MB fp16(Wqkv) row-major
__device__ __half g_wo16[(size_t)HID * HID];    // 34 MB  fp16(Wo)   row-major
__device__ __half g_qk16[SEQ * 2 * HID];        // 34 MB  roped q,k fp16 (dim-permuted)
__device__ __half g_vT[(size_t)NH * HD * SEQ];  // 17 MB  V^T per head (key-permuted)

// ---------------- cp.async helpers ----------------
__device__ __forceinline__ void cp_async16(void* smem_dst, const void* gsrc) {
    unsigned s = (unsigned)__cvta_generic_to_shared(smem_dst);
    asm volatile("cp.async.cg.shared.global [%0], [%1], 16;\n" :: "r"(s), "l"(gsrc));
}
__device__ __forceinline__ void cp_commit() {
    asm volatile("cp.async.commit_group;\n");
}
template <int N> __device__ __forceinline__ void cp_wait() {
    asm volatile("cp.async.wait_group %0;\n" :: "n"(N));
}

// permutation within a 16-element chunk: pairs (2c,2c+1,2c+8,2c+9) adjacent
__device__ __forceinline__ int p16(int h) {
    return (h < 8) ? ((h >> 1) << 2) + (h & 1)
                   : (((h - 8) >> 1) << 2) + 2 + (h & 1);
}
__device__ __forceinline__ int permd(int d) {   // full permutation over chunks
    return (d & ~15) + p16(d & 15);
}

// ---------------- fp16 pre-convert ----------------
__global__ __launch_bounds__(256)
void cvt_f16(const float* __restrict__ in, __half* __restrict__ out, int n4) {
    int i = blockIdx.x * blockDim.x + threadIdx.x;
    if (i < n4) {
        float4 v = ((const float4*)in)[i];
        __half2 h0 = __floats2half2_rn(v.x, v.y);
        __half2 h1 = __floats2half2_rn(v.z, v.w);
        uint2 pk;
        pk.x = *(unsigned*)&h0;
        pk.y = *(unsigned*)&h1;
        ((uint2*)out)[i] = pk;
    }
}

// ================= fp16 tensor-core GEMM + bias (3-stage pipeline) =======
#define BM 128
#define BN 128
#define BK 32
#define A_LD 40
#define B_LD 136
#define STG 3
#define GEMM_SMEM_BYTES (STG * (BM * A_LD + BK * B_LD) * 2)

__global__ __launch_bounds__(256)
void gemm_f16_bias(const __half* __restrict__ A, const __half* __restrict__ B,
                   const float* __restrict__ bias, float* __restrict__ C,
                   int K, int N) {
    extern __shared__ __half gsm[];
    __half* Asm = gsm;
    __half* Bsm = gsm + STG * BM * A_LD;

    const int tid  = threadIdx.x;
    const int wid  = tid >> 5;
    const int lane = tid & 31;
    const int warp_m = (wid >> 1) * 32;
    const int warp_n = (wid & 1) * 64;

    const int bx = blockIdx.x, by = blockIdx.y;

    const int a_row = tid >> 1;
    const int a_ck  = (tid & 1) * 16;
    const int b_row = tid >> 4;
    const int b_ck  = (tid & 15) * 8;

    const __half* Ag = A + (size_t)(by * BM) * K;
    const __half* Bg = B + bx * BN;

    wmma::fragment<wmma::accumulator, 16, 16, 16, float> acc[2][4];
#pragma unroll
    for (int i = 0; i < 2; i++)
#pragma unroll
        for (int j = 0; j < 4; j++) wmma::fill_fragment(acc[i][j], 0.0f);

    const int T = K / BK;

#pragma unroll
    for (int pt = 0; pt < 2; pt++) {
        const int k0 = pt * BK;
        __half* As_s = Asm + pt * BM * A_LD;
        __half* Bs_s = Bsm + pt * BK * B_LD;
        cp_async16(&As_s[a_row * A_LD + a_ck],     Ag + (size_t)a_row * K + k0 + a_ck);
        cp_async16(&As_s[a_row * A_LD + a_ck + 8], Ag + (size_t)a_row * K + k0 + a_ck + 8);
#pragma unroll
        for (int p = 0; p < 2; p++) {
            int r = b_row + p * 16;
            cp_async16(&Bs_s[r * B_LD + b_ck], Bg + (size_t)(k0 + r) * N + b_ck);
        }
        cp_commit();
    }

    for (int t = 0; t < T; t++) {
        if (t + 2 < T) {
            const int s  = (t + 2) % 3;
            const int k0 = (t + 2) * BK;
            __half* As_s = Asm + s * BM * A_LD;
            __half* Bs_s = Bsm + s * BK * B_LD;
            cp_async16(&As_s[a_row * A_LD + a_ck],     Ag + (size_t)a_row * K + k0 + a_ck);
            cp_async16(&As_s[a_row * A_LD + a_ck + 8], Ag + (size_t)a_row * K + k0 + a_ck + 8);
#pragma unroll
            for (int p = 0; p < 2; p++) {
                int r = b_row + p * 16;
                cp_async16(&Bs_s[r * B_LD + b_ck], Bg + (size_t)(k0 + r) * N + b_ck);
            }
        }
        cp_commit();
        cp_wait<2>();
        __syncthreads();

        const int cur = t % 3;
        const __half* At = Asm + cur * BM * A_LD;
        const __half* Bt = Bsm + cur * BK * B_LD;
#pragma unroll
        for (int kk = 0; kk < BK; kk += 16) {
            wmma::fragment<wmma::matrix_a, 16, 16, 16, __half, wmma::row_major> af[2];
#pragma unroll
            for (int i = 0; i < 2; i++)
                wmma::load_matrix_sync(af[i], At + (warp_m + i * 16) * A_LD + kk, A_LD);
            wmma::fragment<wmma::matrix_b, 16, 16, 16, __half, wmma::row_major> bf[4];
#pragma unroll
            for (int j = 0; j < 4; j++)
                wmma::load_matrix_sync(bf[j], Bt + kk * B_LD + warp_n + j * 16, B_LD);
#pragma unroll
            for (int i = 0; i < 2; i++)
#pragma unroll
                for (int j = 0; j < 4; j++)
                    wmma::mma_sync(acc[i][j], af[i], bf[j], acc[i][j]);
        }
        __syncthreads();
    }
    __syncthreads();

    float* epi = (float*)gsm + wid * 256;
#pragma unroll
    for (int i = 0; i < 2; i++) {
#pragma unroll
        for (int j = 0; j < 4; j++) {
            wmma::store_matrix_sync(epi, acc[i][j], 16, wmma::mem_row_major);
            __syncwarp();
            int r = lane >> 1;
            int c = (lane & 1) * 8;
            int grow = by * BM + warp_m + i * 16 + r;
            int gcol = bx * BN + warp_n + j * 16 + c;
            float4 v0 = *(float4*)&epi[r * 16 + c];
            float4 v1 = *(float4*)&epi[r * 16 + c + 4];
            const float* bp = bias + gcol;
            v0.x += bp[0]; v0.y += bp[1]; v0.z += bp[2]; v0.w += bp[3];
            v1.x += bp[4]; v1.y += bp[5]; v1.z += bp[6]; v1.w += bp[7];
            float* cp = C + (size_t)grow * N + gcol;
            *(float4*)cp = v0;
            *(float4*)(cp + 4) = v1;
            __syncwarp();
        }
    }
}

// ---------------- RoPE: fp32 qkv -> fp16 q,k (dim-permuted, q scaled) ----
__global__ __launch_bounds__(256)
void rope16_kernel(const float* __restrict__ qkv, __half* __restrict__ qk16) {
    int idx = blockIdx.x * blockDim.x + threadIdx.x;
    if (idx >= SEQ * NH * 64) return;
    int i = idx & 63;
    int h = (idx >> 6) & 31;
    int s = idx >> 11;
    double invf = exp(-log(10000.0) * (double)(2 * i) / 128.0);
    double f = (double)s * invf;
    float c  = (float)cos(f);
    float sn = (float)sin(f);
    const float scale = 0.08838834764831843f;
    const float* q = qkv + (size_t)s * QKVN + h * HD;
    const float* k = q + HID;
    __half* oq = qk16 + (size_t)s * 2 * HID + h * HD;
    __half* ok = oq + HID;
    float q1 = q[i], q2 = q[i + 64];
    oq[permd(i)]      = __float2half((q1 * c - q2 * sn) * scale);
    oq[permd(i + 64)] = __float2half((q2 * c + q1 * sn) * scale);
    float k1 = k[i], k2 = k[i + 64];
    ok[permd(i)]      = __float2half(k1 * c - k2 * sn);
    ok[permd(i + 64)] = __float2half(k2 * c + k1 * sn);
}

// ---------------- V transpose: fp32 v -> fp16 vT[h][d][seq] (key-perm) ---
__global__ __launch_bounds__(256)
void vT_kernel(const float* __restrict__ qkv, __half* __restrict__ vT) {
    __shared__ float tile[32][33];
    const int h  = blockIdx.z;
    const int s0 = blockIdx.x * 32;
    const int d0 = blockIdx.y * 32;
    int di = threadIdx.x & 31;
    int si = threadIdx.x >> 5;     // 0..7, x4
#pragma unroll
    for (int j = 0; j < 4; j++) {
        int s = si + j * 8;
        tile[s][di] = qkv[(size_t)(s0 + s) * QKVN + 2 * HID + h * HD + d0 + di];
    }
    __syncthreads();
    int sj = threadIdx.x & 31;
    int wj = threadIdx.x >> 5;
    int sp = (sj & 16) + p16(sj & 15);   // key permutation within 32
#pragma unroll
    for (int j = 0; j < 4; j++) {
        int d = wj + j * 8;
        vT[(size_t)(h * HD + d0 + d) * SEQ + s0 + sp] = __float2half(tile[sj][d]);
    }
}

// ================== fused flash attention (fp16 m16n8k16) ======
// 128 q-rows x 1 head per CTA, 8 warps x 16 rows, 32-key tiles double-buffered.
// All operand loads are single conflict-free LDS.64 (strides 288B / 96B).
#define KT 32
#define QK_LDH 144          // halves; 288B rows (72 banks = 8 mod 32)
#define VT_LDH 48           // halves; 96B rows  (24 banks)
#define P_LDH  48
#define SM_Q 0
#define SM_K (128 * QK_LDH)                  // 18432
#define SM_V (SM_K + 2 * KT * QK_LDH)        // 27648
#define SM_P (SM_V + 2 * HD * VT_LDH)        // 39936
#define FA_SMEM_HALVES (SM_P + 8 * 16 * P_LDH)
#define FA_SMEM_BYTES (FA_SMEM_HALVES * 2)   // 92160

__device__ __forceinline__ void mma_f16(float* d, unsigned a0, unsigned a1,
                                        unsigned a2, unsigned a3,
                                        unsigned b0, unsigned b1) {
    asm volatile(
        "mma.sync.aligned.m16n8k16.row.col.f32.f16.f16.f32 "
        "{%0,%1,%2,%3}, {%4,%5,%6,%7}, {%8,%9}, {%0,%1,%2,%3};\n"
        : "+f"(d[0]), "+f"(d[1]), "+f"(d[2]), "+f"(d[3])
        : "r"(a0), "r"(a1), "r"(a2), "r"(a3), "r"(b0), "r"(b1));
}

__global__ __launch_bounds__(256, 2)
void flash_kernel(const __half* __restrict__ qk16, const __half* __restrict__ vT,
                  __half* __restrict__ attn) {
    extern __shared__ __half smh[];
    const int h  = blockIdx.y;
    const int by = (gridDim.x - 1) - blockIdx.x;   // heavy tiles first
    const int tid  = threadIdx.x;
    const int wid  = tid >> 5;
    const int lane = tid & 31;
    const int g = lane >> 2;
    const int c = lane & 3;

    __half* Qs = smh + SM_Q;
    __half* Ks = smh + SM_K;
    __half* Vs = smh + SM_V;
    __half* Ps = smh + SM_P + wid * 16 * P_LDH;   // warp-private

    const __half* Qg = qk16 + h * HD;
    const __half* Kg = qk16 + HID + h * HD;
    const __half* Vg = vT + (size_t)h * HD * SEQ;

    const int ktmax = 4 * by + 4;

    // prefetch K/V tile 0 (buffer 0)
    for (int i = tid; i < 512; i += 256) {
        int r = i >> 4, ch = (i & 15) * 8;
        cp_async16(&Ks[r * QK_LDH + ch], Kg + (size_t)r * 2 * HID + ch);
    }
    for (int i = tid; i < 512; i += 256) {
        int r = i >> 2, ch = (i & 3) * 8;
        cp_async16(&Vs[r * VT_LDH + ch], Vg + (size_t)r * SEQ + ch);
    }
    cp_commit();

    // Q tile (already permuted+scaled fp16 in global)
    for (int i = tid; i < 128 * 16; i += 256) {
        int r = i >> 4, ch = (i & 15) * 8;
        cp_async16(&Qs[r * QK_LDH + ch],
                   Qg + (size_t)(by * 128 + r) * 2 * HID + ch);
    }
    cp_commit();

    float o[16][4];
#pragma unroll
    for (int i = 0; i < 16; i++)
#pragma unroll
        for (int j = 0; j < 4; j++) o[i][j] = 0.0f;
    float m0 = -1e30f, m1 = -1e30f, l0 = 0.0f, l1 = 0.0f;

    const int row0 = by * 128 + wid * 16 + g;
    const int row1 = row0 + 8;

    for (int kt = 0; kt < ktmax; kt++) {
        if (kt + 1 < ktmax) {
            const int nb   = (kt + 1) & 1;
            const int key0 = (kt + 1) * KT;
            for (int i = tid; i < 512; i += 256) {
                int r = i >> 4, ch = (i & 15) * 8;
                cp_async16(&Ks[nb * KT * QK_LDH + r * QK_LDH + ch],
                           Kg + (size_t)(key0 + r) * 2 * HID + ch);
            }
            for (int i = tid; i < 512; i += 256) {
                int r = i >> 2, ch = (i & 3) * 8;
                cp_async16(&Vs[nb * HD * VT_LDH + r * VT_LDH + ch],
                           Vg + (size_t)r * SEQ + key0 + ch);
            }
        }
        cp_commit();
        cp_wait<1>();
        __syncthreads();

        const __half* Kbuf = Ks + (kt & 1) * KT * QK_LDH;
        const __half* Vbuf = Vs + (kt & 1) * HD * VT_LDH;
        const int key0 = kt * KT;

        // ---- S = Q K^T (16 rows x 32 keys per warp) ----
        float s[4][4];
#pragma unroll
        for (int i = 0; i < 4; i++)
#pragma unroll
            for (int j = 0; j < 4; j++) s[i][j] = 0.0f;

        const __half* Qr0 = Qs + (wid * 16 + g) * QK_LDH;
        const __half* Qr1 = Qr0 + 8 * QK_LDH;
#pragma unroll
        for (int ks = 0; ks < 8; ks++) {
            uint2 a02 = *(const uint2*)(Qr0 + ks * 16 + 4 * c);
            uint2 a13 = *(const uint2*)(Qr1 + ks * 16 + 4 * c);
#pragma unroll
            for (int nt = 0; nt < 4; nt++) {
                uint2 b = *(const uint2*)(Kbuf + (nt * 8 + g) * QK_LDH + ks * 16 + 4 * c);
                mma_f16(s[nt], a02.x, a13.x, a02.y, a13.y, b.x, b.y);
            }
        }

        // ---- causal mask (last 4 tiles of this block row) ----
        if (kt >= 4 * by) {
#pragma unroll
            for (int nt = 0; nt < 4; nt++) {
                int col = key0 + nt * 8 + 2 * c;
                if (col     > row0) s[nt][0] = -1e30f;
                if (col + 1 > row0) s[nt][1] = -1e30f;
                if (col     > row1) s[nt][2] = -1e30f;
                if (col + 1 > row1) s[nt][3] = -1e30f;
            }
        }

        // ---- online softmax (fp32) ----
        float tm0 = -1e30f, tm1 = -1e30f;
#pragma unroll
        for (int nt = 0; nt < 4; nt++) {
            tm0 = fmaxf(tm0, fmaxf(s[nt][0], s[nt][1]));
            tm1 = fmaxf(tm1, fmaxf(s[nt][2], s[nt][3]));
        }
        tm0 = fmaxf(tm0, __shfl_xor_sync(0xffffffffu, tm0, 1));
        tm0 = fmaxf(tm0, __shfl_xor_sync(0xffffffffu, tm0, 2));
        tm1 = fmaxf(tm1, __shfl_xor_sync(0xffffffffu, tm1, 1));
        tm1 = fmaxf(tm1, __shfl_xor_sync(0xffffffffu, tm1, 2));

        float mn0 = fmaxf(m0, tm0), mn1 = fmaxf(m1, tm1);
        float al0 = __expf(m0 - mn0), al1 = __expf(m1 - mn1);
        m0 = mn0; m1 = mn1;

        float sum0 = 0.0f, sum1 = 0.0f;
#pragma unroll
        for (int nt = 0; nt < 4; nt++) {
            float p0 = __expf(s[nt][0] - mn0);
            float p1 = __expf(s[nt][1] - mn0);
            float p2 = __expf(s[nt][2] - mn1);
            float p3 = __expf(s[nt][3] - mn1);
            sum0 += p0 + p1;
            sum1 += p2 + p3;
            // key k = nt*8+2c -> permuted slot (nt>>1)*16 + 4c + (nt&1)*2
            int slot = (nt >> 1) * 16 + 4 * c + ((nt & 1) << 1);
            *(__half2*)(Ps + g * P_LDH + slot)       = __floats2half2_rn(p0, p1);
            *(__half2*)(Ps + (g + 8) * P_LDH + slot) = __floats2half2_rn(p2, p3);
        }
        sum0 += __shfl_xor_sync(0xffffffffu, sum0, 1);
        sum0 += __shfl_xor_sync(0xffffffffu, sum0, 2);
        sum1 += __shfl_xor_sync(0xffffffffu, sum1, 1);
        sum1 += __shfl_xor_sync(0xffffffffu, sum1, 2);
        l0 = l0 * al0 + sum0;
        l1 = l1 * al1 + sum1;

#pragma unroll
        for (int nt = 0; nt < 16; nt++) {
            o[nt][0] *= al0; o[nt][1] *= al0;
            o[nt][2] *= al1; o[nt][3] *= al1;
        }
        __syncwarp();

        // ---- O += P V  (A=P 16x32 keys, B=V^T; n = head dims) ----
        const __half* Pr0 = Ps + g * P_LDH;
        const __half* Pr1 = Pr0 + 8 * P_LDH;
#pragma unroll
        for (int ks = 0; ks < 2; ks++) {
            uint2 a02 = *(const uint2*)(Pr0 + ks * 16 + 4 * c);
            uint2 a13 = *(const uint2*)(Pr1 + ks * 16 + 4 * c);
#pragma unroll
            for (int nt = 0; nt < 16; nt++) {
                uint2 b = *(const uint2*)(Vbuf + (nt * 8 + g) * VT_LDH + ks * 16 + 4 * c);
                mma_f16(o[nt], a02.x, a13.x, a02.y, a13.y, b.x, b.y);
            }
        }
        __syncwarp();
        __syncthreads();
    }

    // ---- epilogue: normalize, emit fp16 for O-projection ----
    float inv0 = 1.0f / l0;
    float inv1 = 1.0f / l1;
    __half* out0 = attn + (size_t)row0 * HID + h * HD;
    __half* out1 = attn + (size_t)row1 * HID + h * HD;
#pragma unroll
    for (int nt = 0; nt < 16; nt++) {
        *(__half2*)(out0 + nt * 8 + 2 * c) = __floats2half2_rn(o[nt][0] * inv0, o[nt][1] * inv0);
        *(__half2*)(out1 + nt * 8 + 2 * c) = __floats2half2_rn(o[nt][2] * inv1, o[nt][3] * inv1);
    }
}

// ---------------- launch ----------------
extern "C" void kernel_launch(void* const* d_in, const int* in_sizes, int n_in,
                              void* d_out, int out_size) {
    const float* hs   = (const float*)d_in[1];
    const float* Wqkv = (const float*)d_in[2];
    const float* bqkv = (const float*)d_in[3];
    const float* Wo   = (const float*)d_in[4];
    const float* bo   = (const float*)d_in[5];
    float* out = (float*)d_out;

    float* qkv;
    __half *attn16, *hs16, *wq16, *wo16, *qk16, *vT;
    cudaGetSymbolAddress((void**)&qkv,    g_qkv);
    cudaGetSymbolAddress((void**)&attn16, g_attn16);
    cudaGetSymbolAddress((void**)&hs16,   g_hs16);
    cudaGetSymbolAddress((void**)&wq16,   g_wq16);
    cudaGetSymbolAddress((void**)&wo16,   g_wo16);
    cudaGetSymbolAddress((void**)&qk16,   g_qk16);
    cudaGetSymbolAddress((void**)&vT,     g_vT);

    cudaFuncSetAttribute(flash_kernel, cudaFuncAttributeMaxDynamicSharedMemorySize,
                         FA_SMEM_BYTES);
    cudaFuncSetAttribute(gemm_f16_bias, cudaFuncAttributeMaxDynamicSharedMemorySize,
                         GEMM_SMEM_BYTES);

    // 0) fp16 pre-conversion of GEMM operands
    cvt_f16<<<(SEQ * HID / 4 + 255) / 256, 256>>>(hs, hs16, SEQ * HID / 4);
    cvt_f16<<<(int)(((size_t)HID * QKVN / 4 + 255) / 256), 256>>>(Wqkv, wq16,
                                                                  HID * QKVN / 4);
    cvt_f16<<<(HID * HID / 4 + 255) / 256, 256>>>(Wo, wo16, HID * HID / 4);

    // 1) QKV = hs @ Wqkv + bqkv  (fp16 tensor cores, fp32 accum)
    gemm_f16_bias<<<dim3(QKVN / BN, SEQ / BM), 256, GEMM_SMEM_BYTES>>>(
        hs16, wq16, bqkv, qkv, HID, QKVN);
    // 2) RoPE -> fp16 q,k (dim-permuted, q scaled); V^T -> fp16 (key-perm)
    rope16_kernel<<<(SEQ * NH * 64 + 255) / 256, 256>>>(qkv, qk16);
    vT_kernel<<<dim3(SEQ / 32, HD / 32, NH), 256>>>(qkv, vT);
    // 3) fused flash attention (fp16 mma) -> g_attn16
    flash_kernel<<<dim3(SEQ / 128, NH), 256, FA_SMEM_BYTES>>>(qk16, vT, attn16);
    // 4) out = attn @ Wo + bo  (fp16 tensor cores, fp32 accum)
    gemm_f16_bias<<<dim3(HID / BN, SEQ / BM), 256, GEMM_SMEM_BYTES>>>(
        attn16, wo16, bo, out, HID, HID);
}

// round 9
// speedup vs baseline: 4.7027x; 1.0164x over previous
#include <cuda_runtime.h>
#include <cuda_fp16.h>
#include <cstdint>
#include <mma.h>
#include <math.h>
#include <float.h>

using namespace nvcuda;

#define SEQ   2048
#define HID   4096
#define NH    32
#define HD    128
#define QKVN  12288   // 3*HID

// ---------------- scratch (no cudaMalloc allowed) ----------------
__device__ float  g_qkv[SEQ * QKVN];            // 100 MB (QKV GEMM out, fp32)
__device__ __half g_attn16[SEQ * HID];          // 17 MB  (flash out, O-proj in)
__device__ __half g_hs16[SEQ * HID];            // 17 MB  fp16(hs)
__device__ __half g_wq16[(size_t)HID * QKVN];   // 100 MB fp16(Wqkv) row-major
__device__ __half g_wo16[(size_t)HID * HID];    // 34 MB  fp16(Wo)   row-major
__device__ __half g_qk16[SEQ * 2 * HID];        // 34 MB  roped q,k fp16 (dim-permuted)
__device__ __half g_vT[(size_t)NH * HD * SEQ];  // 17 MB  V^T per head (key-permuted)

// ---------------- cp.async helpers ----------------
__device__ __forceinline__ void cp_async16(void* smem_dst, const void* gsrc) {
    unsigned s = (unsigned)__cvta_generic_to_shared(smem_dst);
    asm volatile("cp.async.cg.shared.global [%0], [%1], 16;\n" :: "r"(s), "l"(gsrc));
}
__device__ __forceinline__ void cp_commit() {
    asm volatile("cp.async.commit_group;\n");
}
template <int N> __device__ __forceinline__ void cp_wait() {
    asm volatile("cp.async.wait_group %0;\n" :: "n"(N));
}

// permutation within a 16-element chunk: pairs (2c,2c+1,2c+8,2c+9) adjacent
__device__ __forceinline__ int p16(int h) {
    return (h < 8) ? ((h >> 1) << 2) + (h & 1)
                   : (((h - 8) >> 1) << 2) + 2 + (h & 1);
}
__device__ __forceinline__ int permd(int d) {   // full permutation over chunks
    return (d & ~15) + p16(d & 15);
}

// ---------------- fp16 pre-convert ----------------
__global__ __launch_bounds__(256)
void cvt_f16(const float* __restrict__ in, __half* __restrict__ out, int n4) {
    int i = blockIdx.x * blockDim.x + threadIdx.x;
    if (i < n4) {
        float4 v = ((const float4*)in)[i];
        __half2 h0 = __floats2half2_rn(v.x, v.y);
        __half2 h1 = __floats2half2_rn(v.z, v.w);
        uint2 pk;
        pk.x = *(unsigned*)&h0;
        pk.y = *(unsigned*)&h1;
        ((uint2*)out)[i] = pk;
    }
}

// ================= fp16 tensor-core GEMM + bias =================
// Tile 128x256x32, 512 threads (16 warps, 4x4), warp tile 32x64.
// 3-stage cp.async pipeline. High arithmetic intensity: 24KB loads / 2M flops.
#define BM 128
#define BN 256
#define BK 32
#define A_LD 40      // halves (80B rows; 20 banks stride, conflict-free LDSM)
#define B_LD 264     // halves (528B rows; 132 banks = 4 mod 32, conflict-free)
#define STG 3
#define GEMM_SMEM_BYTES (STG * (BM * A_LD + BK * B_LD) * 2)   // 81408

__global__ __launch_bounds__(512)
void gemm_f16_bias(const __half* __restrict__ A, const __half* __restrict__ B,
                   const float* __restrict__ bias, float* __restrict__ C,
                   int K, int N) {
    extern __shared__ __half gsm[];
    __half* Asm = gsm;                       // [STG][BM][A_LD]
    __half* Bsm = gsm + STG * BM * A_LD;     // [STG][BK][B_LD]

    const int tid  = threadIdx.x;
    const int wid  = tid >> 5;
    const int lane = tid & 31;
    const int warp_m = (wid & 3) * 32;       // 0,32,64,96
    const int warp_n = (wid >> 2) * 64;      // 0,64,128,192

    const int bx = blockIdx.x, by = blockIdx.y;

    // global-load mapping (16B = 8-half chunks)
    const int a_row = tid >> 2;              // 0..127
    const int a_ck  = (tid & 3) * 8;         // halves 0,8,16,24
    const int b_row = tid >> 5;              // 0..15 (+16 second pass)
    const int b_ck  = (tid & 31) * 8;        // halves 0..248

    const __half* Ag = A + (size_t)(by * BM) * K;
    const __half* Bg = B + bx * BN;

    wmma::fragment<wmma::accumulator, 16, 16, 16, float> acc[2][4];
#pragma unroll
    for (int i = 0; i < 2; i++)
#pragma unroll
        for (int j = 0; j < 4; j++) wmma::fill_fragment(acc[i][j], 0.0f);

    const int T = K / BK;

    // prologue: stages 0 and 1
#pragma unroll
    for (int pt = 0; pt < 2; pt++) {
        const int k0 = pt * BK;
        __half* As_s = Asm + pt * BM * A_LD;
        __half* Bs_s = Bsm + pt * BK * B_LD;
        cp_async16(&As_s[a_row * A_LD + a_ck], Ag + (size_t)a_row * K + k0 + a_ck);
#pragma unroll
        for (int p = 0; p < 2; p++) {
            int r = b_row + p * 16;
            cp_async16(&Bs_s[r * B_LD + b_ck], Bg + (size_t)(k0 + r) * N + b_ck);
        }
        cp_commit();
    }

    for (int t = 0; t < T; t++) {
        if (t + 2 < T) {
            const int s  = (t + 2) % 3;
            const int k0 = (t + 2) * BK;
            __half* As_s = Asm + s * BM * A_LD;
            __half* Bs_s = Bsm + s * BK * B_LD;
            cp_async16(&As_s[a_row * A_LD + a_ck], Ag + (size_t)a_row * K + k0 + a_ck);
#pragma unroll
            for (int p = 0; p < 2; p++) {
                int r = b_row + p * 16;
                cp_async16(&Bs_s[r * B_LD + b_ck], Bg + (size_t)(k0 + r) * N + b_ck);
            }
        }
        cp_commit();
        cp_wait<2>();
        __syncthreads();

        const int cur = t % 3;
        const __half* At = Asm + cur * BM * A_LD;
        const __half* Bt = Bsm + cur * BK * B_LD;
#pragma unroll
        for (int kk = 0; kk < BK; kk += 16) {
            wmma::fragment<wmma::matrix_a, 16, 16, 16, __half, wmma::row_major> af[2];
#pragma unroll
            for (int i = 0; i < 2; i++)
                wmma::load_matrix_sync(af[i], At + (warp_m + i * 16) * A_LD + kk, A_LD);
            wmma::fragment<wmma::matrix_b, 16, 16, 16, __half, wmma::row_major> bf[4];
#pragma unroll
            for (int j = 0; j < 4; j++)
                wmma::load_matrix_sync(bf[j], Bt + kk * B_LD + warp_n + j * 16, B_LD);
#pragma unroll
            for (int i = 0; i < 2; i++)
#pragma unroll
                for (int j = 0; j < 4; j++)
                    wmma::mma_sync(acc[i][j], af[i], bf[j], acc[i][j]);
        }
        __syncthreads();
    }
    __syncthreads();

    // epilogue: stage each 16x16 patch through smem (as float), add fp32 bias
    float* epi = (float*)gsm + wid * 256;
#pragma unroll
    for (int i = 0; i < 2; i++) {
#pragma unroll
        for (int j = 0; j < 4; j++) {
            wmma::store_matrix_sync(epi, acc[i][j], 16, wmma::mem_row_major);
            __syncwarp();
            int r = lane >> 1;
            int c = (lane & 1) * 8;
            int grow = by * BM + warp_m + i * 16 + r;
            int gcol = bx * BN + warp_n + j * 16 + c;
            float4 v0 = *(float4*)&epi[r * 16 + c];
            float4 v1 = *(float4*)&epi[r * 16 + c + 4];
            const float* bp = bias + gcol;
            v0.x += bp[0]; v0.y += bp[1]; v0.z += bp[2]; v0.w += bp[3];
            v1.x += bp[4]; v1.y += bp[5]; v1.z += bp[6]; v1.w += bp[7];
            float* cp = C + (size_t)grow * N + gcol;
            *(float4*)cp = v0;
            *(float4*)(cp + 4) = v1;
            __syncwarp();
        }
    }
}

// ---------------- RoPE: fp32 qkv -> fp16 q,k (dim-permuted, q scaled) ----
__global__ __launch_bounds__(256)
void rope16_kernel(const float* __restrict__ qkv, __half* __restrict__ qk16) {
    int idx = blockIdx.x * blockDim.x + threadIdx.x;
    if (idx >= SEQ * NH * 64) return;
    int i = idx & 63;
    int h = (idx >> 6) & 31;
    int s = idx >> 11;
    double invf = exp(-log(10000.0) * (double)(2 * i) / 128.0);
    double f = (double)s * invf;
    float c  = (float)cos(f);
    float sn = (float)sin(f);
    const float scale = 0.08838834764831843f;
    const float* q = qkv + (size_t)s * QKVN + h * HD;
    const float* k = q + HID;
    __half* oq = qk16 + (size_t)s * 2 * HID + h * HD;
    __half* ok = oq + HID;
    float q1 = q[i], q2 = q[i + 64];
    oq[permd(i)]      = __float2half((q1 * c - q2 * sn) * scale);
    oq[permd(i + 64)] = __float2half((q2 * c + q1 * sn) * scale);
    float k1 = k[i], k2 = k[i + 64];
    ok[permd(i)]      = __float2half(k1 * c - k2 * sn);
    ok[permd(i + 64)] = __float2half(k2 * c + k1 * sn);
}

// ---------------- V transpose: fp32 v -> fp16 vT[h][d][seq] (key-perm) ---
__global__ __launch_bounds__(256)
void vT_kernel(const float* __restrict__ qkv, __half* __restrict__ vT) {
    __shared__ float tile[32][33];
    const int h  = blockIdx.z;
    const int s0 = blockIdx.x * 32;
    const int d0 = blockIdx.y * 32;
    int di = threadIdx.x & 31;
    int si = threadIdx.x >> 5;     // 0..7, x4
#pragma unroll
    for (int j = 0; j < 4; j++) {
        int s = si + j * 8;
        tile[s][di] = qkv[(size_t)(s0 + s) * QKVN + 2 * HID + h * HD + d0 + di];
    }
    __syncthreads();
    int sj = threadIdx.x & 31;
    int wj = threadIdx.x >> 5;
    int sp = (sj & 16) + p16(sj & 15);   // key permutation within 32
#pragma unroll
    for (int j = 0; j < 4; j++) {
        int d = wj + j * 8;
        vT[(size_t)(h * HD + d0 + d) * SEQ + s0 + sp] = __float2half(tile[sj][d]);
    }
}

// ================== fused flash attention (fp16 m16n8k16) ======
#define KT 32
#define QK_LDH 144          // halves; 288B rows
#define VT_LDH 48           // halves; 96B rows
#define P_LDH  48
#define SM_Q 0
#define SM_K (128 * QK_LDH)
#define SM_V (SM_K + 2 * KT * QK_LDH)
#define SM_P (SM_V + 2 * HD * VT_LDH)
#define FA_SMEM_HALVES (SM_P + 8 * 16 * P_LDH)
#define FA_SMEM_BYTES (FA_SMEM_HALVES * 2)   // 92160

__device__ __forceinline__ void mma_f16(float* d, unsigned a0, unsigned a1,
                                        unsigned a2, unsigned a3,
                                        unsigned b0, unsigned b1) {
    asm volatile(
        "mma.sync.aligned.m16n8k16.row.col.f32.f16.f16.f32 "
        "{%0,%1,%2,%3}, {%4,%5,%6,%7}, {%8,%9}, {%0,%1,%2,%3};\n"
        : "+f"(d[0]), "+f"(d[1]), "+f"(d[2]), "+f"(d[3])
        : "r"(a0), "r"(a1), "r"(a2), "r"(a3), "r"(b0), "r"(b1));
}

__global__ __launch_bounds__(256, 2)
void flash_kernel(const __half* __restrict__ qk16, const __half* __restrict__ vT,
                  __half* __restrict__ attn) {
    extern __shared__ __half smh[];
    const int h  = blockIdx.y;
    const int by = (gridDim.x - 1) - blockIdx.x;   // heavy tiles first
    const int tid  = threadIdx.x;
    const int wid  = tid >> 5;
    const int lane = tid & 31;
    const int g = lane >> 2;
    const int c = lane & 3;

    __half* Qs = smh + SM_Q;
    __half* Ks = smh + SM_K;
    __half* Vs = smh + SM_V;
    __half* Ps = smh + SM_P + wid * 16 * P_LDH;

    const __half* Qg = qk16 + h * HD;
    const __half* Kg = qk16 + HID + h * HD;
    const __half* Vg = vT + (size_t)h * HD * SEQ;

    const int ktmax = 4 * by + 4;

    for (int i = tid; i < 512; i += 256) {
        int r = i >> 4, ch = (i & 15) * 8;
        cp_async16(&Ks[r * QK_LDH + ch], Kg + (size_t)r * 2 * HID + ch);
    }
    for (int i = tid; i < 512; i += 256) {
        int r = i >> 2, ch = (i & 3) * 8;
        cp_async16(&Vs[r * VT_LDH + ch], Vg + (size_t)r * SEQ + ch);
    }
    cp_commit();

    for (int i = tid; i < 128 * 16; i += 256) {
        int r = i >> 4, ch = (i & 15) * 8;
        cp_async16(&Qs[r * QK_LDH + ch],
                   Qg + (size_t)(by * 128 + r) * 2 * HID + ch);
    }
    cp_commit();

    float o[16][4];
#pragma unroll
    for (int i = 0; i < 16; i++)
#pragma unroll
        for (int j = 0; j < 4; j++) o[i][j] = 0.0f;
    float m0 = -1e30f, m1 = -1e30f, l0 = 0.0f, l1 = 0.0f;

    const int row0 = by * 128 + wid * 16 + g;
    const int row1 = row0 + 8;

    for (int kt = 0; kt < ktmax; kt++) {
        if (kt + 1 < ktmax) {
            const int nb   = (kt + 1) & 1;
            const int key0 = (kt + 1) * KT;
            for (int i = tid; i < 512; i += 256) {
                int r = i >> 4, ch = (i & 15) * 8;
                cp_async16(&Ks[nb * KT * QK_LDH + r * QK_LDH + ch],
                           Kg + (size_t)(key0 + r) * 2 * HID + ch);
            }
            for (int i = tid; i < 512; i += 256) {
                int r = i >> 2, ch = (i & 3) * 8;
                cp_async16(&Vs[nb * HD * VT_LDH + r * VT_LDH + ch],
                           Vg + (size_t)r * SEQ + key0 + ch);
            }
        }
        cp_commit();
        cp_wait<1>();
        __syncthreads();

        const __half* Kbuf = Ks + (kt & 1) * KT * QK_LDH;
        const __half* Vbuf = Vs + (kt & 1) * HD * VT_LDH;
        const int key0 = kt * KT;

        float s[4][4];
#pragma unroll
        for (int i = 0; i < 4; i++)
#pragma unroll
            for (int j = 0; j < 4; j++) s[i][j] = 0.0f;

        const __half* Qr0 = Qs + (wid * 16 + g) * QK_LDH;
        const __half* Qr1 = Qr0 + 8 * QK_LDH;
#pragma unroll
        for (int ks = 0; ks < 8; ks++) {
            uint2 a02 = *(const uint2*)(Qr0 + ks * 16 + 4 * c);
            uint2 a13 = *(const uint2*)(Qr1 + ks * 16 + 4 * c);
#pragma unroll
            for (int nt = 0; nt < 4; nt++) {
                uint2 b = *(const uint2*)(Kbuf + (nt * 8 + g) * QK_LDH + ks * 16 + 4 * c);
                mma_f16(s[nt], a02.x, a13.x, a02.y, a13.y, b.x, b.y);
            }
        }

        if (kt >= 4 * by) {
#pragma unroll
            for (int nt = 0; nt < 4; nt++) {
                int col = key0 + nt * 8 + 2 * c;
                if (col     > row0) s[nt][0] = -1e30f;
                if (col + 1 > row0) s[nt][1] = -1e30f;
                if (col     > row1) s[nt][2] = -1e30f;
                if (col + 1 > row1) s[nt][3] = -1e30f;
            }
        }

        float tm0 = -1e30f, tm1 = -1e30f;
#pragma unroll
        for (int nt = 0; nt < 4; nt++) {
            tm0 = fmaxf(tm0, fmaxf(s[nt][0], s[nt][1]));
            tm1 = fmaxf(tm1, fmaxf(s[nt][2], s[nt][3]));
        }
        tm0 = fmaxf(tm0, __shfl_xor_sync(0xffffffffu, tm0, 1));
        tm0 = fmaxf(tm0, __shfl_xor_sync(0xffffffffu, tm0, 2));
        tm1 = fmaxf(tm1, __shfl_xor_sync(0xffffffffu, tm1, 1));
        tm1 = fmaxf(tm1, __shfl_xor_sync(0xffffffffu, tm1, 2));

        float mn0 = fmaxf(m0, tm0), mn1 = fmaxf(m1, tm1);
        float al0 = __expf(m0 - mn0), al1 = __expf(m1 - mn1);
        m0 = mn0; m1 = mn1;

        float sum0 = 0.0f, sum1 = 0.0f;
#pragma unroll
        for (int nt = 0; nt < 4; nt++) {
            float p0 = __expf(s[nt][0] - mn0);
            float p1 = __expf(s[nt][1] - mn0);
            float p2 = __expf(s[nt][2] - mn1);
            float p3 = __expf(s[nt][3] - mn1);
            sum0 += p0 + p1;
            sum1 += p2 + p3;
            int slot = (nt >> 1) * 16 + 4 * c + ((nt & 1) << 1);
            *(__half2*)(Ps + g * P_LDH + slot)       = __floats2half2_rn(p0, p1);
            *(__half2*)(Ps + (g + 8) * P_LDH + slot) = __floats2half2_rn(p2, p3);
        }
        sum0 += __shfl_xor_sync(0xffffffffu, sum0, 1);
        sum0 += __shfl_xor_sync(0xffffffffu, sum0, 2);
        sum1 += __shfl_xor_sync(0xffffffffu, sum1, 1);
        sum1 += __shfl_xor_sync(0xffffffffu, sum1, 2);
        l0 = l0 * al0 + sum0;
        l1 = l1 * al1 + sum1;

#pragma unroll
        for (int nt = 0; nt < 16; nt++) {
            o[nt][0] *= al0; o[nt][1] *= al0;
            o[nt][2] *= al1; o[nt][3] *= al1;
        }
        __syncwarp();

        const __half* Pr0 = Ps + g * P_LDH;
        const __half* Pr1 = Pr0 + 8 * P_LDH;
#pragma unroll
        for (int ks = 0; ks < 2; ks++) {
            uint2 a02 = *(const uint2*)(Pr0 + ks * 16 + 4 * c);
            uint2 a13 = *(const uint2*)(Pr1 + ks * 16 + 4 * c);
#pragma unroll
            for (int nt = 0; nt < 16; nt++) {
                uint2 b = *(const uint2*)(Vbuf + (nt * 8 + g) * VT_LDH + ks * 16 + 4 * c);
                mma_f16(o[nt], a02.x, a13.x, a02.y, a13.y, b.x, b.y);
            }
        }
        __syncwarp();
        __syncthreads();
    }

    float inv0 = 1.0f / l0;
    float inv1 = 1.0f / l1;
    __half* out0 = attn + (size_t)row0 * HID + h * HD;
    __half* out1 = attn + (size_t)row1 * HID + h * HD;
#pragma unroll
    for (int nt = 0; nt < 16; nt++) {
        *(__half2*)(out0 + nt * 8 + 2 * c) = __floats2half2_rn(o[nt][0] * inv0, o[nt][1] * inv0);
        *(__half2*)(out1 + nt * 8 + 2 * c) = __floats2half2_rn(o[nt][2] * inv1, o[nt][3] * inv1);
    }
}

// ---------------- launch ----------------
extern "C" void kernel_launch(void* const* d_in, const int* in_sizes, int n_in,
                              void* d_out, int out_size) {
    const float* hs   = (const float*)d_in[1];
    const float* Wqkv = (const float*)d_in[2];
    const float* bqkv = (const float*)d_in[3];
    const float* Wo   = (const float*)d_in[4];
    const float* bo   = (const float*)d_in[5];
    float* out = (float*)d_out;

    float* qkv;
    __half *attn16, *hs16, *wq16, *wo16, *qk16, *vT;
    cudaGetSymbolAddress((void**)&qkv,    g_qkv);
    cudaGetSymbolAddress((void**)&attn16, g_attn16);
    cudaGetSymbolAddress((void**)&hs16,   g_hs16);
    cudaGetSymbolAddress((void**)&wq16,   g_wq16);
    cudaGetSymbolAddress((void**)&wo16,   g_wo16);
    cudaGetSymbolAddress((void**)&qk16,   g_qk16);
    cudaGetSymbolAddress((void**)&vT,     g_vT);

    cudaFuncSetAttribute(flash_kernel, cudaFuncAttributeMaxDynamicSharedMemorySize,
                         FA_SMEM_BYTES);
    cudaFuncSetAttribute(gemm_f16_bias, cudaFuncAttributeMaxDynamicSharedMemorySize,
                         GEMM_SMEM_BYTES);

    // 0) fp16 pre-conversion of GEMM operands
    cvt_f16<<<(SEQ * HID / 4 + 255) / 256, 256>>>(hs, hs16, SEQ * HID / 4);
    cvt_f16<<<(int)(((size_t)HID * QKVN / 4 + 255) / 256), 256>>>(Wqkv, wq16,
                                                                  HID * QKVN / 4);
    cvt_f16<<<(HID * HID / 4 + 255) / 256, 256>>>(Wo, wo16, HID * HID / 4);

    // 1) QKV = hs @ Wqkv + bqkv  (fp16 tensor cores, 128x256 tiles)
    gemm_f16_bias<<<dim3(QKVN / BN, SEQ / BM), 512, GEMM_SMEM_BYTES>>>(
        hs16, wq16, bqkv, qkv, HID, QKVN);
    // 2) RoPE -> fp16 q,k (dim-permuted, q scaled); V^T -> fp16 (key-perm)
    rope16_kernel<<<(SEQ * NH * 64 + 255) / 256, 256>>>(qkv, qk16);
    vT_kernel<<<dim3(SEQ / 32, HD / 32, NH), 256>>>(qkv, vT);
    // 3) fused flash attention (fp16 mma) -> g_attn16
    flash_kernel<<<dim3(SEQ / 128, NH), 256, FA_SMEM_BYTES>>>(qk16, vT, attn16);
    // 4) out = attn @ Wo + bo  (fp16 tensor cores, 128x256 tiles)
    gemm_f16_bias<<<dim3(HID / BN, SEQ / BM), 512, GEMM_SMEM_BYTES>>>(
        attn16, wo16, bo, out, HID, HID);
}

// round 10
// speedup vs baseline: 4.9223x; 1.0467x over previous
#include <cuda_runtime.h>
#include <cuda_fp16.h>
#include <cstdint>
#include <mma.h>
#include <math.h>
#include <float.h>

using namespace nvcuda;

#define SEQ   2048
#define HID   4096
#define NH    32
#define HD    128
#define QKVN  12288   // 3*HID

// ---------------- scratch (no cudaMalloc allowed) ----------------
__device__ float  g_qkv[SEQ * QKVN];            // 100 MB (QKV GEMM out, fp32)
__device__ __half g_attn16[SEQ * HID];          // 17 MB  (flash out, O-proj in)
__device__ __half g_hs16[SEQ * HID];            // 17 MB  fp16(hs)
__device__ __half g_wq16[(size_t)HID * QKVN];   // 100 MB fp16(Wqkv) row-major
__device__ __half g_wo16[(size_t)HID * HID];    // 34 MB  fp16(Wo)   row-major
__device__ __half g_qk16[SEQ * 2 * HID];        // 34 MB  roped q,k fp16 (dim-permuted)
__device__ __half g_vT[(size_t)NH * HD * SEQ];  // 17 MB  V^T per head (key-permuted)

// ---------------- cp.async helpers ----------------
__device__ __forceinline__ void cp_async16(void* smem_dst, const void* gsrc) {
    unsigned s = (unsigned)__cvta_generic_to_shared(smem_dst);
    asm volatile("cp.async.cg.shared.global [%0], [%1], 16;\n" :: "r"(s), "l"(gsrc));
}
__device__ __forceinline__ void cp_commit() {
    asm volatile("cp.async.commit_group;\n");
}
template <int N> __device__ __forceinline__ void cp_wait() {
    asm volatile("cp.async.wait_group %0;\n" :: "n"(N));
}

// permutation within a 16-element chunk: pairs (2c,2c+1,2c+8,2c+9) adjacent
__device__ __forceinline__ int p16(int h) {
    return (h < 8) ? ((h >> 1) << 2) + (h & 1)
                   : (((h - 8) >> 1) << 2) + 2 + (h & 1);
}
__device__ __forceinline__ int permd(int d) {
    return (d & ~15) + p16(d & 15);
}

// ---------------- fp16 pre-convert ----------------
__global__ __launch_bounds__(256)
void cvt_f16(const float* __restrict__ in, __half* __restrict__ out, int n4) {
    int i = blockIdx.x * blockDim.x + threadIdx.x;
    if (i < n4) {
        float4 v = ((const float4*)in)[i];
        __half2 h0 = __floats2half2_rn(v.x, v.y);
        __half2 h1 = __floats2half2_rn(v.z, v.w);
        uint2 pk;
        pk.x = *(unsigned*)&h0;
        pk.y = *(unsigned*)&h1;
        ((uint2*)out)[i] = pk;
    }
}

// ================= fp16 tensor-core GEMM + bias =================
// Tile 128x256x64, 512 threads (16 warps, 4x4), warp tile 32x64.
// 3-stage cp.async pipeline, ONE barrier per K-iteration.
#define BM 128
#define BN 256
#define BK 64
#define A_LD 72      // halves (144B rows; 36 banks = 4 mod 32 -> conflict-free)
#define B_LD 264     // halves (528B rows; 132 banks = 4 mod 32 -> conflict-free)
#define STG 3
#define GEMM_SMEM_BYTES (STG * (BM * A_LD + BK * B_LD) * 2)   // 156672

__global__ __launch_bounds__(512)
void gemm_f16_bias(const __half* __restrict__ A, const __half* __restrict__ B,
                   const float* __restrict__ bias, float* __restrict__ C,
                   int K, int N) {
    extern __shared__ __half gsm[];
    __half* Asm = gsm;                       // [STG][BM][A_LD]
    __half* Bsm = gsm + STG * BM * A_LD;     // [STG][BK][B_LD]

    const int tid  = threadIdx.x;
    const int wid  = tid >> 5;
    const int lane = tid & 31;
    const int warp_m = (wid & 3) * 32;       // 0,32,64,96
    const int warp_n = (wid >> 2) * 64;      // 0,64,128,192

    const int bx = blockIdx.x, by = blockIdx.y;

    const __half* Ag = A + (size_t)(by * BM) * K;
    const __half* Bg = B + bx * BN;

    // global-load mapping: A 1024 16B-chunks/stage (2/thread), B 2048 (4/thread)
    const int a_row0 = tid >> 3;             // chunk tid: rows 0..63
    const int a_ck0  = (tid & 7) * 8;
    const int b_ck   = (tid & 31) * 8;
    const int b_row0 = tid >> 5;             // 0..15 (+16,+32,+48)

    auto load_stage = [&](int s, int k0) {
        __half* As_s = Asm + s * BM * A_LD;
        __half* Bs_s = Bsm + s * BK * B_LD;
        cp_async16(&As_s[a_row0 * A_LD + a_ck0],
                   Ag + (size_t)a_row0 * K + k0 + a_ck0);
        cp_async16(&As_s[(a_row0 + 64) * A_LD + a_ck0],
                   Ag + (size_t)(a_row0 + 64) * K + k0 + a_ck0);
#pragma unroll
        for (int p = 0; p < 4; p++) {
            int r = b_row0 + p * 16;
            cp_async16(&Bs_s[r * B_LD + b_ck], Bg + (size_t)(k0 + r) * N + b_ck);
        }
    };

    wmma::fragment<wmma::accumulator, 16, 16, 16, float> acc[2][4];
#pragma unroll
    for (int i = 0; i < 2; i++)
#pragma unroll
        for (int j = 0; j < 4; j++) wmma::fill_fragment(acc[i][j], 0.0f);

    const int T = K / BK;

    load_stage(0, 0);  cp_commit();
    load_stage(1, BK); cp_commit();

    for (int t = 0; t < T; t++) {
        cp_wait<1>();          // stage t data arrived
        __syncthreads();       // all warps done with stage (t-1) == (t+2)%3
        if (t + 2 < T) load_stage((t + 2) % 3, (t + 2) * BK);
        cp_commit();

        const int cur = t % 3;
        const __half* At = Asm + cur * BM * A_LD;
        const __half* Bt = Bsm + cur * BK * B_LD;
#pragma unroll
        for (int kk = 0; kk < BK; kk += 16) {
            wmma::fragment<wmma::matrix_a, 16, 16, 16, __half, wmma::row_major> af[2];
#pragma unroll
            for (int i = 0; i < 2; i++)
                wmma::load_matrix_sync(af[i], At + (warp_m + i * 16) * A_LD + kk, A_LD);
            wmma::fragment<wmma::matrix_b, 16, 16, 16, __half, wmma::row_major> bf[4];
#pragma unroll
            for (int j = 0; j < 4; j++)
                wmma::load_matrix_sync(bf[j], Bt + kk * B_LD + warp_n + j * 16, B_LD);
#pragma unroll
            for (int i = 0; i < 2; i++)
#pragma unroll
                for (int j = 0; j < 4; j++)
                    wmma::mma_sync(acc[i][j], af[i], bf[j], acc[i][j]);
        }
    }
    __syncthreads();

    // epilogue: stage each 16x16 patch through smem (as float), add fp32 bias
    float* epi = (float*)gsm + wid * 256;
#pragma unroll
    for (int i = 0; i < 2; i++) {
#pragma unroll
        for (int j = 0; j < 4; j++) {
            wmma::store_matrix_sync(epi, acc[i][j], 16, wmma::mem_row_major);
            __syncwarp();
            int r = lane >> 1;
            int c = (lane & 1) * 8;
            int grow = by * BM + warp_m + i * 16 + r;
            int gcol = bx * BN + warp_n + j * 16 + c;
            float4 v0 = *(float4*)&epi[r * 16 + c];
            float4 v1 = *(float4*)&epi[r * 16 + c + 4];
            const float* bp = bias + gcol;
            v0.x += bp[0]; v0.y += bp[1]; v0.z += bp[2]; v0.w += bp[3];
            v1.x += bp[4]; v1.y += bp[5]; v1.z += bp[6]; v1.w += bp[7];
            float* cp = C + (size_t)grow * N + gcol;
            *(float4*)cp = v0;
            *(float4*)(cp + 4) = v1;
            __syncwarp();
        }
    }
}

// ---------------- RoPE: fp32 qkv -> fp16 q,k (dim-permuted, q scaled) ----
__global__ __launch_bounds__(256)
void rope16_kernel(const float* __restrict__ qkv, __half* __restrict__ qk16) {
    int idx = blockIdx.x * blockDim.x + threadIdx.x;
    if (idx >= SEQ * NH * 64) return;
    int i = idx & 63;
    int h = (idx >> 6) & 31;
    int s = idx >> 11;
    double invf = exp(-log(10000.0) * (double)(2 * i) / 128.0);
    double f = (double)s * invf;
    float c  = (float)cos(f);
    float sn = (float)sin(f);
    const float scale = 0.08838834764831843f;
    const float* q = qkv + (size_t)s * QKVN + h * HD;
    const float* k = q + HID;
    __half* oq = qk16 + (size_t)s * 2 * HID + h * HD;
    __half* ok = oq + HID;
    float q1 = q[i], q2 = q[i + 64];
    oq[permd(i)]      = __float2half((q1 * c - q2 * sn) * scale);
    oq[permd(i + 64)] = __float2half((q2 * c + q1 * sn) * scale);
    float k1 = k[i], k2 = k[i + 64];
    ok[permd(i)]      = __float2half(k1 * c - k2 * sn);
    ok[permd(i + 64)] = __float2half(k2 * c + k1 * sn);
}

// ---------------- V transpose: fp32 v -> fp16 vT[h][d][seq] (key-perm) ---
__global__ __launch_bounds__(256)
void vT_kernel(const float* __restrict__ qkv, __half* __restrict__ vT) {
    __shared__ float tile[32][33];
    const int h  = blockIdx.z;
    const int s0 = blockIdx.x * 32;
    const int d0 = blockIdx.y * 32;
    int di = threadIdx.x & 31;
    int si = threadIdx.x >> 5;
#pragma unroll
    for (int j = 0; j < 4; j++) {
        int s = si + j * 8;
        tile[s][di] = qkv[(size_t)(s0 + s) * QKVN + 2 * HID + h * HD + d0 + di];
    }
    __syncthreads();
    int sj = threadIdx.x & 31;
    int wj = threadIdx.x >> 5;
    int sp = (sj & 16) + p16(sj & 15);
#pragma unroll
    for (int j = 0; j < 4; j++) {
        int d = wj + j * 8;
        vT[(size_t)(h * HD + d0 + d) * SEQ + s0 + sp] = __float2half(tile[sj][d]);
    }
}

// ================== fused flash attention (fp16 m16n8k16) ======
#define KT 32
#define QK_LDH 144
#define VT_LDH 48
#define P_LDH  48
#define SM_Q 0
#define SM_K (128 * QK_LDH)
#define SM_V (SM_K + 2 * KT * QK_LDH)
#define SM_P (SM_V + 2 * HD * VT_LDH)
#define FA_SMEM_HALVES (SM_P + 8 * 16 * P_LDH)
#define FA_SMEM_BYTES (FA_SMEM_HALVES * 2)   // 92160

__device__ __forceinline__ void mma_f16(float* d, unsigned a0, unsigned a1,
                                        unsigned a2, unsigned a3,
                                        unsigned b0, unsigned b1) {
    asm volatile(
        "mma.sync.aligned.m16n8k16.row.col.f32.f16.f16.f32 "
        "{%0,%1,%2,%3}, {%4,%5,%6,%7}, {%8,%9}, {%0,%1,%2,%3};\n"
        : "+f"(d[0]), "+f"(d[1]), "+f"(d[2]), "+f"(d[3])
        : "r"(a0), "r"(a1), "r"(a2), "r"(a3), "r"(b0), "r"(b1));
}

__global__ __launch_bounds__(256, 2)
void flash_kernel(const __half* __restrict__ qk16, const __half* __restrict__ vT,
                  __half* __restrict__ attn) {
    extern __shared__ __half smh[];
    const int h  = blockIdx.y;
    const int by = (gridDim.x - 1) - blockIdx.x;
    const int tid  = threadIdx.x;
    const int wid  = tid >> 5;
    const int lane = tid & 31;
    const int g = lane >> 2;
    const int c = lane & 3;

    __half* Qs = smh + SM_Q;
    __half* Ks = smh + SM_K;
    __half* Vs = smh + SM_V;
    __half* Ps = smh + SM_P + wid * 16 * P_LDH;

    const __half* Qg = qk16 + h * HD;
    const __half* Kg = qk16 + HID + h * HD;
    const __half* Vg = vT + (size_t)h * HD * SEQ;

    const int ktmax = 4 * by + 4;

    for (int i = tid; i < 512; i += 256) {
        int r = i >> 4, ch = (i & 15) * 8;
        cp_async16(&Ks[r * QK_LDH + ch], Kg + (size_t)r * 2 * HID + ch);
    }
    for (int i = tid; i < 512; i += 256) {
        int r = i >> 2, ch = (i & 3) * 8;
        cp_async16(&Vs[r * VT_LDH + ch], Vg + (size_t)r * SEQ + ch);
    }
    cp_commit();

    for (int i = tid; i < 128 * 16; i += 256) {
        int r = i >> 4, ch = (i & 15) * 8;
        cp_async16(&Qs[r * QK_LDH + ch],
                   Qg + (size_t)(by * 128 + r) * 2 * HID + ch);
    }
    cp_commit();

    float o[16][4];
#pragma unroll
    for (int i = 0; i < 16; i++)
#pragma unroll
        for (int j = 0; j < 4; j++) o[i][j] = 0.0f;
    float m0 = -1e30f, m1 = -1e30f, l0 = 0.0f, l1 = 0.0f;

    const int row0 = by * 128 + wid * 16 + g;
    const int row1 = row0 + 8;

    for (int kt = 0; kt < ktmax; kt++) {
        if (kt + 1 < ktmax) {
            const int nb   = (kt + 1) & 1;
            const int key0 = (kt + 1) * KT;
            for (int i = tid; i < 512; i += 256) {
                int r = i >> 4, ch = (i & 15) * 8;
                cp_async16(&Ks[nb * KT * QK_LDH + r * QK_LDH + ch],
                           Kg + (size_t)(key0 + r) * 2 * HID + ch);
            }
            for (int i = tid; i < 512; i += 256) {
                int r = i >> 2, ch = (i & 3) * 8;
                cp_async16(&Vs[nb * HD * VT_LDH + r * VT_LDH + ch],
                           Vg + (size_t)r * SEQ + key0 + ch);
            }
        }
        cp_commit();
        cp_wait<1>();
        __syncthreads();

        const __half* Kbuf = Ks + (kt & 1) * KT * QK_LDH;
        const __half* Vbuf = Vs + (kt & 1) * HD * VT_LDH;
        const int key0 = kt * KT;

        float s[4][4];
#pragma unroll
        for (int i = 0; i < 4; i++)
#pragma unroll
            for (int j = 0; j < 4; j++) s[i][j] = 0.0f;

        const __half* Qr0 = Qs + (wid * 16 + g) * QK_LDH;
        const __half* Qr1 = Qr0 + 8 * QK_LDH;
#pragma unroll
        for (int ks = 0; ks < 8; ks++) {
            uint2 a02 = *(const uint2*)(Qr0 + ks * 16 + 4 * c);
            uint2 a13 = *(const uint2*)(Qr1 + ks * 16 + 4 * c);
#pragma unroll
            for (int nt = 0; nt < 4; nt++) {
                uint2 b = *(const uint2*)(Kbuf + (nt * 8 + g) * QK_LDH + ks * 16 + 4 * c);
                mma_f16(s[nt], a02.x, a13.x, a02.y, a13.y, b.x, b.y);
            }
        }

        if (kt >= 4 * by) {
#pragma unroll
            for (int nt = 0; nt < 4; nt++) {
                int col = key0 + nt * 8 + 2 * c;
                if (col     > row0) s[nt][0] = -1e30f;
                if (col + 1 > row0) s[nt][1] = -1e30f;
                if (col     > row1) s[nt][2] = -1e30f;
                if (col + 1 > row1) s[nt][3] = -1e30f;
            }
        }

        float tm0 = -1e30f, tm1 = -1e30f;
#pragma unroll
        for (int nt = 0; nt < 4; nt++) {
            tm0 = fmaxf(tm0, fmaxf(s[nt][0], s[nt][1]));
            tm1 = fmaxf(tm1, fmaxf(s[nt][2], s[nt][3]));
        }
        tm0 = fmaxf(tm0, __shfl_xor_sync(0xffffffffu, tm0, 1));
        tm0 = fmaxf(tm0, __shfl_xor_sync(0xffffffffu, tm0, 2));
        tm1 = fmaxf(tm1, __shfl_xor_sync(0xffffffffu, tm1, 1));
        tm1 = fmaxf(tm1, __shfl_xor_sync(0xffffffffu, tm1, 2));

        float mn0 = fmaxf(m0, tm0), mn1 = fmaxf(m1, tm1);
        float al0 = __expf(m0 - mn0), al1 = __expf(m1 - mn1);
        m0 = mn0; m1 = mn1;

        float sum0 = 0.0f, sum1 = 0.0f;
#pragma unroll
        for (int nt = 0; nt < 4; nt++) {
            float p0 = __expf(s[nt][0] - mn0);
            float p1 = __expf(s[nt][1] - mn0);
            float p2 = __expf(s[nt][2] - mn1);
            float p3 = __expf(s[nt][3] - mn1);
            sum0 += p0 + p1;
            sum1 += p2 + p3;
            int slot = (nt >> 1) * 16 + 4 * c + ((nt & 1) << 1);
            *(__half2*)(Ps + g * P_LDH + slot)       = __floats2half2_rn(p0, p1);
            *(__half2*)(Ps + (g + 8) * P_LDH + slot) = __floats2half2_rn(p2, p3);
        }
        sum0 += __shfl_xor_sync(0xffffffffu, sum0, 1);
        sum0 += __shfl_xor_sync(0xffffffffu, sum0, 2);
        sum1 += __shfl_xor_sync(0xffffffffu, sum1, 1);
        sum1 += __shfl_xor_sync(0xffffffffu, sum1, 2);
        l0 = l0 * al0 + sum0;
        l1 = l1 * al1 + sum1;

#pragma unroll
        for (int nt = 0; nt < 16; nt++) {
            o[nt][0] *= al0; o[nt][1] *= al0;
            o[nt][2] *= al1; o[nt][3] *= al1;
        }
        __syncwarp();

        const __half* Pr0 = Ps + g * P_LDH;
        const __half* Pr1 = Pr0 + 8 * P_LDH;
#pragma unroll
        for (int ks = 0; ks < 2; ks++) {
            uint2 a02 = *(const uint2*)(Pr0 + ks * 16 + 4 * c);
            uint2 a13 = *(const uint2*)(Pr1 + ks * 16 + 4 * c);
#pragma unroll
            for (int nt = 0; nt < 16; nt++) {
                uint2 b = *(const uint2*)(Vbuf + (nt * 8 + g) * VT_LDH + ks * 16 + 4 * c);
                mma_f16(o[nt], a02.x, a13.x, a02.y, a13.y, b.x, b.y);
            }
        }
        __syncwarp();
        __syncthreads();
    }

    float inv0 = 1.0f / l0;
    float inv1 = 1.0f / l1;
    __half* out0 = attn + (size_t)row0 * HID + h * HD;
    __half* out1 = attn + (size_t)row1 * HID + h * HD;
#pragma unroll
    for (int nt = 0; nt < 16; nt++) {
        *(__half2*)(out0 + nt * 8 + 2 * c) = __floats2half2_rn(o[nt][0] * inv0, o[nt][1] * inv0);
        *(__half2*)(out1 + nt * 8 + 2 * c) = __floats2half2_rn(o[nt][2] * inv1, o[nt][3] * inv1);
    }
}

// ---------------- launch ----------------
extern "C" void kernel_launch(void* const* d_in, const int* in_sizes, int n_in,
                              void* d_out, int out_size) {
    const float* hs   = (const float*)d_in[1];
    const float* Wqkv = (const float*)d_in[2];
    const float* bqkv = (const float*)d_in[3];
    const float* Wo   = (const float*)d_in[4];
    const float* bo   = (const float*)d_in[5];
    float* out = (float*)d_out;

    float* qkv;
    __half *attn16, *hs16, *wq16, *wo16, *qk16, *vT;
    cudaGetSymbolAddress((void**)&qkv,    g_qkv);
    cudaGetSymbolAddress((void**)&attn16, g_attn16);
    cudaGetSymbolAddress((void**)&hs16,   g_hs16);
    cudaGetSymbolAddress((void**)&wq16,   g_wq16);
    cudaGetSymbolAddress((void**)&wo16,   g_wo16);
    cudaGetSymbolAddress((void**)&qk16,   g_qk16);
    cudaGetSymbolAddress((void**)&vT,     g_vT);

    cudaFuncSetAttribute(flash_kernel, cudaFuncAttributeMaxDynamicSharedMemorySize,
                         FA_SMEM_BYTES);
    cudaFuncSetAttribute(gemm_f16_bias, cudaFuncAttributeMaxDynamicSharedMemorySize,
                         GEMM_SMEM_BYTES);

    // 0) fp16 pre-conversion of GEMM operands
    cvt_f16<<<(SEQ * HID / 4 + 255) / 256, 256>>>(hs, hs16, SEQ * HID / 4);
    cvt_f16<<<(int)(((size_t)HID * QKVN / 4 + 255) / 256), 256>>>(Wqkv, wq16,
                                                                  HID * QKVN / 4);
    cvt_f16<<<(HID * HID / 4 + 255) / 256, 256>>>(Wo, wo16, HID * HID / 4);

    // 1) QKV = hs @ Wqkv + bqkv  (fp16 tensor cores, 128x256x64 tiles)
    gemm_f16_bias<<<dim3(QKVN / BN, SEQ / BM), 512, GEMM_SMEM_BYTES>>>(
        hs16, wq16, bqkv, qkv, HID, QKVN);
    // 2) RoPE -> fp16 q,k (dim-permuted, q scaled); V^T -> fp16 (key-perm)
    rope16_kernel<<<(SEQ * NH * 64 + 255) / 256, 256>>>(qkv, qk16);
    vT_kernel<<<dim3(SEQ / 32, HD / 32, NH), 256>>>(qkv, vT);
    // 3) fused flash attention (fp16 mma) -> g_attn16
    flash_kernel<<<dim3(SEQ / 128, NH), 256, FA_SMEM_BYTES>>>(qk16, vT, attn16);
    // 4) out = attn @ Wo + bo  (fp16 tensor cores, 128x256x64 tiles)
    gemm_f16_bias<<<dim3(HID / BN, SEQ / BM), 512, GEMM_SMEM_BYTES>>>(
        attn16, wo16, bo, out, HID, HID);
}

// round 11
// speedup vs baseline: 5.1946x; 1.0553x over previous
#include <cuda_runtime.h>
#include <cuda_fp16.h>
#include <cstdint>
#include <mma.h>
#include <math.h>
#include <float.h>

using namespace nvcuda;

#define SEQ   2048
#define HID   4096
#define NH    32
#define HD    128
#define QKVN  12288   // 3*HID

// ---------------- scratch (no cudaMalloc allowed) ----------------
__device__ float  g_qkv[SEQ * QKVN];            // 100 MB (QKV GEMM out, fp32)
__device__ __half g_attn16[SEQ * HID];          // 17 MB  (flash out, O-proj in)
__device__ __half g_hs16[SEQ * HID];            // 17 MB  fp16(hs)
__device__ __half g_wq16[(size_t)HID * QKVN];   // 100 MB fp16(Wqkv) row-major
__device__ __half g_wo16[(size_t)HID * HID];    // 34 MB  fp16(Wo)   row-major
__device__ __half g_qk16[SEQ * 2 * HID];        // 34 MB  roped q,k fp16 (dim-permuted)
__device__ __half g_vT[(size_t)NH * HD * SEQ];  // 17 MB  V^T per head (key-permuted)

// ---------------- cp.async helpers ----------------
__device__ __forceinline__ void cp_async16(void* smem_dst, const void* gsrc) {
    unsigned s = (unsigned)__cvta_generic_to_shared(smem_dst);
    asm volatile("cp.async.cg.shared.global [%0], [%1], 16;\n" :: "r"(s), "l"(gsrc));
}
__device__ __forceinline__ void cp_commit() {
    asm volatile("cp.async.commit_group;\n");
}
template <int N> __device__ __forceinline__ void cp_wait() {
    asm volatile("cp.async.wait_group %0;\n" :: "n"(N));
}

// permutation within a 16-element chunk: pairs (2c,2c+1,2c+8,2c+9) adjacent
__device__ __forceinline__ int p16(int h) {
    return (h < 8) ? ((h >> 1) << 2) + (h & 1)
                   : (((h - 8) >> 1) << 2) + 2 + (h & 1);
}
__device__ __forceinline__ int permd(int d) {
    return (d & ~15) + p16(d & 15);
}

// ---------------- fp16 pre-convert ----------------
__global__ __launch_bounds__(256)
void cvt_f16(const float* __restrict__ in, __half* __restrict__ out, int n4) {
    int i = blockIdx.x * blockDim.x + threadIdx.x;
    if (i < n4) {
        float4 v = ((const float4*)in)[i];
        __half2 h0 = __floats2half2_rn(v.x, v.y);
        __half2 h1 = __floats2half2_rn(v.z, v.w);
        uint2 pk;
        pk.x = *(unsigned*)&h0;
        pk.y = *(unsigned*)&h1;
        ((uint2*)out)[i] = pk;
    }
}

// ================= fp16 tensor-core GEMM + bias =================
// Tile 128x128x64, 256 threads (8 warps, 4x2), warp tile 32x64.
// 3-stage cp.async pipeline, one barrier per K-iter, 2 CTAs/SM.
#define BM 128
#define BN 128
#define BK 64
#define A_LD 72      // halves (144B rows)
#define B_LD 136     // halves (272B rows)
#define STG 3
#define GEMM_SMEM_BYTES (STG * (BM * A_LD + BK * B_LD) * 2)   // 107520

__global__ __launch_bounds__(256, 2)
void gemm_f16_bias(const __half* __restrict__ A, const __half* __restrict__ B,
                   const float* __restrict__ bias, float* __restrict__ C,
                   int K, int N) {
    extern __shared__ __half gsm[];
    __half* Asm = gsm;                       // [STG][BM][A_LD]
    __half* Bsm = gsm + STG * BM * A_LD;     // [STG][BK][B_LD]

    const int tid  = threadIdx.x;
    const int wid  = tid >> 5;
    const int lane = tid & 31;
    const int warp_m = (wid & 3) * 32;       // 0,32,64,96
    const int warp_n = (wid >> 2) * 64;      // 0,64

    const int bx = blockIdx.x, by = blockIdx.y;

    const __half* Ag = A + (size_t)(by * BM) * K;
    const __half* Bg = B + bx * BN;

    // per stage: A 1024 16B-chunks (4/thread), B 1024 (4/thread)
    auto load_stage = [&](int s, int k0) {
        __half* As_s = Asm + s * BM * A_LD;
        __half* Bs_s = Bsm + s * BK * B_LD;
#pragma unroll
        for (int p = 0; p < 4; p++) {
            int idx = tid + p * 256;
            int ar = idx >> 3, ack = (idx & 7) * 8;
            cp_async16(&As_s[ar * A_LD + ack], Ag + (size_t)ar * K + k0 + ack);
        }
#pragma unroll
        for (int p = 0; p < 4; p++) {
            int idx = tid + p * 256;
            int br = idx >> 4, bck = (idx & 15) * 8;
            cp_async16(&Bs_s[br * B_LD + bck], Bg + (size_t)(k0 + br) * N + bck);
        }
    };

    wmma::fragment<wmma::accumulator, 16, 16, 16, float> acc[2][4];
#pragma unroll
    for (int i = 0; i < 2; i++)
#pragma unroll
        for (int j = 0; j < 4; j++) wmma::fill_fragment(acc[i][j], 0.0f);

    const int T = K / BK;

    load_stage(0, 0);  cp_commit();
    load_stage(1, BK); cp_commit();

    for (int t = 0; t < T; t++) {
        cp_wait<1>();          // stage t data arrived
        __syncthreads();       // all warps done with stage (t+2)%3's previous use
        if (t + 2 < T) load_stage((t + 2) % 3, (t + 2) * BK);
        cp_commit();

        const int cur = t % 3;
        const __half* At = Asm + cur * BM * A_LD;
        const __half* Bt = Bsm + cur * BK * B_LD;
#pragma unroll
        for (int kk = 0; kk < BK; kk += 16) {
            wmma::fragment<wmma::matrix_a, 16, 16, 16, __half, wmma::row_major> af[2];
#pragma unroll
            for (int i = 0; i < 2; i++)
                wmma::load_matrix_sync(af[i], At + (warp_m + i * 16) * A_LD + kk, A_LD);
            wmma::fragment<wmma::matrix_b, 16, 16, 16, __half, wmma::row_major> bf[4];
#pragma unroll
            for (int j = 0; j < 4; j++)
                wmma::load_matrix_sync(bf[j], Bt + kk * B_LD + warp_n + j * 16, B_LD);
#pragma unroll
            for (int i = 0; i < 2; i++)
#pragma unroll
                for (int j = 0; j < 4; j++)
                    wmma::mma_sync(acc[i][j], af[i], bf[j], acc[i][j]);
        }
    }
    __syncthreads();

    // epilogue: stage each 16x16 patch through smem (as float), add fp32 bias
    float* epi = (float*)gsm + wid * 256;
#pragma unroll
    for (int i = 0; i < 2; i++) {
#pragma unroll
        for (int j = 0; j < 4; j++) {
            wmma::store_matrix_sync(epi, acc[i][j], 16, wmma::mem_row_major);
            __syncwarp();
            int r = lane >> 1;
            int c = (lane & 1) * 8;
            int grow = by * BM + warp_m + i * 16 + r;
            int gcol = bx * BN + warp_n + j * 16 + c;
            float4 v0 = *(float4*)&epi[r * 16 + c];
            float4 v1 = *(float4*)&epi[r * 16 + c + 4];
            const float* bp = bias + gcol;
            v0.x += bp[0]; v0.y += bp[1]; v0.z += bp[2]; v0.w += bp[3];
            v1.x += bp[4]; v1.y += bp[5]; v1.z += bp[6]; v1.w += bp[7];
            float* cp = C + (size_t)grow * N + gcol;
            *(float4*)cp = v0;
            *(float4*)(cp + 4) = v1;
            __syncwarp();
        }
    }
}

// ---------------- RoPE: fp32 qkv -> fp16 q,k (dim-permuted, q scaled) ----
__global__ __launch_bounds__(256)
void rope16_kernel(const float* __restrict__ qkv, __half* __restrict__ qk16) {
    int idx = blockIdx.x * blockDim.x + threadIdx.x;
    if (idx >= SEQ * NH * 64) return;
    int i = idx & 63;
    int h = (idx >> 6) & 31;
    int s = idx >> 11;
    double invf = exp(-log(10000.0) * (double)(2 * i) / 128.0);
    double f = (double)s * invf;
    float c  = (float)cos(f);
    float sn = (float)sin(f);
    const float scale = 0.08838834764831843f;
    const float* q = qkv + (size_t)s * QKVN + h * HD;
    const float* k = q + HID;
    __half* oq = qk16 + (size_t)s * 2 * HID + h * HD;
    __half* ok = oq + HID;
    float q1 = q[i], q2 = q[i + 64];
    oq[permd(i)]      = __float2half((q1 * c - q2 * sn) * scale);
    oq[permd(i + 64)] = __float2half((q2 * c + q1 * sn) * scale);
    float k1 = k[i], k2 = k[i + 64];
    ok[permd(i)]      = __float2half(k1 * c - k2 * sn);
    ok[permd(i + 64)] = __float2half(k2 * c + k1 * sn);
}

// ---------------- V transpose: fp32 v -> fp16 vT[h][d][seq] (key-perm) ---
__global__ __launch_bounds__(256)
void vT_kernel(const float* __restrict__ qkv, __half* __restrict__ vT) {
    __shared__ float tile[32][33];
    const int h  = blockIdx.z;
    const int s0 = blockIdx.x * 32;
    const int d0 = blockIdx.y * 32;
    int di = threadIdx.x & 31;
    int si = threadIdx.x >> 5;
#pragma unroll
    for (int j = 0; j < 4; j++) {
        int s = si + j * 8;
        tile[s][di] = qkv[(size_t)(s0 + s) * QKVN + 2 * HID + h * HD + d0 + di];
    }
    __syncthreads();
    int sj = threadIdx.x & 31;
    int wj = threadIdx.x >> 5;
    int sp = (sj & 16) + p16(sj & 15);
#pragma unroll
    for (int j = 0; j < 4; j++) {
        int d = wj + j * 8;
        vT[(size_t)(h * HD + d0 + d) * SEQ + s0 + sp] = __float2half(tile[sj][d]);
    }
}

// ================== fused flash attention (fp16 m16n8k16) ======
#define KT 32
#define QK_LDH 144
#define VT_LDH 48
#define P_LDH  48
#define SM_Q 0
#define SM_K (128 * QK_LDH)
#define SM_V (SM_K + 2 * KT * QK_LDH)
#define SM_P (SM_V + 2 * HD * VT_LDH)
#define FA_SMEM_HALVES (SM_P + 8 * 16 * P_LDH)
#define FA_SMEM_BYTES (FA_SMEM_HALVES * 2)   // 92160

__device__ __forceinline__ void mma_f16(float* d, unsigned a0, unsigned a1,
                                        unsigned a2, unsigned a3,
                                        unsigned b0, unsigned b1) {
    asm volatile(
        "mma.sync.aligned.m16n8k16.row.col.f32.f16.f16.f32 "
        "{%0,%1,%2,%3}, {%4,%5,%6,%7}, {%8,%9}, {%0,%1,%2,%3};\n"
        : "+f"(d[0]), "+f"(d[1]), "+f"(d[2]), "+f"(d[3])
        : "r"(a0), "r"(a1), "r"(a2), "r"(a3), "r"(b0), "r"(b1));
}

__global__ __launch_bounds__(256, 2)
void flash_kernel(const __half* __restrict__ qk16, const __half* __restrict__ vT,
                  __half* __restrict__ attn) {
    extern __shared__ __half smh[];
    const int h  = blockIdx.y;
    const int by = (gridDim.x - 1) - blockIdx.x;   // heavy tiles first
    const int tid  = threadIdx.x;
    const int wid  = tid >> 5;
    const int lane = tid & 31;
    const int g = lane >> 2;
    const int c = lane & 3;

    __half* Qs = smh + SM_Q;
    __half* Ks = smh + SM_K;
    __half* Vs = smh + SM_V;
    __half* Ps = smh + SM_P + wid * 16 * P_LDH;

    const __half* Qg = qk16 + h * HD;
    const __half* Kg = qk16 + HID + h * HD;
    const __half* Vg = vT + (size_t)h * HD * SEQ;

    const int ktmax = 4 * by + 4;

    // prologue: issue K/V tile 0 and Q tile
    for (int i = tid; i < 512; i += 256) {
        int r = i >> 4, ch = (i & 15) * 8;
        cp_async16(&Ks[r * QK_LDH + ch], Kg + (size_t)r * 2 * HID + ch);
    }
    for (int i = tid; i < 512; i += 256) {
        int r = i >> 2, ch = (i & 3) * 8;
        cp_async16(&Vs[r * VT_LDH + ch], Vg + (size_t)r * SEQ + ch);
    }
    for (int i = tid; i < 128 * 16; i += 256) {
        int r = i >> 4, ch = (i & 15) * 8;
        cp_async16(&Qs[r * QK_LDH + ch],
                   Qg + (size_t)(by * 128 + r) * 2 * HID + ch);
    }
    cp_commit();

    float o[16][4];
#pragma unroll
    for (int i = 0; i < 16; i++)
#pragma unroll
        for (int j = 0; j < 4; j++) o[i][j] = 0.0f;
    float m0 = -1e30f, m1 = -1e30f, l0 = 0.0f, l1 = 0.0f;

    const int row0 = by * 128 + wid * 16 + g;
    const int row1 = row0 + 8;

    for (int kt = 0; kt < ktmax; kt++) {
        cp_wait<0>();          // tile kt (and Q on kt==0) arrived
        __syncthreads();       // visibility + all warps done reading buf (kt+1)&1
        if (kt + 1 < ktmax) {  // prefetch next tile into the other buffer
            const int nb   = (kt + 1) & 1;
            const int key0 = (kt + 1) * KT;
            for (int i = tid; i < 512; i += 256) {
                int r = i >> 4, ch = (i & 15) * 8;
                cp_async16(&Ks[nb * KT * QK_LDH + r * QK_LDH + ch],
                           Kg + (size_t)(key0 + r) * 2 * HID + ch);
            }
            for (int i = tid; i < 512; i += 256) {
                int r = i >> 2, ch = (i & 3) * 8;
                cp_async16(&Vs[nb * HD * VT_LDH + r * VT_LDH + ch],
                           Vg + (size_t)r * SEQ + key0 + ch);
            }
        }
        cp_commit();

        const __half* Kbuf = Ks + (kt & 1) * KT * QK_LDH;
        const __half* Vbuf = Vs + (kt & 1) * HD * VT_LDH;
        const int key0 = kt * KT;

        float s[4][4];
#pragma unroll
        for (int i = 0; i < 4; i++)
#pragma unroll
            for (int j = 0; j < 4; j++) s[i][j] = 0.0f;

        const __half* Qr0 = Qs + (wid * 16 + g) * QK_LDH;
        const __half* Qr1 = Qr0 + 8 * QK_LDH;
#pragma unroll
        for (int ks = 0; ks < 8; ks++) {
            uint2 a02 = *(const uint2*)(Qr0 + ks * 16 + 4 * c);
            uint2 a13 = *(const uint2*)(Qr1 + ks * 16 + 4 * c);
#pragma unroll
            for (int nt = 0; nt < 4; nt++) {
                uint2 b = *(const uint2*)(Kbuf + (nt * 8 + g) * QK_LDH + ks * 16 + 4 * c);
                mma_f16(s[nt], a02.x, a13.x, a02.y, a13.y, b.x, b.y);
            }
        }

        if (kt >= 4 * by) {
#pragma unroll
            for (int nt = 0; nt < 4; nt++) {
                int col = key0 + nt * 8 + 2 * c;
                if (col     > row0) s[nt][0] = -1e30f;
                if (col + 1 > row0) s[nt][1] = -1e30f;
                if (col     > row1) s[nt][2] = -1e30f;
                if (col + 1 > row1) s[nt][3] = -1e30f;
            }
        }

        float tm0 = -1e30f, tm1 = -1e30f;
#pragma unroll
        for (int nt = 0; nt < 4; nt++) {
            tm0 = fmaxf(tm0, fmaxf(s[nt][0], s[nt][1]));
            tm1 = fmaxf(tm1, fmaxf(s[nt][2], s[nt][3]));
        }
        tm0 = fmaxf(tm0, __shfl_xor_sync(0xffffffffu, tm0, 1));
        tm0 = fmaxf(tm0, __shfl_xor_sync(0xffffffffu, tm0, 2));
        tm1 = fmaxf(tm1, __shfl_xor_sync(0xffffffffu, tm1, 1));
        tm1 = fmaxf(tm1, __shfl_xor_sync(0xffffffffu, tm1, 2));

        float mn0 = fmaxf(m0, tm0), mn1 = fmaxf(m1, tm1);
        float al0 = __expf(m0 - mn0), al1 = __expf(m1 - mn1);
        m0 = mn0; m1 = mn1;

        float sum0 = 0.0f, sum1 = 0.0f;
#pragma unroll
        for (int nt = 0; nt < 4; nt++) {
            float p0 = __expf(s[nt][0] - mn0);
            float p1 = __expf(s[nt][1] - mn0);
            float p2 = __expf(s[nt][2] - mn1);
            float p3 = __expf(s[nt][3] - mn1);
            sum0 += p0 + p1;
            sum1 += p2 + p3;
            int slot = (nt >> 1) * 16 + 4 * c + ((nt & 1) << 1);
            *(__half2*)(Ps + g * P_LDH + slot)       = __floats2half2_rn(p0, p1);
            *(__half2*)(Ps + (g + 8) * P_LDH + slot) = __floats2half2_rn(p2, p3);
        }
        sum0 += __shfl_xor_sync(0xffffffffu, sum0, 1);
        sum0 += __shfl_xor_sync(0xffffffffu, sum0, 2);
        sum1 += __shfl_xor_sync(0xffffffffu, sum1, 1);
        sum1 += __shfl_xor_sync(0xffffffffu, sum1, 2);
        l0 = l0 * al0 + sum0;
        l1 = l1 * al1 + sum1;

        // rescale O only if any lane's running max actually changed
        if (__ballot_sync(0xffffffffu, (al0 != 1.0f) || (al1 != 1.0f))) {
#pragma unroll
            for (int nt = 0; nt < 16; nt++) {
                o[nt][0] *= al0; o[nt][1] *= al0;
                o[nt][2] *= al1; o[nt][3] *= al1;
            }
        }
        __syncwarp();

        const __half* Pr0 = Ps + g * P_LDH;
        const __half* Pr1 = Pr0 + 8 * P_LDH;
#pragma unroll
        for (int ks = 0; ks < 2; ks++) {
            uint2 a02 = *(const uint2*)(Pr0 + ks * 16 + 4 * c);
            uint2 a13 = *(const uint2*)(Pr1 + ks * 16 + 4 * c);
#pragma unroll
            for (int nt = 0; nt < 16; nt++) {
                uint2 b = *(const uint2*)(Vbuf + (nt * 8 + g) * VT_LDH + ks * 16 + 4 * c);
                mma_f16(o[nt], a02.x, a13.x, a02.y, a13.y, b.x, b.y);
            }
        }
        __syncwarp();
    }

    float inv0 = 1.0f / l0;
    float inv1 = 1.0f / l1;
    __half* out0 = attn + (size_t)row0 * HID + h * HD;
    __half* out1 = attn + (size_t)row1 * HID + h * HD;
#pragma unroll
    for (int nt = 0; nt < 16; nt++) {
        *(__half2*)(out0 + nt * 8 + 2 * c) = __floats2half2_rn(o[nt][0] * inv0, o[nt][1] * inv0);
        *(__half2*)(out1 + nt * 8 + 2 * c) = __floats2half2_rn(o[nt][2] * inv1, o[nt][3] * inv1);
    }
}

// ---------------- launch ----------------
extern "C" void kernel_launch(void* const* d_in, const int* in_sizes, int n_in,
                              void* d_out, int out_size) {
    const float* hs   = (const float*)d_in[1];
    const float* Wqkv = (const float*)d_in[2];
    const float* bqkv = (const float*)d_in[3];
    const float* Wo   = (const float*)d_in[4];
    const float* bo   = (const float*)d_in[5];
    float* out = (float*)d_out;

    float* qkv;
    __half *attn16, *hs16, *wq16, *wo16, *qk16, *vT;
    cudaGetSymbolAddress((void**)&qkv,    g_qkv);
    cudaGetSymbolAddress((void**)&attn16, g_attn16);
    cudaGetSymbolAddress((void**)&hs16,   g_hs16);
    cudaGetSymbolAddress((void**)&wq16,   g_wq16);
    cudaGetSymbolAddress((void**)&wo16,   g_wo16);
    cudaGetSymbolAddress((void**)&qk16,   g_qk16);
    cudaGetSymbolAddress((void**)&vT,     g_vT);

    cudaFuncSetAttribute(flash_kernel, cudaFuncAttributeMaxDynamicSharedMemorySize,
                         FA_SMEM_BYTES);
    cudaFuncSetAttribute(gemm_f16_bias, cudaFuncAttributeMaxDynamicSharedMemorySize,
                         GEMM_SMEM_BYTES);

    // 0) fp16 pre-conversion of GEMM operands
    cvt_f16<<<(SEQ * HID / 4 + 255) / 256, 256>>>(hs, hs16, SEQ * HID / 4);
    cvt_f16<<<(int)(((size_t)HID * QKVN / 4 + 255) / 256), 256>>>(Wqkv, wq16,
                                                                  HID * QKVN / 4);
    cvt_f16<<<(HID * HID / 4 + 255) / 256, 256>>>(Wo, wo16, HID * HID / 4);

    // 1) QKV = hs @ Wqkv + bqkv  (fp16 tensor cores, 128x128x64, 2 CTAs/SM)
    gemm_f16_bias<<<dim3(QKVN / BN, SEQ / BM), 256, GEMM_SMEM_BYTES>>>(
        hs16, wq16, bqkv, qkv, HID, QKVN);
    // 2) RoPE -> fp16 q,k (dim-permuted, q scaled); V^T -> fp16 (key-perm)
    rope16_kernel<<<(SEQ * NH * 64 + 255) / 256, 256>>>(qkv, qk16);
    vT_kernel<<<dim3(SEQ / 32, HD / 32, NH), 256>>>(qkv, vT);
    // 3) fused flash attention (fp16 mma) -> g_attn16
    flash_kernel<<<dim3(SEQ / 128, NH), 256, FA_SMEM_BYTES>>>(qk16, vT, attn16);
    // 4) out = attn @ Wo + bo  (fp16 tensor cores, 128x128x64, 2 CTAs/SM)
    gemm_f16_bias<<<dim3(HID / BN, SEQ / BM), 256, GEMM_SMEM_BYTES>>>(
        attn16, wo16, bo, out, HID, HID);
}

// round 12
// speedup vs baseline: 8.1694x; 1.5727x over previous
#include <cuda_runtime.h>
#include <cuda_fp16.h>
#include <cstdint>
#include <mma.h>
#include <math.h>
#include <float.h>

using namespace nvcuda;

#define SEQ   2048
#define HID   4096
#define NH    32
#define HD    128
#define QKVN  12288   // 3*HID

// ---------------- scratch (no cudaMalloc allowed) ----------------
__device__ float  g_qkv[SEQ * QKVN];            // 100 MB (QKV GEMM out, fp32)
__device__ __half g_attn16[SEQ * HID];          // 17 MB  (flash out, O-proj in)
__device__ __half g_hs16[SEQ * HID];            // 17 MB  fp16(hs)
__device__ __half g_wq16[(size_t)HID * QKVN];   // 100 MB fp16(Wqkv) row-major
__device__ __half g_wo16[(size_t)HID * HID];    // 34 MB  fp16(Wo)   row-major
__device__ __half g_qk16[SEQ * 2 * HID];        // 34 MB  roped q,k fp16 (dim-permuted)
__device__ __half g_vT[(size_t)NH * HD * SEQ];  // 17 MB  V^T per head (key-permuted)

// ---------------- cp.async helpers ----------------
__device__ __forceinline__ void cp_async16(void* smem_dst, const void* gsrc) {
    unsigned s = (unsigned)__cvta_generic_to_shared(smem_dst);
    asm volatile("cp.async.cg.shared.global [%0], [%1], 16;\n" :: "r"(s), "l"(gsrc));
}
__device__ __forceinline__ void cp_commit() {
    asm volatile("cp.async.commit_group;\n");
}
template <int N> __device__ __forceinline__ void cp_wait() {
    asm volatile("cp.async.wait_group %0;\n" :: "n"(N));
}

// permutation within a 16-element chunk: pairs (2c,2c+1,2c+8,2c+9) adjacent
__device__ __forceinline__ int p16(int h) {
    return (h < 8) ? ((h >> 1) << 2) + (h & 1)
                   : (((h - 8) >> 1) << 2) + 2 + (h & 1);
}
__device__ __forceinline__ int permd(int d) {
    return (d & ~15) + p16(d & 15);
}

// ---------------- fp16 pre-convert ----------------
__global__ __launch_bounds__(256)
void cvt_f16(const float* __restrict__ in, __half* __restrict__ out, int n4) {
    int i = blockIdx.x * blockDim.x + threadIdx.x;
    if (i < n4) {
        float4 v = ((const float4*)in)[i];
        __half2 h0 = __floats2half2_rn(v.x, v.y);
        __half2 h1 = __floats2half2_rn(v.z, v.w);
        uint2 pk;
        pk.x = *(unsigned*)&h0;
        pk.y = *(unsigned*)&h1;
        ((uint2*)out)[i] = pk;
    }
}

// ================= fp16 tensor-core GEMM + bias =================
// Tile 128x128x64, 256 threads (8 warps, 4x2), warp tile 32x64.
// 3-stage cp.async pipeline, one barrier per K-iter, 2 CTAs/SM.
#define BM 128
#define BN 128
#define BK 64
#define A_LD 72      // halves (144B rows)
#define B_LD 136     // halves (272B rows)
#define STG 3
#define GEMM_SMEM_BYTES (STG * (BM * A_LD + BK * B_LD) * 2)   // 107520

__global__ __launch_bounds__(256, 2)
void gemm_f16_bias(const __half* __restrict__ A, const __half* __restrict__ B,
                   const float* __restrict__ bias, float* __restrict__ C,
                   int K, int N) {
    extern __shared__ __half gsm[];
    __half* Asm = gsm;                       // [STG][BM][A_LD]
    __half* Bsm = gsm + STG * BM * A_LD;     // [STG][BK][B_LD]

    const int tid  = threadIdx.x;
    const int wid  = tid >> 5;
    const int lane = tid & 31;
    const int warp_m = (wid & 3) * 32;
    const int warp_n = (wid >> 2) * 64;

    const int bx = blockIdx.x, by = blockIdx.y;

    const __half* Ag = A + (size_t)(by * BM) * K;
    const __half* Bg = B + bx * BN;

    auto load_stage = [&](int s, int k0) {
        __half* As_s = Asm + s * BM * A_LD;
        __half* Bs_s = Bsm + s * BK * B_LD;
#pragma unroll
        for (int p = 0; p < 4; p++) {
            int idx = tid + p * 256;
            int ar = idx >> 3, ack = (idx & 7) * 8;
            cp_async16(&As_s[ar * A_LD + ack], Ag + (size_t)ar * K + k0 + ack);
        }
#pragma unroll
        for (int p = 0; p < 4; p++) {
            int idx = tid + p * 256;
            int br = idx >> 4, bck = (idx & 15) * 8;
            cp_async16(&Bs_s[br * B_LD + bck], Bg + (size_t)(k0 + br) * N + bck);
        }
    };

    wmma::fragment<wmma::accumulator, 16, 16, 16, float> acc[2][4];
#pragma unroll
    for (int i = 0; i < 2; i++)
#pragma unroll
        for (int j = 0; j < 4; j++) wmma::fill_fragment(acc[i][j], 0.0f);

    const int T = K / BK;

    load_stage(0, 0);  cp_commit();
    load_stage(1, BK); cp_commit();

    for (int t = 0; t < T; t++) {
        cp_wait<1>();
        __syncthreads();
        if (t + 2 < T) load_stage((t + 2) % 3, (t + 2) * BK);
        cp_commit();

        const int cur = t % 3;
        const __half* At = Asm + cur * BM * A_LD;
        const __half* Bt = Bsm + cur * BK * B_LD;
#pragma unroll
        for (int kk = 0; kk < BK; kk += 16) {
            wmma::fragment<wmma::matrix_a, 16, 16, 16, __half, wmma::row_major> af[2];
#pragma unroll
            for (int i = 0; i < 2; i++)
                wmma::load_matrix_sync(af[i], At + (warp_m + i * 16) * A_LD + kk, A_LD);
            wmma::fragment<wmma::matrix_b, 16, 16, 16, __half, wmma::row_major> bf[4];
#pragma unroll
            for (int j = 0; j < 4; j++)
                wmma::load_matrix_sync(bf[j], Bt + kk * B_LD + warp_n + j * 16, B_LD);
#pragma unroll
            for (int i = 0; i < 2; i++)
#pragma unroll
                for (int j = 0; j < 4; j++)
                    wmma::mma_sync(acc[i][j], af[i], bf[j], acc[i][j]);
        }
    }
    __syncthreads();

    float* epi = (float*)gsm + wid * 256;
#pragma unroll
    for (int i = 0; i < 2; i++) {
#pragma unroll
        for (int j = 0; j < 4; j++) {
            wmma::store_matrix_sync(epi, acc[i][j], 16, wmma::mem_row_major);
            __syncwarp();
            int r = lane >> 1;
            int c = (lane & 1) * 8;
            int grow = by * BM + warp_m + i * 16 + r;
            int gcol = bx * BN + warp_n + j * 16 + c;
            float4 v0 = *(float4*)&epi[r * 16 + c];
            float4 v1 = *(float4*)&epi[r * 16 + c + 4];
            const float* bp = bias + gcol;
            v0.x += bp[0]; v0.y += bp[1]; v0.z += bp[2]; v0.w += bp[3];
            v1.x += bp[4]; v1.y += bp[5]; v1.z += bp[6]; v1.w += bp[7];
            float* cp = C + (size_t)grow * N + gcol;
            *(float4*)cp = v0;
            *(float4*)(cp + 4) = v1;
            __syncwarp();
        }
    }
}

// ---------------- RoPE (fp32 math): fp32 qkv -> fp16 q,k --------------
__global__ __launch_bounds__(256)
void rope16_kernel(const float* __restrict__ qkv, __half* __restrict__ qk16) {
    int idx = blockIdx.x * blockDim.x + threadIdx.x;
    if (idx >= SEQ * NH * 64) return;
    int i = idx & 63;
    int h = (idx >> 6) & 31;
    int s = idx >> 11;
    // inv_freq = 10000^(-i/64)  (fp32, matches reference's fp32 pipeline)
    float invf = expf(-0.14391156831212787f * (float)i);
    float f = (float)s * invf;
    float c  = cosf(f);
    float sn = sinf(f);
    const float scale = 0.08838834764831843f;
    const float* q = qkv + (size_t)s * QKVN + h * HD;
    const float* k = q + HID;
    __half* oq = qk16 + (size_t)s * 2 * HID + h * HD;
    __half* ok = oq + HID;
    float q1 = q[i], q2 = q[i + 64];
    oq[permd(i)]      = __float2half((q1 * c - q2 * sn) * scale);
    oq[permd(i + 64)] = __float2half((q2 * c + q1 * sn) * scale);
    float k1 = k[i], k2 = k[i + 64];
    ok[permd(i)]      = __float2half(k1 * c - k2 * sn);
    ok[permd(i + 64)] = __float2half(k2 * c + k1 * sn);
}

// ---------------- V transpose: fp32 v -> fp16 vT[h][d][seq] (key-perm) ---
__global__ __launch_bounds__(256)
void vT_kernel(const float* __restrict__ qkv, __half* __restrict__ vT) {
    __shared__ float tile[32][33];
    const int h  = blockIdx.z;
    const int s0 = blockIdx.x * 32;
    const int d0 = blockIdx.y * 32;
    int di = threadIdx.x & 31;
    int si = threadIdx.x >> 5;
#pragma unroll
    for (int j = 0; j < 4; j++) {
        int s = si + j * 8;
        tile[s][di] = qkv[(size_t)(s0 + s) * QKVN + 2 * HID + h * HD + d0 + di];
    }
    __syncthreads();
    int sj = threadIdx.x & 31;
    int wj = threadIdx.x >> 5;
    int sp = (sj & 16) + p16(sj & 15);
#pragma unroll
    for (int j = 0; j < 4; j++) {
        int d = wj + j * 8;
        vT[(size_t)(h * HD + d0 + d) * SEQ + s0 + sp] = __float2half(tile[sj][d]);
    }
}

// ================== fused flash attention (fp16 m16n8k16, register P) ====
#define KT 32
#define QK_LDH 144
#define VT_LDH 48
#define SM_Q 0
#define SM_K (128 * QK_LDH)
#define SM_V (SM_K + 2 * KT * QK_LDH)
#define FA_SMEM_HALVES (SM_V + 2 * HD * VT_LDH)
#define FA_SMEM_BYTES (FA_SMEM_HALVES * 2)   // 79872

__device__ __forceinline__ void mma_f16(float* d, unsigned a0, unsigned a1,
                                        unsigned a2, unsigned a3,
                                        unsigned b0, unsigned b1) {
    asm volatile(
        "mma.sync.aligned.m16n8k16.row.col.f32.f16.f16.f32 "
        "{%0,%1,%2,%3}, {%4,%5,%6,%7}, {%8,%9}, {%0,%1,%2,%3};\n"
        : "+f"(d[0]), "+f"(d[1]), "+f"(d[2]), "+f"(d[3])
        : "r"(a0), "r"(a1), "r"(a2), "r"(a3), "r"(b0), "r"(b1));
}
__device__ __forceinline__ unsigned packh2(float a, float b) {
    __half2 h = __floats2half2_rn(a, b);
    return *(unsigned*)&h;
}

__global__ __launch_bounds__(256, 2)
void flash_kernel(const __half* __restrict__ qk16, const __half* __restrict__ vT,
                  __half* __restrict__ attn) {
    extern __shared__ __half smh[];
    const int h  = blockIdx.y;
    const int by = (gridDim.x - 1) - blockIdx.x;   // heavy tiles first
    const int tid  = threadIdx.x;
    const int wid  = tid >> 5;
    const int lane = tid & 31;
    const int g = lane >> 2;
    const int c = lane & 3;

    __half* Qs = smh + SM_Q;
    __half* Ks = smh + SM_K;
    __half* Vs = smh + SM_V;

    const __half* Qg = qk16 + h * HD;
    const __half* Kg = qk16 + HID + h * HD;
    const __half* Vg = vT + (size_t)h * HD * SEQ;

    const int ktmax = 4 * by + 4;

    // prologue: issue K/V tile 0 and Q tile
    for (int i = tid; i < 512; i += 256) {
        int r = i >> 4, ch = (i & 15) * 8;
        cp_async16(&Ks[r * QK_LDH + ch], Kg + (size_t)r * 2 * HID + ch);
    }
    for (int i = tid; i < 512; i += 256) {
        int r = i >> 2, ch = (i & 3) * 8;
        cp_async16(&Vs[r * VT_LDH + ch], Vg + (size_t)r * SEQ + ch);
    }
    for (int i = tid; i < 128 * 16; i += 256) {
        int r = i >> 4, ch = (i & 15) * 8;
        cp_async16(&Qs[r * QK_LDH + ch],
                   Qg + (size_t)(by * 128 + r) * 2 * HID + ch);
    }
    cp_commit();

    float o[16][4];
#pragma unroll
    for (int i = 0; i < 16; i++)
#pragma unroll
        for (int j = 0; j < 4; j++) o[i][j] = 0.0f;
    float m0 = -1e30f, m1 = -1e30f, l0 = 0.0f, l1 = 0.0f;

    const int row0 = by * 128 + wid * 16 + g;
    const int row1 = row0 + 8;

    for (int kt = 0; kt < ktmax; kt++) {
        cp_wait<0>();
        __syncthreads();
        if (kt + 1 < ktmax) {
            const int nb   = (kt + 1) & 1;
            const int key0 = (kt + 1) * KT;
            for (int i = tid; i < 512; i += 256) {
                int r = i >> 4, ch = (i & 15) * 8;
                cp_async16(&Ks[nb * KT * QK_LDH + r * QK_LDH + ch],
                           Kg + (size_t)(key0 + r) * 2 * HID + ch);
            }
            for (int i = tid; i < 512; i += 256) {
                int r = i >> 2, ch = (i & 3) * 8;
                cp_async16(&Vs[nb * HD * VT_LDH + r * VT_LDH + ch],
                           Vg + (size_t)r * SEQ + key0 + ch);
            }
        }
        cp_commit();

        const __half* Kbuf = Ks + (kt & 1) * KT * QK_LDH;
        const __half* Vbuf = Vs + (kt & 1) * HD * VT_LDH;
        const int key0 = kt * KT;

        // ---- S = Q K^T ----
        float s[4][4];
#pragma unroll
        for (int i = 0; i < 4; i++)
#pragma unroll
            for (int j = 0; j < 4; j++) s[i][j] = 0.0f;

        const __half* Qr0 = Qs + (wid * 16 + g) * QK_LDH;
        const __half* Qr1 = Qr0 + 8 * QK_LDH;
#pragma unroll
        for (int ks = 0; ks < 8; ks++) {
            uint2 a02 = *(const uint2*)(Qr0 + ks * 16 + 4 * c);
            uint2 a13 = *(const uint2*)(Qr1 + ks * 16 + 4 * c);
#pragma unroll
            for (int nt = 0; nt < 4; nt++) {
                uint2 b = *(const uint2*)(Kbuf + (nt * 8 + g) * QK_LDH + ks * 16 + 4 * c);
                mma_f16(s[nt], a02.x, a13.x, a02.y, a13.y, b.x, b.y);
            }
        }

        // ---- causal mask ----
        if (kt >= 4 * by) {
#pragma unroll
            for (int nt = 0; nt < 4; nt++) {
                int col = key0 + nt * 8 + 2 * c;
                if (col     > row0) s[nt][0] = -1e30f;
                if (col + 1 > row0) s[nt][1] = -1e30f;
                if (col     > row1) s[nt][2] = -1e30f;
                if (col + 1 > row1) s[nt][3] = -1e30f;
            }
        }

        // ---- online softmax (fp32), P packed into registers ----
        float tm0 = -1e30f, tm1 = -1e30f;
#pragma unroll
        for (int nt = 0; nt < 4; nt++) {
            tm0 = fmaxf(tm0, fmaxf(s[nt][0], s[nt][1]));
            tm1 = fmaxf(tm1, fmaxf(s[nt][2], s[nt][3]));
        }
        tm0 = fmaxf(tm0, __shfl_xor_sync(0xffffffffu, tm0, 1));
        tm0 = fmaxf(tm0, __shfl_xor_sync(0xffffffffu, tm0, 2));
        tm1 = fmaxf(tm1, __shfl_xor_sync(0xffffffffu, tm1, 1));
        tm1 = fmaxf(tm1, __shfl_xor_sync(0xffffffffu, tm1, 2));

        float mn0 = fmaxf(m0, tm0), mn1 = fmaxf(m1, tm1);
        float al0 = __expf(m0 - mn0), al1 = __expf(m1 - mn1);
        m0 = mn0; m1 = mn1;

        unsigned plo[4], phi[4];   // row g / row g+8 P fragments
        float sum0 = 0.0f, sum1 = 0.0f;
#pragma unroll
        for (int nt = 0; nt < 4; nt++) {
            float p0 = __expf(s[nt][0] - mn0);
            float p1 = __expf(s[nt][1] - mn0);
            float p2 = __expf(s[nt][2] - mn1);
            float p3 = __expf(s[nt][3] - mn1);
            sum0 += p0 + p1;
            sum1 += p2 + p3;
            plo[nt] = packh2(p0, p1);
            phi[nt] = packh2(p2, p3);
        }
        sum0 += __shfl_xor_sync(0xffffffffu, sum0, 1);
        sum0 += __shfl_xor_sync(0xffffffffu, sum0, 2);
        sum1 += __shfl_xor_sync(0xffffffffu, sum1, 1);
        sum1 += __shfl_xor_sync(0xffffffffu, sum1, 2);
        l0 = l0 * al0 + sum0;
        l1 = l1 * al1 + sum1;

        if (__ballot_sync(0xffffffffu, (al0 != 1.0f) || (al1 != 1.0f))) {
#pragma unroll
            for (int nt = 0; nt < 16; nt++) {
                o[nt][0] *= al0; o[nt][1] *= al0;
                o[nt][2] *= al1; o[nt][3] *= al1;
            }
        }

        // ---- O += P V  (P from registers; B from key-permuted V^T) ----
#pragma unroll
        for (int ks = 0; ks < 2; ks++) {
            unsigned a0 = plo[2 * ks], a1 = phi[2 * ks];
            unsigned a2 = plo[2 * ks + 1], a3 = phi[2 * ks + 1];
#pragma unroll
            for (int nt = 0; nt < 16; nt++) {
                uint2 b = *(const uint2*)(Vbuf + (nt * 8 + g) * VT_LDH + ks * 16 + 4 * c);
                mma_f16(o[nt], a0, a1, a2, a3, b.x, b.y);
            }
        }
    }

    float inv0 = 1.0f / l0;
    float inv1 = 1.0f / l1;
    __half* out0 = attn + (size_t)row0 * HID + h * HD;
    __half* out1 = attn + (size_t)row1 * HID + h * HD;
#pragma unroll
    for (int nt = 0; nt < 16; nt++) {
        *(__half2*)(out0 + nt * 8 + 2 * c) = __floats2half2_rn(o[nt][0] * inv0, o[nt][1] * inv0);
        *(__half2*)(out1 + nt * 8 + 2 * c) = __floats2half2_rn(o[nt][2] * inv1, o[nt][3] * inv1);
    }
}

// ---------------- launch ----------------
extern "C" void kernel_launch(void* const* d_in, const int* in_sizes, int n_in,
                              void* d_out, int out_size) {
    const float* hs   = (const float*)d_in[1];
    const float* Wqkv = (const float*)d_in[2];
    const float* bqkv = (const float*)d_in[3];
    const float* Wo   = (const float*)d_in[4];
    const float* bo   = (const float*)d_in[5];
    float* out = (float*)d_out;

    float* qkv;
    __half *attn16, *hs16, *wq16, *wo16, *qk16, *vT;
    cudaGetSymbolAddress((void**)&qkv,    g_qkv);
    cudaGetSymbolAddress((void**)&attn16, g_attn16);
    cudaGetSymbolAddress((void**)&hs16,   g_hs16);
    cudaGetSymbolAddress((void**)&wq16,   g_wq16);
    cudaGetSymbolAddress((void**)&wo16,   g_wo16);
    cudaGetSymbolAddress((void**)&qk16,   g_qk16);
    cudaGetSymbolAddress((void**)&vT,     g_vT);

    cudaFuncSetAttribute(flash_kernel, cudaFuncAttributeMaxDynamicSharedMemorySize,
                         FA_SMEM_BYTES);
    cudaFuncSetAttribute(gemm_f16_bias, cudaFuncAttributeMaxDynamicSharedMemorySize,
                         GEMM_SMEM_BYTES);

    // 0) fp16 pre-conversion of GEMM operands
    cvt_f16<<<(SEQ * HID / 4 + 255) / 256, 256>>>(hs, hs16, SEQ * HID / 4);
    cvt_f16<<<(int)(((size_t)HID * QKVN / 4 + 255) / 256), 256>>>(Wqkv, wq16,
                                                                  HID * QKVN / 4);
    cvt_f16<<<(HID * HID / 4 + 255) / 256, 256>>>(Wo, wo16, HID * HID / 4);

    // 1) QKV = hs @ Wqkv + bqkv
    gemm_f16_bias<<<dim3(QKVN / BN, SEQ / BM), 256, GEMM_SMEM_BYTES>>>(
        hs16, wq16, bqkv, qkv, HID, QKVN);
    // 2) RoPE -> fp16 q,k (dim-permuted, q scaled); V^T -> fp16 (key-perm)
    rope16_kernel<<<(SEQ * NH * 64 + 255) / 256, 256>>>(qkv, qk16);
    vT_kernel<<<dim3(SEQ / 32, HD / 32, NH), 256>>>(qkv, vT);
    // 3) fused flash attention (fp16 mma, register-resident P) -> g_attn16
    flash_kernel<<<dim3(SEQ / 128, NH), 256, FA_SMEM_BYTES>>>(qk16, vT, attn16);
    // 4) out = attn @ Wo + bo
    gemm_f16_bias<<<dim3(HID / BN, SEQ / BM), 256, GEMM_SMEM_BYTES>>>(
        attn16, wo16, bo, out, HID, HID);
}

// round 13
// speedup vs baseline: 8.4243x; 1.0312x over previous
#include <cuda_runtime.h>
#include <cuda_fp16.h>
#include <cstdint>
#include <mma.h>
#include <math.h>
#include <float.h>

using namespace nvcuda;

#define SEQ   2048
#define HID   4096
#define NH    32
#define HD    128
#define QKVN  12288   // 3*HID

// ---------------- scratch (no cudaMalloc allowed) ----------------
__device__ float  g_qkv[SEQ * QKVN];            // 100 MB (QKV GEMM out, fp32)
__device__ __half g_attn16[SEQ * HID];          // 17 MB  (flash out, O-proj in)
__device__ __half g_hs16[SEQ * HID];            // 17 MB  fp16(hs)
__device__ __half g_wq16[(size_t)HID * QKVN];   // 100 MB fp16(Wqkv) row-major
__device__ __half g_wo16[(size_t)HID * HID];    // 34 MB  fp16(Wo)   row-major
__device__ __half g_qk16[SEQ * 2 * HID];        // 34 MB  roped q,k fp16 (dim-permuted)
__device__ __half g_vT[(size_t)NH * HD * SEQ];  // 17 MB  V^T per head (key-permuted)

// ---------------- cp.async helpers ----------------
__device__ __forceinline__ void cp_async16(void* smem_dst, const void* gsrc) {
    unsigned s = (unsigned)__cvta_generic_to_shared(smem_dst);
    asm volatile("cp.async.cg.shared.global [%0], [%1], 16;\n" :: "r"(s), "l"(gsrc));
}
__device__ __forceinline__ void cp_commit() {
    asm volatile("cp.async.commit_group;\n");
}
template <int N> __device__ __forceinline__ void cp_wait() {
    asm volatile("cp.async.wait_group %0;\n" :: "n"(N));
}

// permutation within a 16-element chunk: pairs (2c,2c+1,2c+8,2c+9) adjacent
__device__ __forceinline__ int p16(int h) {
    return (h < 8) ? ((h >> 1) << 2) + (h & 1)
                   : (((h - 8) >> 1) << 2) + 2 + (h & 1);
}
__device__ __forceinline__ int permd(int d) {
    return (d & ~15) + p16(d & 15);
}

// ---------------- fp16 pre-convert ----------------
__global__ __launch_bounds__(256)
void cvt_f16(const float* __restrict__ in, __half* __restrict__ out, int n4) {
    int i = blockIdx.x * blockDim.x + threadIdx.x;
    if (i < n4) {
        float4 v = ((const float4*)in)[i];
        __half2 h0 = __floats2half2_rn(v.x, v.y);
        __half2 h1 = __floats2half2_rn(v.z, v.w);
        uint2 pk;
        pk.x = *(unsigned*)&h0;
        pk.y = *(unsigned*)&h1;
        ((uint2*)out)[i] = pk;
    }
}

// ================= fp16 tensor-core GEMM + bias =================
// Tile 128x128x64, 128 threads (4 warps, 2x2), warp tile 64x64 (high reuse).
// 3-stage cp.async pipeline, one barrier per K-iter, 2 CTAs/SM.
#define BM 128
#define BN 128
#define BK 64
#define A_LD 72      // halves (144B rows)
#define B_LD 136     // halves (272B rows)
#define STG 3
#define GEMM_SMEM_BYTES (STG * (BM * A_LD + BK * B_LD) * 2)   // 107520

__global__ __launch_bounds__(128, 2)
void gemm_f16_bias(const __half* __restrict__ A, const __half* __restrict__ B,
                   const float* __restrict__ bias, float* __restrict__ C,
                   int K, int N) {
    extern __shared__ __half gsm[];
    __half* Asm = gsm;                       // [STG][BM][A_LD]
    __half* Bsm = gsm + STG * BM * A_LD;     // [STG][BK][B_LD]

    const int tid  = threadIdx.x;
    const int wid  = tid >> 5;
    const int lane = tid & 31;
    const int warp_m = (wid & 1) * 64;       // 0,64
    const int warp_n = (wid >> 1) * 64;      // 0,64

    const int bx = blockIdx.x, by = blockIdx.y;

    const __half* Ag = A + (size_t)(by * BM) * K;
    const __half* Bg = B + bx * BN;

    // per stage: A 1024 16B-chunks (8/thread), B 1024 (8/thread)
    auto load_stage = [&](int s, int k0) {
        __half* As_s = Asm + s * BM * A_LD;
        __half* Bs_s = Bsm + s * BK * B_LD;
#pragma unroll
        for (int p = 0; p < 8; p++) {
            int idx = tid + p * 128;
            int ar = idx >> 3, ack = (idx & 7) * 8;
            cp_async16(&As_s[ar * A_LD + ack], Ag + (size_t)ar * K + k0 + ack);
        }
#pragma unroll
        for (int p = 0; p < 8; p++) {
            int idx = tid + p * 128;
            int br = idx >> 4, bck = (idx & 15) * 8;
            cp_async16(&Bs_s[br * B_LD + bck], Bg + (size_t)(k0 + br) * N + bck);
        }
    };

    wmma::fragment<wmma::accumulator, 16, 16, 16, float> acc[4][4];
#pragma unroll
    for (int i = 0; i < 4; i++)
#pragma unroll
        for (int j = 0; j < 4; j++) wmma::fill_fragment(acc[i][j], 0.0f);

    const int T = K / BK;

    load_stage(0, 0);  cp_commit();
    load_stage(1, BK); cp_commit();

    for (int t = 0; t < T; t++) {
        cp_wait<1>();          // stage t data arrived
        __syncthreads();       // all warps done with the stage being overwritten
        if (t + 2 < T) load_stage((t + 2) % 3, (t + 2) * BK);
        cp_commit();

        const int cur = t % 3;
        const __half* At = Asm + cur * BM * A_LD;
        const __half* Bt = Bsm + cur * BK * B_LD;
#pragma unroll
        for (int kk = 0; kk < BK; kk += 16) {
            wmma::fragment<wmma::matrix_a, 16, 16, 16, __half, wmma::row_major> af[4];
#pragma unroll
            for (int i = 0; i < 4; i++)
                wmma::load_matrix_sync(af[i], At + (warp_m + i * 16) * A_LD + kk, A_LD);
            // interleave B loads with mma so LDSM hides under HMMA
#pragma unroll
            for (int j = 0; j < 4; j++) {
                wmma::fragment<wmma::matrix_b, 16, 16, 16, __half, wmma::row_major> bf;
                wmma::load_matrix_sync(bf, Bt + kk * B_LD + warp_n + j * 16, B_LD);
#pragma unroll
                for (int i = 0; i < 4; i++)
                    wmma::mma_sync(acc[i][j], af[i], bf, acc[i][j]);
            }
        }
    }
    __syncthreads();

    // epilogue: stage each 16x16 patch through smem (as float), add fp32 bias
    float* epi = (float*)gsm + wid * 256;
#pragma unroll
    for (int i = 0; i < 4; i++) {
#pragma unroll
        for (int j = 0; j < 4; j++) {
            wmma::store_matrix_sync(epi, acc[i][j], 16, wmma::mem_row_major);
            __syncwarp();
            int r = lane >> 1;
            int c = (lane & 1) * 8;
            int grow = by * BM + warp_m + i * 16 + r;
            int gcol = bx * BN + warp_n + j * 16 + c;
            float4 v0 = *(float4*)&epi[r * 16 + c];
            float4 v1 = *(float4*)&epi[r * 16 + c + 4];
            const float* bp = bias + gcol;
            v0.x += bp[0]; v0.y += bp[1]; v0.z += bp[2]; v0.w += bp[3];
            v1.x += bp[4]; v1.y += bp[5]; v1.z += bp[6]; v1.w += bp[7];
            float* cp = C + (size_t)grow * N + gcol;
            *(float4*)cp = v0;
            *(float4*)(cp + 4) = v1;
            __syncwarp();
        }
    }
}

// ---------------- RoPE (fp32 math): fp32 qkv -> fp16 q,k --------------
__global__ __launch_bounds__(256)
void rope16_kernel(const float* __restrict__ qkv, __half* __restrict__ qk16) {
    int idx = blockIdx.x * blockDim.x + threadIdx.x;
    if (idx >= SEQ * NH * 64) return;
    int i = idx & 63;
    int h = (idx >> 6) & 31;
    int s = idx >> 11;
    float invf = expf(-0.14391156831212787f * (float)i);
    float f = (float)s * invf;
    float c  = cosf(f);
    float sn = sinf(f);
    const float scale = 0.08838834764831843f;
    const float* q = qkv + (size_t)s * QKVN + h * HD;
    const float* k = q + HID;
    __half* oq = qk16 + (size_t)s * 2 * HID + h * HD;
    __half* ok = oq + HID;
    float q1 = q[i], q2 = q[i + 64];
    oq[permd(i)]      = __float2half((q1 * c - q2 * sn) * scale);
    oq[permd(i + 64)] = __float2half((q2 * c + q1 * sn) * scale);
    float k1 = k[i], k2 = k[i + 64];
    ok[permd(i)]      = __float2half(k1 * c - k2 * sn);
    ok[permd(i + 64)] = __float2half(k2 * c + k1 * sn);
}

// ---------------- V transpose: fp32 v -> fp16 vT[h][d][seq] (key-perm) ---
__global__ __launch_bounds__(256)
void vT_kernel(const float* __restrict__ qkv, __half* __restrict__ vT) {
    __shared__ float tile[32][33];
    const int h  = blockIdx.z;
    const int s0 = blockIdx.x * 32;
    const int d0 = blockIdx.y * 32;
    int di = threadIdx.x & 31;
    int si = threadIdx.x >> 5;
#pragma unroll
    for (int j = 0; j < 4; j++) {
        int s = si + j * 8;
        tile[s][di] = qkv[(size_t)(s0 + s) * QKVN + 2 * HID + h * HD + d0 + di];
    }
    __syncthreads();
    int sj = threadIdx.x & 31;
    int wj = threadIdx.x >> 5;
    int sp = (sj & 16) + p16(sj & 15);
#pragma unroll
    for (int j = 0; j < 4; j++) {
        int d = wj + j * 8;
        vT[(size_t)(h * HD + d0 + d) * SEQ + s0 + sp] = __float2half(tile[sj][d]);
    }
}

// ================== fused flash attention (fp16 m16n8k16, register P) ====
#define KT 32
#define QK_LDH 144
#define VT_LDH 48
#define SM_Q 0
#define SM_K (128 * QK_LDH)
#define SM_V (SM_K + 2 * KT * QK_LDH)
#define FA_SMEM_HALVES (SM_V + 2 * HD * VT_LDH)
#define FA_SMEM_BYTES (FA_SMEM_HALVES * 2)   // 79872

__device__ __forceinline__ void mma_f16(float* d, unsigned a0, unsigned a1,
                                        unsigned a2, unsigned a3,
                                        unsigned b0, unsigned b1) {
    asm volatile(
        "mma.sync.aligned.m16n8k16.row.col.f32.f16.f16.f32 "
        "{%0,%1,%2,%3}, {%4,%5,%6,%7}, {%8,%9}, {%0,%1,%2,%3};\n"
        : "+f"(d[0]), "+f"(d[1]), "+f"(d[2]), "+f"(d[3])
        : "r"(a0), "r"(a1), "r"(a2), "r"(a3), "r"(b0), "r"(b1));
}
__device__ __forceinline__ unsigned packh2(float a, float b) {
    __half2 h = __floats2half2_rn(a, b);
    return *(unsigned*)&h;
}

__global__ __launch_bounds__(256, 2)
void flash_kernel(const __half* __restrict__ qk16, const __half* __restrict__ vT,
                  __half* __restrict__ attn) {
    extern __shared__ __half smh[];
    const int h  = blockIdx.y;
    const int by = (gridDim.x - 1) - blockIdx.x;   // heavy tiles first
    const int tid  = threadIdx.x;
    const int wid  = tid >> 5;
    const int lane = tid & 31;
    const int g = lane >> 2;
    const int c = lane & 3;

    __half* Qs = smh + SM_Q;
    __half* Ks = smh + SM_K;
    __half* Vs = smh + SM_V;

    const __half* Qg = qk16 + h * HD;
    const __half* Kg = qk16 + HID + h * HD;
    const __half* Vg = vT + (size_t)h * HD * SEQ;

    const int ktmax = 4 * by + 4;

    // prologue: issue K/V tile 0 and Q tile
    for (int i = tid; i < 512; i += 256) {
        int r = i >> 4, ch = (i & 15) * 8;
        cp_async16(&Ks[r * QK_LDH + ch], Kg + (size_t)r * 2 * HID + ch);
    }
    for (int i = tid; i < 512; i += 256) {
        int r = i >> 2, ch = (i & 3) * 8;
        cp_async16(&Vs[r * VT_LDH + ch], Vg + (size_t)r * SEQ + ch);
    }
    for (int i = tid; i < 128 * 16; i += 256) {
        int r = i >> 4, ch = (i & 15) * 8;
        cp_async16(&Qs[r * QK_LDH + ch],
                   Qg + (size_t)(by * 128 + r) * 2 * HID + ch);
    }
    cp_commit();

    float o[16][4];
#pragma unroll
    for (int i = 0; i < 16; i++)
#pragma unroll
        for (int j = 0; j < 4; j++) o[i][j] = 0.0f;
    float m0 = -1e30f, m1 = -1e30f, l0 = 0.0f, l1 = 0.0f;

    const int row0 = by * 128 + wid * 16 + g;
    const int row1 = row0 + 8;

    for (int kt = 0; kt < ktmax; kt++) {
        cp_wait<0>();
        __syncthreads();
        if (kt + 1 < ktmax) {
            const int nb   = (kt + 1) & 1;
            const int key0 = (kt + 1) * KT;
            for (int i = tid; i < 512; i += 256) {
                int r = i >> 4, ch = (i & 15) * 8;
                cp_async16(&Ks[nb * KT * QK_LDH + r * QK_LDH + ch],
                           Kg + (size_t)(key0 + r) * 2 * HID + ch);
            }
            for (int i = tid; i < 512; i += 256) {
                int r = i >> 2, ch = (i & 3) * 8;
                cp_async16(&Vs[nb * HD * VT_LDH + r * VT_LDH + ch],
                           Vg + (size_t)r * SEQ + key0 + ch);
            }
        }
        cp_commit();

        const __half* Kbuf = Ks + (kt & 1) * KT * QK_LDH;
        const __half* Vbuf = Vs + (kt & 1) * HD * VT_LDH;
        const int key0 = kt * KT;

        // ---- S = Q K^T ----
        float s[4][4];
#pragma unroll
        for (int i = 0; i < 4; i++)
#pragma unroll
            for (int j = 0; j < 4; j++) s[i][j] = 0.0f;

        const __half* Qr0 = Qs + (wid * 16 + g) * QK_LDH;
        const __half* Qr1 = Qr0 + 8 * QK_LDH;
#pragma unroll
        for (int ks = 0; ks < 8; ks++) {
            uint2 a02 = *(const uint2*)(Qr0 + ks * 16 + 4 * c);
            uint2 a13 = *(const uint2*)(Qr1 + ks * 16 + 4 * c);
#pragma unroll
            for (int nt = 0; nt < 4; nt++) {
                uint2 b = *(const uint2*)(Kbuf + (nt * 8 + g) * QK_LDH + ks * 16 + 4 * c);
                mma_f16(s[nt], a02.x, a13.x, a02.y, a13.y, b.x, b.y);
            }
        }

        // ---- causal mask ----
        if (kt >= 4 * by) {
#pragma unroll
            for (int nt = 0; nt < 4; nt++) {
                int col = key0 + nt * 8 + 2 * c;
                if (col     > row0) s[nt][0] = -1e30f;
                if (col + 1 > row0) s[nt][1] = -1e30f;
                if (col     > row1) s[nt][2] = -1e30f;
                if (col + 1 > row1) s[nt][3] = -1e30f;
            }
        }

        // ---- online softmax (fp32), P packed into registers ----
        float tm0 = -1e30f, tm1 = -1e30f;
#pragma unroll
        for (int nt = 0; nt < 4; nt++) {
            tm0 = fmaxf(tm0, fmaxf(s[nt][0], s[nt][1]));
            tm1 = fmaxf(tm1, fmaxf(s[nt][2], s[nt][3]));
        }
        tm0 = fmaxf(tm0, __shfl_xor_sync(0xffffffffu, tm0, 1));
        tm0 = fmaxf(tm0, __shfl_xor_sync(0xffffffffu, tm0, 2));
        tm1 = fmaxf(tm1, __shfl_xor_sync(0xffffffffu, tm1, 1));
        tm1 = fmaxf(tm1, __shfl_xor_sync(0xffffffffu, tm1, 2));

        float mn0 = fmaxf(m0, tm0), mn1 = fmaxf(m1, tm1);
        float al0 = __expf(m0 - mn0), al1 = __expf(m1 - mn1);
        m0 = mn0; m1 = mn1;

        unsigned plo[4], phi[4];
        float sum0 = 0.0f, sum1 = 0.0f;
#pragma unroll
        for (int nt = 0; nt < 4; nt++) {
            float p0 = __expf(s[nt][0] - mn0);
            float p1 = __expf(s[nt][1] - mn0);
            float p2 = __expf(s[nt][2] - mn1);
            float p3 = __expf(s[nt][3] - mn1);
            sum0 += p0 + p1;
            sum1 += p2 + p3;
            plo[nt] = packh2(p0, p1);
            phi[nt] = packh2(p2, p3);
        }
        sum0 += __shfl_xor_sync(0xffffffffu, sum0, 1);
        sum0 += __shfl_xor_sync(0xffffffffu, sum0, 2);
        sum1 += __shfl_xor_sync(0xffffffffu, sum1, 1);
        sum1 += __shfl_xor_sync(0xffffffffu, sum1, 2);
        l0 = l0 * al0 + sum0;
        l1 = l1 * al1 + sum1;

        if (__ballot_sync(0xffffffffu, (al0 != 1.0f) || (al1 != 1.0f))) {
#pragma unroll
            for (int nt = 0; nt < 16; nt++) {
                o[nt][0] *= al0; o[nt][1] *= al0;
                o[nt][2] *= al1; o[nt][3] *= al1;
            }
        }

        // ---- O += P V  (P from registers; B from key-permuted V^T) ----
#pragma unroll
        for (int ks = 0; ks < 2; ks++) {
            unsigned a0 = plo[2 * ks], a1 = phi[2 * ks];
            unsigned a2 = plo[2 * ks + 1], a3 = phi[2 * ks + 1];
#pragma unroll
            for (int nt = 0; nt < 16; nt++) {
                uint2 b = *(const uint2*)(Vbuf + (nt * 8 + g) * VT_LDH + ks * 16 + 4 * c);
                mma_f16(o[nt], a0, a1, a2, a3, b.x, b.y);
            }
        }
    }

    float inv0 = 1.0f / l0;
    float inv1 = 1.0f / l1;
    __half* out0 = attn + (size_t)row0 * HID + h * HD;
    __half* out1 = attn + (size_t)row1 * HID + h * HD;
#pragma unroll
    for (int nt = 0; nt < 16; nt++) {
        *(__half2*)(out0 + nt * 8 + 2 * c) = __floats2half2_rn(o[nt][0] * inv0, o[nt][1] * inv0);
        *(__half2*)(out1 + nt * 8 + 2 * c) = __floats2half2_rn(o[nt][2] * inv1, o[nt][3] * inv1);
    }
}

// ---------------- launch ----------------
extern "C" void kernel_launch(void* const* d_in, const int* in_sizes, int n_in,
                              void* d_out, int out_size) {
    const float* hs   = (const float*)d_in[1];
    const float* Wqkv = (const float*)d_in[2];
    const float* bqkv = (const float*)d_in[3];
    const float* Wo   = (const float*)d_in[4];
    const float* bo   = (const float*)d_in[5];
    float* out = (float*)d_out;

    float* qkv;
    __half *attn16, *hs16, *wq16, *wo16, *qk16, *vT;
    cudaGetSymbolAddress((void**)&qkv,    g_qkv);
    cudaGetSymbolAddress((void**)&attn16, g_attn16);
    cudaGetSymbolAddress((void**)&hs16,   g_hs16);
    cudaGetSymbolAddress((void**)&wq16,   g_wq16);
    cudaGetSymbolAddress((void**)&wo16,   g_wo16);
    cudaGetSymbolAddress((void**)&qk16,   g_qk16);
    cudaGetSymbolAddress((void**)&vT,     g_vT);

    cudaFuncSetAttribute(flash_kernel, cudaFuncAttributeMaxDynamicSharedMemorySize,
                         FA_SMEM_BYTES);
    cudaFuncSetAttribute(gemm_f16_bias, cudaFuncAttributeMaxDynamicSharedMemorySize,
                         GEMM_SMEM_BYTES);

    // 0) fp16 pre-conversion of GEMM operands
    cvt_f16<<<(SEQ * HID / 4 + 255) / 256, 256>>>(hs, hs16, SEQ * HID / 4);
    cvt_f16<<<(int)(((size_t)HID * QKVN / 4 + 255) / 256), 256>>>(Wqkv, wq16,
                                                                  HID * QKVN / 4);
    cvt_f16<<<(HID * HID / 4 + 255) / 256, 256>>>(Wo, wo16, HID * HID / 4);

    // 1) QKV = hs @ Wqkv + bqkv  (fp16 tensor cores, 64x64 warp tiles)
    gemm_f16_bias<<<dim3(QKVN / BN, SEQ / BM), 128, GEMM_SMEM_BYTES>>>(
        hs16, wq16, bqkv, qkv, HID, QKVN);
    // 2) RoPE -> fp16 q,k (dim-permuted, q scaled); V^T -> fp16 (key-perm)
    rope16_kernel<<<(SEQ * NH * 64 + 255) / 256, 256>>>(qkv, qk16);
    vT_kernel<<<dim3(SEQ / 32, HD / 32, NH), 256>>>(qkv, vT);
    // 3) fused flash attention (fp16 mma, register-resident P) -> g_attn16
    flash_kernel<<<dim3(SEQ / 128, NH), 256, FA_SMEM_BYTES>>>(qk16, vT, attn16);
    // 4) out = attn @ Wo + bo  (fp16 tensor cores, 64x64 warp tiles)
    gemm_f16_bias<<<dim3(HID / BN, SEQ / BM), 128, GEMM_SMEM_BYTES>>>(
        attn16, wo16, bo, out, HID, HID);
}

// round 14
// speedup vs baseline: 8.6686x; 1.0290x over previous
#include <cuda_runtime.h>
#include <cuda_fp16.h>
#include <cstdint>
#include <mma.h>
#include <math.h>
#include <float.h>

using namespace nvcuda;

#define SEQ   2048
#define HID   4096
#define NH    32
#define HD    128
#define QKVN  12288   // 3*HID

// ---------------- scratch (no cudaMalloc allowed) ----------------
__device__ __half g_attn16[SEQ * HID];          // flash out, O-proj in
__device__ __half g_hs16[SEQ * HID];            // fp16(hs)
__device__ __half g_wq16[(size_t)HID * QKVN];   // fp16(Wqkv) row-major
__device__ __half g_wo16[(size_t)HID * HID];    // fp16(Wo) row-major (cvt in flash tail)
__device__ __half g_qk16[SEQ * 2 * HID];        // roped q,k fp16 (dim-permuted)
__device__ __half g_vT[(size_t)NH * HD * SEQ];  // V^T per head (key-permuted)
__device__ float2 g_tab[SEQ * 64];              // rope (cos,sin) table

// ---------------- cp.async helpers ----------------
__device__ __forceinline__ void cp_async16(void* smem_dst, const void* gsrc) {
    unsigned s = (unsigned)__cvta_generic_to_shared(smem_dst);
    asm volatile("cp.async.cg.shared.global [%0], [%1], 16;\n" :: "r"(s), "l"(gsrc));
}
__device__ __forceinline__ void cp_commit() {
    asm volatile("cp.async.commit_group;\n");
}
template <int N> __device__ __forceinline__ void cp_wait() {
    asm volatile("cp.async.wait_group %0;\n" :: "n"(N));
}

// permutation within a 16-element chunk: pairs (2c,2c+1,2c+8,2c+9) adjacent
__device__ __forceinline__ constexpr int p16(int h) {
    return (h < 8) ? ((h >> 1) << 2) + (h & 1)
                   : (((h - 8) >> 1) << 2) + 2 + (h & 1);
}
__device__ __forceinline__ int permd(int d) {
    return (d & ~15) + p16(d & 15);
}

// ---------------- fp16 pre-convert ----------------
__global__ __launch_bounds__(256)
void cvt_f16(const float* __restrict__ in, __half* __restrict__ out, int n4) {
    int i = blockIdx.x * blockDim.x + threadIdx.x;
    if (i < n4) {
        float4 v = ((const float4*)in)[i];
        __half2 h0 = __floats2half2_rn(v.x, v.y);
        __half2 h1 = __floats2half2_rn(v.z, v.w);
        uint2 pk;
        pk.x = *(unsigned*)&h0;
        pk.y = *(unsigned*)&h1;
        ((uint2*)out)[i] = pk;
    }
}

// ---------------- rope table (identical fp32 math to prior rope kernel) --
__global__ __launch_bounds__(256)
void tab_kernel(float2* __restrict__ tab) {
    int idx = blockIdx.x * blockDim.x + threadIdx.x;
    if (idx >= SEQ * 64) return;
    int s = idx >> 6, i = idx & 63;
    float invf = expf(-0.14391156831212787f * (float)i);
    float f = (float)s * invf;
    tab[idx] = make_float2(cosf(f), sinf(f));
}

// ================= fp16 GEMM core (128x128x64, 4 warps 2x2, 64x64/warp) ==
#define BM 128
#define BN 128
#define BK 64
#define A_LD 72
#define B_LD 136
#define STG 3
#define GEMM_SMEM_BYTES (STG * (BM * A_LD + BK * B_LD) * 2)   // 107520

// ---- QKV GEMM with FUSED rope + V-transpose epilogue ----
__global__ __launch_bounds__(128, 2)
void gemm_qkv_fused(const __half* __restrict__ A, const __half* __restrict__ B,
                    const float* __restrict__ bias,
                    __half* __restrict__ qk16, __half* __restrict__ vT,
                    const float2* __restrict__ tab) {
    extern __shared__ __half gsm[];
    __half* Asm = gsm;
    __half* Bsm = gsm + STG * BM * A_LD;
    const int K = HID, N = QKVN;

    const int tid  = threadIdx.x;
    const int wid  = tid >> 5;
    const int warp_m = (wid & 1) * 64;
    const int warp_n = (wid >> 1) * 64;

    const int bx = blockIdx.x, by = blockIdx.y;

    const __half* Ag = A + (size_t)(by * BM) * K;
    const __half* Bg = B + bx * BN;

    auto load_stage = [&](int s, int k0) {
        __half* As_s = Asm + s * BM * A_LD;
        __half* Bs_s = Bsm + s * BK * B_LD;
#pragma unroll
        for (int p = 0; p < 8; p++) {
            int idx = tid + p * 128;
            int ar = idx >> 3, ack = (idx & 7) * 8;
            cp_async16(&As_s[ar * A_LD + ack], Ag + (size_t)ar * K + k0 + ack);
        }
#pragma unroll
        for (int p = 0; p < 8; p++) {
            int idx = tid + p * 128;
            int br = idx >> 4, bck = (idx & 15) * 8;
            cp_async16(&Bs_s[br * B_LD + bck], Bg + (size_t)(k0 + br) * N + bck);
        }
    };

    wmma::fragment<wmma::accumulator, 16, 16, 16, float> acc[4][4];
#pragma unroll
    for (int i = 0; i < 4; i++)
#pragma unroll
        for (int j = 0; j < 4; j++) wmma::fill_fragment(acc[i][j], 0.0f);

    const int T = K / BK;
    load_stage(0, 0);  cp_commit();
    load_stage(1, BK); cp_commit();

    for (int t = 0; t < T; t++) {
        cp_wait<1>();
        __syncthreads();
        if (t + 2 < T) load_stage((t + 2) % 3, (t + 2) * BK);
        cp_commit();

        const int cur = t % 3;
        const __half* At = Asm + cur * BM * A_LD;
        const __half* Bt = Bsm + cur * BK * B_LD;
#pragma unroll
        for (int kk = 0; kk < BK; kk += 16) {
            wmma::fragment<wmma::matrix_a, 16, 16, 16, __half, wmma::row_major> af[4];
#pragma unroll
            for (int i = 0; i < 4; i++)
                wmma::load_matrix_sync(af[i], At + (warp_m + i * 16) * A_LD + kk, A_LD);
#pragma unroll
            for (int j = 0; j < 4; j++) {
                wmma::fragment<wmma::matrix_b, 16, 16, 16, __half, wmma::row_major> bf;
                wmma::load_matrix_sync(bf, Bt + kk * B_LD + warp_n + j * 16, B_LD);
#pragma unroll
                for (int i = 0; i < 4; i++)
                    wmma::mma_sync(acc[i][j], af[i], bf, acc[i][j]);
            }
        }
    }
    __syncthreads();

    // ---- fused epilogue: stage full 128x128 tile fp32 in smem ----
    float* buf = (float*)gsm;   // [128][132]
#pragma unroll
    for (int i = 0; i < 4; i++)
#pragma unroll
        for (int j = 0; j < 4; j++)
            wmma::store_matrix_sync(buf + (warp_m + i * 16) * 132 + warp_n + j * 16,
                                    acc[i][j], 132, wmma::mem_row_major);
    __syncthreads();

    if (bx < 64) {
        // ---- q or k head tile: bias + rope + dim-permute -> qk16 fp16 ----
        const bool isQ = (bx < 32);
        const int h = isQ ? bx : bx - 32;
        const float scale = 0.08838834764831843f;
        int dp  = tid & 63;          // dim pair (dp, dp+64)
        int s0h = tid >> 6;          // 0 or 1
        const float b1 = bias[bx * 128 + dp];
        const float b2 = bias[bx * 128 + dp + 64];
        const int pd1 = permd(dp), pd2 = permd(dp + 64);
        __half* base = qk16 + (isQ ? 0 : HID) + h * HD;
        for (int s = s0h; s < 128; s += 2) {
            float f1 = buf[s * 132 + dp] + b1;
            float f2 = buf[s * 132 + dp + 64] + b2;
            int row = by * 128 + s;
            float2 cs = tab[row * 64 + dp];
            float o1 = f1 * cs.x - f2 * cs.y;
            float o2 = f2 * cs.x + f1 * cs.y;
            if (isQ) { o1 *= scale; o2 *= scale; }
            __half* dst = base + (size_t)row * 2 * HID;
            dst[pd1] = __float2half(o1);
            dst[pd2] = __float2half(o2);
        }
    } else {
        // ---- v head tile: bias + transpose + key-permute -> vT fp16 ----
        const int h = bx - 64;
        const int d = tid;           // 0..127 = head dim
        const float bv = bias[bx * 128 + d];
        __half* dst = vT + (size_t)(h * HD + d) * SEQ + by * 128;
        for (int sb = 0; sb < 128; sb += 16) {
            __align__(16) __half hb[16];
#pragma unroll
            for (int j = 0; j < 16; j++)
                hb[p16(j)] = __float2half(buf[(sb + j) * 132 + d] + bv);
            *(uint4*)(dst + sb)     = *(uint4*)&hb[0];
            *(uint4*)(dst + sb + 8) = *(uint4*)&hb[8];
        }
    }
}

// ---- generic fp16 GEMM + bias (fp32 out) for the O-projection ----
__global__ __launch_bounds__(128, 2)
void gemm_f16_bias(const __half* __restrict__ A, const __half* __restrict__ B,
                   const float* __restrict__ bias, float* __restrict__ C,
                   int K, int N) {
    extern __shared__ __half gsm[];
    __half* Asm = gsm;
    __half* Bsm = gsm + STG * BM * A_LD;

    const int tid  = threadIdx.x;
    const int wid  = tid >> 5;
    const int lane = tid & 31;
    const int warp_m = (wid & 1) * 64;
    const int warp_n = (wid >> 1) * 64;

    const int bx = blockIdx.x, by = blockIdx.y;

    const __half* Ag = A + (size_t)(by * BM) * K;
    const __half* Bg = B + bx * BN;

    auto load_stage = [&](int s, int k0) {
        __half* As_s = Asm + s * BM * A_LD;
        __half* Bs_s = Bsm + s * BK * B_LD;
#pragma unroll
        for (int p = 0; p < 8; p++) {
            int idx = tid + p * 128;
            int ar = idx >> 3, ack = (idx & 7) * 8;
            cp_async16(&As_s[ar * A_LD + ack], Ag + (size_t)ar * K + k0 + ack);
        }
#pragma unroll
        for (int p = 0; p < 8; p++) {
            int idx = tid + p * 128;
            int br = idx >> 4, bck = (idx & 15) * 8;
            cp_async16(&Bs_s[br * B_LD + bck], Bg + (size_t)(k0 + br) * N + bck);
        }
    };

    wmma::fragment<wmma::accumulator, 16, 16, 16, float> acc[4][4];
#pragma unroll
    for (int i = 0; i < 4; i++)
#pragma unroll
        for (int j = 0; j < 4; j++) wmma::fill_fragment(acc[i][j], 0.0f);

    const int T = K / BK;
    load_stage(0, 0);  cp_commit();
    load_stage(1, BK); cp_commit();

    for (int t = 0; t < T; t++) {
        cp_wait<1>();
        __syncthreads();
        if (t + 2 < T) load_stage((t + 2) % 3, (t + 2) * BK);
        cp_commit();

        const int cur = t % 3;
        const __half* At = Asm + cur * BM * A_LD;
        const __half* Bt = Bsm + cur * BK * B_LD;
#pragma unroll
        for (int kk = 0; kk < BK; kk += 16) {
            wmma::fragment<wmma::matrix_a, 16, 16, 16, __half, wmma::row_major> af[4];
#pragma unroll
            for (int i = 0; i < 4; i++)
                wmma::load_matrix_sync(af[i], At + (warp_m + i * 16) * A_LD + kk, A_LD);
#pragma unroll
            for (int j = 0; j < 4; j++) {
                wmma::fragment<wmma::matrix_b, 16, 16, 16, __half, wmma::row_major> bf;
                wmma::load_matrix_sync(bf, Bt + kk * B_LD + warp_n + j * 16, B_LD);
#pragma unroll
                for (int i = 0; i < 4; i++)
                    wmma::mma_sync(acc[i][j], af[i], bf, acc[i][j]);
            }
        }
    }
    __syncthreads();

    float* epi = (float*)gsm + wid * 256;
#pragma unroll
    for (int i = 0; i < 4; i++) {
#pragma unroll
        for (int j = 0; j < 4; j++) {
            wmma::store_matrix_sync(epi, acc[i][j], 16, wmma::mem_row_major);
            __syncwarp();
            int r = lane >> 1;
            int c = (lane & 1) * 8;
            int grow = by * BM + warp_m + i * 16 + r;
            int gcol = bx * BN + warp_n + j * 16 + c;
            float4 v0 = *(float4*)&epi[r * 16 + c];
            float4 v1 = *(float4*)&epi[r * 16 + c + 4];
            const float* bp = bias + gcol;
            v0.x += bp[0]; v0.y += bp[1]; v0.z += bp[2]; v0.w += bp[3];
            v1.x += bp[4]; v1.y += bp[5]; v1.z += bp[6]; v1.w += bp[7];
            float* cp = C + (size_t)grow * N + gcol;
            *(float4*)cp = v0;
            *(float4*)(cp + 4) = v1;
            __syncwarp();
        }
    }
}

// ================== fused flash attention (fp16 m16n8k16, register P) ====
#define KT 32
#define QK_LDH 144
#define VT_LDH 48
#define SM_Q 0
#define SM_K (128 * QK_LDH)
#define SM_V (SM_K + 2 * KT * QK_LDH)
#define FA_SMEM_HALVES (SM_V + 2 * HD * VT_LDH)
#define FA_SMEM_BYTES (FA_SMEM_HALVES * 2)   // 79872

__device__ __forceinline__ void mma_f16(float* d, unsigned a0, unsigned a1,
                                        unsigned a2, unsigned a3,
                                        unsigned b0, unsigned b1) {
    asm volatile(
        "mma.sync.aligned.m16n8k16.row.col.f32.f16.f16.f32 "
        "{%0,%1,%2,%3}, {%4,%5,%6,%7}, {%8,%9}, {%0,%1,%2,%3};\n"
        : "+f"(d[0]), "+f"(d[1]), "+f"(d[2]), "+f"(d[3])
        : "r"(a0), "r"(a1), "r"(a2), "r"(a3), "r"(b0), "r"(b1));
}
__device__ __forceinline__ unsigned packh2(float a, float b) {
    __half2 h = __floats2half2_rn(a, b);
    return *(unsigned*)&h;
}

__global__ __launch_bounds__(256, 2)
void flash_kernel(const __half* __restrict__ qk16, const __half* __restrict__ vT,
                  __half* __restrict__ attn,
                  const float* __restrict__ Wo, __half* __restrict__ wo16) {
    extern __shared__ __half smh[];
    const int h  = blockIdx.y;
    const int by = (gridDim.x - 1) - blockIdx.x;   // heavy tiles first
    const int tid  = threadIdx.x;
    const int wid  = tid >> 5;
    const int lane = tid & 31;
    const int g = lane >> 2;
    const int c = lane & 3;

    __half* Qs = smh + SM_Q;
    __half* Ks = smh + SM_K;
    __half* Vs = smh + SM_V;

    const __half* Qg = qk16 + h * HD;
    const __half* Kg = qk16 + HID + h * HD;
    const __half* Vg = vT + (size_t)h * HD * SEQ;

    const int ktmax = 4 * by + 4;

    for (int i = tid; i < 512; i += 256) {
        int r = i >> 4, ch = (i & 15) * 8;
        cp_async16(&Ks[r * QK_LDH + ch], Kg + (size_t)r * 2 * HID + ch);
    }
    for (int i = tid; i < 512; i += 256) {
        int r = i >> 2, ch = (i & 3) * 8;
        cp_async16(&Vs[r * VT_LDH + ch], Vg + (size_t)r * SEQ + ch);
    }
    for (int i = tid; i < 128 * 16; i += 256) {
        int r = i >> 4, ch = (i & 15) * 8;
        cp_async16(&Qs[r * QK_LDH + ch],
                   Qg + (size_t)(by * 128 + r) * 2 * HID + ch);
    }
    cp_commit();

    float o[16][4];
#pragma unroll
    for (int i = 0; i < 16; i++)
#pragma unroll
        for (int j = 0; j < 4; j++) o[i][j] = 0.0f;
    float m0 = -1e30f, m1 = -1e30f, l0 = 0.0f, l1 = 0.0f;

    const int row0 = by * 128 + wid * 16 + g;
    const int row1 = row0 + 8;

    for (int kt = 0; kt < ktmax; kt++) {
        cp_wait<0>();
        __syncthreads();
        if (kt + 1 < ktmax) {
            const int nb   = (kt + 1) & 1;
            const int key0 = (kt + 1) * KT;
            for (int i = tid; i < 512; i += 256) {
                int r = i >> 4, ch = (i & 15) * 8;
                cp_async16(&Ks[nb * KT * QK_LDH + r * QK_LDH + ch],
                           Kg + (size_t)(key0 + r) * 2 * HID + ch);
            }
            for (int i = tid; i < 512; i += 256) {
                int r = i >> 2, ch = (i & 3) * 8;
                cp_async16(&Vs[nb * HD * VT_LDH + r * VT_LDH + ch],
                           Vg + (size_t)r * SEQ + key0 + ch);
            }
        }
        cp_commit();

        const __half* Kbuf = Ks + (kt & 1) * KT * QK_LDH;
        const __half* Vbuf = Vs + (kt & 1) * HD * VT_LDH;
        const int key0 = kt * KT;

        float s[4][4];
#pragma unroll
        for (int i = 0; i < 4; i++)
#pragma unroll
            for (int j = 0; j < 4; j++) s[i][j] = 0.0f;

        const __half* Qr0 = Qs + (wid * 16 + g) * QK_LDH;
        const __half* Qr1 = Qr0 + 8 * QK_LDH;
#pragma unroll
        for (int ks = 0; ks < 8; ks++) {
            uint2 a02 = *(const uint2*)(Qr0 + ks * 16 + 4 * c);
            uint2 a13 = *(const uint2*)(Qr1 + ks * 16 + 4 * c);
#pragma unroll
            for (int nt = 0; nt < 4; nt++) {
                uint2 b = *(const uint2*)(Kbuf + (nt * 8 + g) * QK_LDH + ks * 16 + 4 * c);
                mma_f16(s[nt], a02.x, a13.x, a02.y, a13.y, b.x, b.y);
            }
        }

        if (kt >= 4 * by) {
#pragma unroll
            for (int nt = 0; nt < 4; nt++) {
                int col = key0 + nt * 8 + 2 * c;
                if (col     > row0) s[nt][0] = -1e30f;
                if (col + 1 > row0) s[nt][1] = -1e30f;
                if (col     > row1) s[nt][2] = -1e30f;
                if (col + 1 > row1) s[nt][3] = -1e30f;
            }
        }

        float tm0 = -1e30f, tm1 = -1e30f;
#pragma unroll
        for (int nt = 0; nt < 4; nt++) {
            tm0 = fmaxf(tm0, fmaxf(s[nt][0], s[nt][1]));
            tm1 = fmaxf(tm1, fmaxf(s[nt][2], s[nt][3]));
        }
        tm0 = fmaxf(tm0, __shfl_xor_sync(0xffffffffu, tm0, 1));
        tm0 = fmaxf(tm0, __shfl_xor_sync(0xffffffffu, tm0, 2));
        tm1 = fmaxf(tm1, __shfl_xor_sync(0xffffffffu, tm1, 1));
        tm1 = fmaxf(tm1, __shfl_xor_sync(0xffffffffu, tm1, 2));

        float mn0 = fmaxf(m0, tm0), mn1 = fmaxf(m1, tm1);
        float al0 = __expf(m0 - mn0), al1 = __expf(m1 - mn1);
        m0 = mn0; m1 = mn1;

        unsigned plo[4], phi[4];
        float sum0 = 0.0f, sum1 = 0.0f;
#pragma unroll
        for (int nt = 0; nt < 4; nt++) {
            float p0 = __expf(s[nt][0] - mn0);
            float p1 = __expf(s[nt][1] - mn0);
            float p2 = __expf(s[nt][2] - mn1);
            float p3 = __expf(s[nt][3] - mn1);
            sum0 += p0 + p1;
            sum1 += p2 + p3;
            plo[nt] = packh2(p0, p1);
            phi[nt] = packh2(p2, p3);
        }
        sum0 += __shfl_xor_sync(0xffffffffu, sum0, 1);
        sum0 += __shfl_xor_sync(0xffffffffu, sum0, 2);
        sum1 += __shfl_xor_sync(0xffffffffu, sum1, 1);
        sum1 += __shfl_xor_sync(0xffffffffu, sum1, 2);
        l0 = l0 * al0 + sum0;
        l1 = l1 * al1 + sum1;

        if (__ballot_sync(0xffffffffu, (al0 != 1.0f) || (al1 != 1.0f))) {
#pragma unroll
            for (int nt = 0; nt < 16; nt++) {
                o[nt][0] *= al0; o[nt][1] *= al0;
                o[nt][2] *= al1; o[nt][3] *= al1;
            }
        }

#pragma unroll
        for (int ks = 0; ks < 2; ks++) {
            unsigned a0 = plo[2 * ks], a1 = phi[2 * ks];
            unsigned a2 = plo[2 * ks + 1], a3 = phi[2 * ks + 1];
#pragma unroll
            for (int nt = 0; nt < 16; nt++) {
                uint2 b = *(const uint2*)(Vbuf + (nt * 8 + g) * VT_LDH + ks * 16 + 4 * c);
                mma_f16(o[nt], a0, a1, a2, a3, b.x, b.y);
            }
        }
    }

    float inv0 = 1.0f / l0;
    float inv1 = 1.0f / l1;
    __half* out0 = attn + (size_t)row0 * HID + h * HD;
    __half* out1 = attn + (size_t)row1 * HID + h * HD;
#pragma unroll
    for (int nt = 0; nt < 16; nt++) {
        *(__half2*)(out0 + nt * 8 + 2 * c) = __floats2half2_rn(o[nt][0] * inv0, o[nt][1] * inv0);
        *(__half2*)(out1 + nt * 8 + 2 * c) = __floats2half2_rn(o[nt][2] * inv1, o[nt][3] * inv1);
    }

    // ---- tail: convert this CTA's slice of Wo to fp16 (hidden under stragglers)
    {
        int cta = blockIdx.y * gridDim.x + blockIdx.x;   // 0..511
        const float4* src = (const float4*)Wo + (size_t)cta * 8192;
        uint2* dst = (uint2*)wo16 + (size_t)cta * 8192;
        for (int i = tid; i < 8192; i += 256) {
            float4 v = src[i];
            __half2 h0 = __floats2half2_rn(v.x, v.y);
            __half2 h1 = __floats2half2_rn(v.z, v.w);
            uint2 pk;
            pk.x = *(unsigned*)&h0;
            pk.y = *(unsigned*)&h1;
            dst[i] = pk;
        }
    }
}

// ---------------- launch ----------------
extern "C" void kernel_launch(void* const* d_in, const int* in_sizes, int n_in,
                              void* d_out, int out_size) {
    const float* hs   = (const float*)d_in[1];
    const float* Wqkv = (const float*)d_in[2];
    const float* bqkv = (const float*)d_in[3];
    const float* Wo   = (const float*)d_in[4];
    const float* bo   = (const float*)d_in[5];
    float* out = (float*)d_out;

    __half *attn16, *hs16, *wq16, *wo16, *qk16, *vT;
    float2* tab;
    cudaGetSymbolAddress((void**)&attn16, g_attn16);
    cudaGetSymbolAddress((void**)&hs16,   g_hs16);
    cudaGetSymbolAddress((void**)&wq16,   g_wq16);
    cudaGetSymbolAddress((void**)&wo16,   g_wo16);
    cudaGetSymbolAddress((void**)&qk16,   g_qk16);
    cudaGetSymbolAddress((void**)&vT,     g_vT);
    cudaGetSymbolAddress((void**)&tab,    g_tab);

    cudaFuncSetAttribute(flash_kernel, cudaFuncAttributeMaxDynamicSharedMemorySize,
                         FA_SMEM_BYTES);
    cudaFuncSetAttribute(gemm_qkv_fused, cudaFuncAttributeMaxDynamicSharedMemorySize,
                         GEMM_SMEM_BYTES);
    cudaFuncSetAttribute(gemm_f16_bias, cudaFuncAttributeMaxDynamicSharedMemorySize,
                         GEMM_SMEM_BYTES);

    // 0) rope table + fp16 pre-conversion of hs and Wqkv
    tab_kernel<<<(SEQ * 64 + 255) / 256, 256>>>(tab);
    cvt_f16<<<(SEQ * HID / 4 + 255) / 256, 256>>>(hs, hs16, SEQ * HID / 4);
    cvt_f16<<<(int)(((size_t)HID * QKVN / 4 + 255) / 256), 256>>>(Wqkv, wq16,
                                                                  HID * QKVN / 4);

    // 1) QKV GEMM with fused bias+rope+permute (q,k) and bias+transpose (v)
    gemm_qkv_fused<<<dim3(QKVN / BN, SEQ / BM), 128, GEMM_SMEM_BYTES>>>(
        hs16, wq16, bqkv, qk16, vT, tab);

    // 2) fused flash attention (+ Wo fp16 conversion in tail) -> attn16
    flash_kernel<<<dim3(SEQ / 128, NH), 256, FA_SMEM_BYTES>>>(
        qk16, vT, attn16, Wo, wo16);

    // 3) out = attn @ Wo + bo
    gemm_f16_bias<<<dim3(HID / BN, SEQ / BM), 128, GEMM_SMEM_BYTES>>>(
        attn16, wo16, bo, out, HID, HID);
}

// round 15
// speedup vs baseline: 8.6893x; 1.0024x over previous
#include <cuda_runtime.h>
#include <cuda_fp16.h>
#include <cstdint>
#include <mma.h>
#include <math.h>
#include <float.h>

using namespace nvcuda;

#define SEQ   2048
#define HID   4096
#define NH    32
#define HD    128
#define QKVN  12288   // 3*HID

// ---------------- scratch (no cudaMalloc allowed) ----------------
__device__ __half g_attn16[SEQ * HID];          // flash out, O-proj in
__device__ __half g_hs16[SEQ * HID];            // fp16(hs)
__device__ __half g_wq16[(size_t)HID * QKVN];   // fp16(Wqkv) row-major
__device__ __half g_wo16[(size_t)HID * HID];    // fp16(Wo) row-major (cvt in flash tail)
__device__ __half g_qk16[SEQ * 2 * HID];        // roped q,k fp16 (dim-permuted)
__device__ __half g_vT[(size_t)NH * HD * SEQ];  // V^T per head (key-permuted)
__device__ float2 g_tab[SEQ * 64];              // rope (cos,sin) table

// ---------------- cp.async helpers ----------------
__device__ __forceinline__ void cp_async16(void* smem_dst, const void* gsrc) {
    unsigned s = (unsigned)__cvta_generic_to_shared(smem_dst);
    asm volatile("cp.async.cg.shared.global [%0], [%1], 16;\n" :: "r"(s), "l"(gsrc));
}
__device__ __forceinline__ void cp_commit() {
    asm volatile("cp.async.commit_group;\n");
}
template <int N> __device__ __forceinline__ void cp_wait() {
    asm volatile("cp.async.wait_group %0;\n" :: "n"(N));
}

// permutation within a 16-element chunk: pairs (2c,2c+1,2c+8,2c+9) adjacent
__device__ __forceinline__ constexpr int p16(int h) {
    return (h < 8) ? ((h >> 1) << 2) + (h & 1)
                   : (((h - 8) >> 1) << 2) + 2 + (h & 1);
}
__device__ __forceinline__ int permd(int d) {
    return (d & ~15) + p16(d & 15);
}

// ---------------- fp16 pre-convert ----------------
__global__ __launch_bounds__(256)
void cvt_f16(const float* __restrict__ in, __half* __restrict__ out, int n4) {
    int i = blockIdx.x * blockDim.x + threadIdx.x;
    if (i < n4) {
        float4 v = ((const float4*)in)[i];
        __half2 h0 = __floats2half2_rn(v.x, v.y);
        __half2 h1 = __floats2half2_rn(v.z, v.w);
        uint2 pk;
        pk.x = *(unsigned*)&h0;
        pk.y = *(unsigned*)&h1;
        ((uint2*)out)[i] = pk;
    }
}

// ---------------- rope table (identical fp32 math) ----------------
__global__ __launch_bounds__(256)
void tab_kernel(float2* __restrict__ tab) {
    int idx = blockIdx.x * blockDim.x + threadIdx.x;
    if (idx >= SEQ * 64) return;
    int s = idx >> 6, i = idx & 63;
    float invf = expf(-0.14391156831212787f * (float)i);
    float f = (float)s * invf;
    tab[idx] = make_float2(cosf(f), sinf(f));
}

// ================= fp16 GEMM core (128x128x64, 4 warps 2x2, 64x64/warp) ==
// Grid: blockIdx.x = M tile (few), blockIdx.y = N tile (many) so resident
// CTAs share B columns and A stays L2-resident (B streamed once from DRAM).
#define BM 128
#define BN 128
#define BK 64
#define A_LD 72
#define B_LD 136
#define STG 3
#define GEMM_SMEM_BYTES (STG * (BM * A_LD + BK * B_LD) * 2)   // 107520

// ---- QKV GEMM with FUSED rope + V-transpose epilogue ----
__global__ __launch_bounds__(128, 2)
void gemm_qkv_fused(const __half* __restrict__ A, const __half* __restrict__ B,
                    const float* __restrict__ bias,
                    __half* __restrict__ qk16, __half* __restrict__ vT,
                    const float2* __restrict__ tab) {
    extern __shared__ __half gsm[];
    __half* Asm = gsm;
    __half* Bsm = gsm + STG * BM * A_LD;
    const int K = HID, N = QKVN;

    const int tid  = threadIdx.x;
    const int wid  = tid >> 5;
    const int warp_m = (wid & 1) * 64;
    const int warp_n = (wid >> 1) * 64;

    const int by = blockIdx.x;   // M tile (16)
    const int bx = blockIdx.y;   // N tile (96)

    const __half* Ag = A + (size_t)(by * BM) * K;
    const __half* Bg = B + bx * BN;

    auto load_stage = [&](int s, int k0) {
        __half* As_s = Asm + s * BM * A_LD;
        __half* Bs_s = Bsm + s * BK * B_LD;
#pragma unroll
        for (int p = 0; p < 8; p++) {
            int idx = tid + p * 128;
            int ar = idx >> 3, ack = (idx & 7) * 8;
            cp_async16(&As_s[ar * A_LD + ack], Ag + (size_t)ar * K + k0 + ack);
        }
#pragma unroll
        for (int p = 0; p < 8; p++) {
            int idx = tid + p * 128;
            int br = idx >> 4, bck = (idx & 15) * 8;
            cp_async16(&Bs_s[br * B_LD + bck], Bg + (size_t)(k0 + br) * N + bck);
        }
    };

    wmma::fragment<wmma::accumulator, 16, 16, 16, float> acc[4][4];
#pragma unroll
    for (int i = 0; i < 4; i++)
#pragma unroll
        for (int j = 0; j < 4; j++) wmma::fill_fragment(acc[i][j], 0.0f);

    const int T = K / BK;
    load_stage(0, 0);  cp_commit();
    load_stage(1, BK); cp_commit();

    for (int t = 0; t < T; t++) {
        cp_wait<1>();
        __syncthreads();
        if (t + 2 < T) load_stage((t + 2) % 3, (t + 2) * BK);
        cp_commit();

        const int cur = t % 3;
        const __half* At = Asm + cur * BM * A_LD;
        const __half* Bt = Bsm + cur * BK * B_LD;
#pragma unroll
        for (int kk = 0; kk < BK; kk += 16) {
            wmma::fragment<wmma::matrix_a, 16, 16, 16, __half, wmma::row_major> af[4];
#pragma unroll
            for (int i = 0; i < 4; i++)
                wmma::load_matrix_sync(af[i], At + (warp_m + i * 16) * A_LD + kk, A_LD);
            wmma::fragment<wmma::matrix_b, 16, 16, 16, __half, wmma::row_major> bf[2];
            wmma::load_matrix_sync(bf[0], Bt + kk * B_LD + warp_n, B_LD);
#pragma unroll
            for (int j = 0; j < 4; j++) {
                if (j < 3)
                    wmma::load_matrix_sync(bf[(j + 1) & 1],
                                           Bt + kk * B_LD + warp_n + (j + 1) * 16, B_LD);
#pragma unroll
                for (int i = 0; i < 4; i++)
                    wmma::mma_sync(acc[i][j], af[i], bf[j & 1], acc[i][j]);
            }
        }
    }
    __syncthreads();

    // ---- fused epilogue: stage full 128x128 tile fp32 in smem ----
    float* buf = (float*)gsm;   // [128][132]
#pragma unroll
    for (int i = 0; i < 4; i++)
#pragma unroll
        for (int j = 0; j < 4; j++)
            wmma::store_matrix_sync(buf + (warp_m + i * 16) * 132 + warp_n + j * 16,
                                    acc[i][j], 132, wmma::mem_row_major);
    __syncthreads();

    if (bx < 64) {
        // ---- q or k head tile: bias + rope + dim-permute -> qk16 fp16 ----
        const bool isQ = (bx < 32);
        const int h = isQ ? bx : bx - 32;
        const float scale = 0.08838834764831843f;
        int dp  = tid & 63;
        int s0h = tid >> 6;
        const float b1 = bias[bx * 128 + dp];
        const float b2 = bias[bx * 128 + dp + 64];
        const int pd1 = permd(dp), pd2 = permd(dp + 64);
        __half* base = qk16 + (isQ ? 0 : HID) + h * HD;
        for (int s = s0h; s < 128; s += 2) {
            float f1 = buf[s * 132 + dp] + b1;
            float f2 = buf[s * 132 + dp + 64] + b2;
            int row = by * 128 + s;
            float2 cs = tab[row * 64 + dp];
            float o1 = f1 * cs.x - f2 * cs.y;
            float o2 = f2 * cs.x + f1 * cs.y;
            if (isQ) { o1 *= scale; o2 *= scale; }
            __half* dst = base + (size_t)row * 2 * HID;
            dst[pd1] = __float2half(o1);
            dst[pd2] = __float2half(o2);
        }
    } else {
        // ---- v head tile: bias + transpose + key-permute -> vT fp16 ----
        const int h = bx - 64;
        const int d = tid;
        const float bv = bias[bx * 128 + d];
        __half* dst = vT + (size_t)(h * HD + d) * SEQ + by * 128;
        for (int sb = 0; sb < 128; sb += 16) {
            __align__(16) __half hb[16];
#pragma unroll
            for (int j = 0; j < 16; j++)
                hb[p16(j)] = __float2half(buf[(sb + j) * 132 + d] + bv);
            *(uint4*)(dst + sb)     = *(uint4*)&hb[0];
            *(uint4*)(dst + sb + 8) = *(uint4*)&hb[8];
        }
    }
}

// ---- generic fp16 GEMM + bias (fp32 out) for the O-projection ----
__global__ __launch_bounds__(128, 2)
void gemm_f16_bias(const __half* __restrict__ A, const __half* __restrict__ B,
                   const float* __restrict__ bias, float* __restrict__ C,
                   int K, int N) {
    extern __shared__ __half gsm[];
    __half* Asm = gsm;
    __half* Bsm = gsm + STG * BM * A_LD;

    const int tid  = threadIdx.x;
    const int wid  = tid >> 5;
    const int lane = tid & 31;
    const int warp_m = (wid & 1) * 64;
    const int warp_n = (wid >> 1) * 64;

    const int by = blockIdx.x;   // M tile
    const int bx = blockIdx.y;   // N tile

    const __half* Ag = A + (size_t)(by * BM) * K;
    const __half* Bg = B + bx * BN;

    auto load_stage = [&](int s, int k0) {
        __half* As_s = Asm + s * BM * A_LD;
        __half* Bs_s = Bsm + s * BK * B_LD;
#pragma unroll
        for (int p = 0; p < 8; p++) {
            int idx = tid + p * 128;
            int ar = idx >> 3, ack = (idx & 7) * 8;
            cp_async16(&As_s[ar * A_LD + ack], Ag + (size_t)ar * K + k0 + ack);
        }
#pragma unroll
        for (int p = 0; p < 8; p++) {
            int idx = tid + p * 128;
            int br = idx >> 4, bck = (idx & 15) * 8;
            cp_async16(&Bs_s[br * B_LD + bck], Bg + (size_t)(k0 + br) * N + bck);
        }
    };

    wmma::fragment<wmma::accumulator, 16, 16, 16, float> acc[4][4];
#pragma unroll
    for (int i = 0; i < 4; i++)
#pragma unroll
        for (int j = 0; j < 4; j++) wmma::fill_fragment(acc[i][j], 0.0f);

    const int T = K / BK;
    load_stage(0, 0);  cp_commit();
    load_stage(1, BK); cp_commit();

    for (int t = 0; t < T; t++) {
        cp_wait<1>();
        __syncthreads();
        if (t + 2 < T) load_stage((t + 2) % 3, (t + 2) * BK);
        cp_commit();

        const int cur = t % 3;
        const __half* At = Asm + cur * BM * A_LD;
        const __half* Bt = Bsm + cur * BK * B_LD;
#pragma unroll
        for (int kk = 0; kk < BK; kk += 16) {
            wmma::fragment<wmma::matrix_a, 16, 16, 16, __half, wmma::row_major> af[4];
#pragma unroll
            for (int i = 0; i < 4; i++)
                wmma::load_matrix_sync(af[i], At + (warp_m + i * 16) * A_LD + kk, A_LD);
            wmma::fragment<wmma::matrix_b, 16, 16, 16, __half, wmma::row_major> bf[2];
            wmma::load_matrix_sync(bf[0], Bt + kk * B_LD + warp_n, B_LD);
#pragma unroll
            for (int j = 0; j < 4; j++) {
                if (j < 3)
                    wmma::load_matrix_sync(bf[(j + 1) & 1],
                                           Bt + kk * B_LD + warp_n + (j + 1) * 16, B_LD);
#pragma unroll
                for (int i = 0; i < 4; i++)
                    wmma::mma_sync(acc[i][j], af[i], bf[j & 1], acc[i][j]);
            }
        }
    }
    __syncthreads();

    float* epi = (float*)gsm + wid * 256;
#pragma unroll
    for (int i = 0; i < 4; i++) {
#pragma unroll
        for (int j = 0; j < 4; j++) {
            wmma::store_matrix_sync(epi, acc[i][j], 16, wmma::mem_row_major);
            __syncwarp();
            int r = lane >> 1;
            int c = (lane & 1) * 8;
            int grow = by * BM + warp_m + i * 16 + r;
            int gcol = bx * BN + warp_n + j * 16 + c;
            float4 v0 = *(float4*)&epi[r * 16 + c];
            float4 v1 = *(float4*)&epi[r * 16 + c + 4];
            const float* bp = bias + gcol;
            v0.x += bp[0]; v0.y += bp[1]; v0.z += bp[2]; v0.w += bp[3];
            v1.x += bp[4]; v1.y += bp[5]; v1.z += bp[6]; v1.w += bp[7];
            float* cp = C + (size_t)grow * N + gcol;
            *(float4*)cp = v0;
            *(float4*)(cp + 4) = v1;
            __syncwarp();
        }
    }
}

// ================== fused flash attention (fp16 m16n8k16, register P) ====
#define KT 32
#define QK_LDH 144
#define VT_LDH 48
#define SM_Q 0
#define SM_K (128 * QK_LDH)
#define SM_V (SM_K + 2 * KT * QK_LDH)
#define FA_SMEM_HALVES (SM_V + 2 * HD * VT_LDH)
#define FA_SMEM_BYTES (FA_SMEM_HALVES * 2)   // 79872

__device__ __forceinline__ void mma_f16(float* d, unsigned a0, unsigned a1,
                                        unsigned a2, unsigned a3,
                                        unsigned b0, unsigned b1) {
    asm volatile(
        "mma.sync.aligned.m16n8k16.row.col.f32.f16.f16.f32 "
        "{%0,%1,%2,%3}, {%4,%5,%6,%7}, {%8,%9}, {%0,%1,%2,%3};\n"
        : "+f"(d[0]), "+f"(d[1]), "+f"(d[2]), "+f"(d[3])
        : "r"(a0), "r"(a1), "r"(a2), "r"(a3), "r"(b0), "r"(b1));
}
__device__ __forceinline__ unsigned packh2(float a, float b) {
    __half2 h = __floats2half2_rn(a, b);
    return *(unsigned*)&h;
}

__global__ __launch_bounds__(256, 2)
void flash_kernel(const __half* __restrict__ qk16, const __half* __restrict__ vT,
                  __half* __restrict__ attn,
                  const float* __restrict__ Wo, __half* __restrict__ wo16) {
    extern __shared__ __half smh[];
    const int h  = blockIdx.y;
    const int by = (gridDim.x - 1) - blockIdx.x;   // heavy tiles first
    const int tid  = threadIdx.x;
    const int wid  = tid >> 5;
    const int lane = tid & 31;
    const int g = lane >> 2;
    const int c = lane & 3;

    __half* Qs = smh + SM_Q;
    __half* Ks = smh + SM_K;
    __half* Vs = smh + SM_V;

    const __half* Qg = qk16 + h * HD;
    const __half* Kg = qk16 + HID + h * HD;
    const __half* Vg = vT + (size_t)h * HD * SEQ;

    const int ktmax = 4 * by + 4;

    for (int i = tid; i < 512; i += 256) {
        int r = i >> 4, ch = (i & 15) * 8;
        cp_async16(&Ks[r * QK_LDH + ch], Kg + (size_t)r * 2 * HID + ch);
    }
    for (int i = tid; i < 512; i += 256) {
        int r = i >> 2, ch = (i & 3) * 8;
        cp_async16(&Vs[r * VT_LDH + ch], Vg + (size_t)r * SEQ + ch);
    }
    for (int i = tid; i < 128 * 16; i += 256) {
        int r = i >> 4, ch = (i & 15) * 8;
        cp_async16(&Qs[r * QK_LDH + ch],
                   Qg + (size_t)(by * 128 + r) * 2 * HID + ch);
    }
    cp_commit();

    float o[16][4];
#pragma unroll
    for (int i = 0; i < 16; i++)
#pragma unroll
        for (int j = 0; j < 4; j++) o[i][j] = 0.0f;
    float m0 = -1e30f, m1 = -1e30f, l0 = 0.0f, l1 = 0.0f;

    const int row0 = by * 128 + wid * 16 + g;
    const int row1 = row0 + 8;

    for (int kt = 0; kt < ktmax; kt++) {
        cp_wait<0>();
        __syncthreads();
        if (kt + 1 < ktmax) {
            const int nb   = (kt + 1) & 1;
            const int key0 = (kt + 1) * KT;
            for (int i = tid; i < 512; i += 256) {
                int r = i >> 4, ch = (i & 15) * 8;
                cp_async16(&Ks[nb * KT * QK_LDH + r * QK_LDH + ch],
                           Kg + (size_t)(key0 + r) * 2 * HID + ch);
            }
            for (int i = tid; i < 512; i += 256) {
                int r = i >> 2, ch = (i & 3) * 8;
                cp_async16(&Vs[nb * HD * VT_LDH + r * VT_LDH + ch],
                           Vg + (size_t)r * SEQ + key0 + ch);
            }
        }
        cp_commit();

        const __half* Kbuf = Ks + (kt & 1) * KT * QK_LDH;
        const __half* Vbuf = Vs + (kt & 1) * HD * VT_LDH;
        const int key0 = kt * KT;

        float s[4][4];
#pragma unroll
        for (int i = 0; i < 4; i++)
#pragma unroll
            for (int j = 0; j < 4; j++) s[i][j] = 0.0f;

        const __half* Qr0 = Qs + (wid * 16 + g) * QK_LDH;
        const __half* Qr1 = Qr0 + 8 * QK_LDH;
#pragma unroll
        for (int ks = 0; ks < 8; ks++) {
            uint2 a02 = *(const uint2*)(Qr0 + ks * 16 + 4 * c);
            uint2 a13 = *(const uint2*)(Qr1 + ks * 16 + 4 * c);
#pragma unroll
            for (int nt = 0; nt < 4; nt++) {
                uint2 b = *(const uint2*)(Kbuf + (nt * 8 + g) * QK_LDH + ks * 16 + 4 * c);
                mma_f16(s[nt], a02.x, a13.x, a02.y, a13.y, b.x, b.y);
            }
        }

        if (kt >= 4 * by) {
#pragma unroll
            for (int nt = 0; nt < 4; nt++) {
                int col = key0 + nt * 8 + 2 * c;
                if (col     > row0) s[nt][0] = -1e30f;
                if (col + 1 > row0) s[nt][1] = -1e30f;
                if (col     > row1) s[nt][2] = -1e30f;
                if (col + 1 > row1) s[nt][3] = -1e30f;
            }
        }

        float tm0 = -1e30f, tm1 = -1e30f;
#pragma unroll
        for (int nt = 0; nt < 4; nt++) {
            tm0 = fmaxf(tm0, fmaxf(s[nt][0], s[nt][1]));
            tm1 = fmaxf(tm1, fmaxf(s[nt][2], s[nt][3]));
        }
        tm0 = fmaxf(tm0, __shfl_xor_sync(0xffffffffu, tm0, 1));
        tm0 = fmaxf(tm0, __shfl_xor_sync(0xffffffffu, tm0, 2));
        tm1 = fmaxf(tm1, __shfl_xor_sync(0xffffffffu, tm1, 1));
        tm1 = fmaxf(tm1, __shfl_xor_sync(0xffffffffu, tm1, 2));

        float mn0 = fmaxf(m0, tm0), mn1 = fmaxf(m1, tm1);
        float al0 = __expf(m0 - mn0), al1 = __expf(m1 - mn1);
        m0 = mn0; m1 = mn1;

        unsigned plo[4], phi[4];
        float sum0 = 0.0f, sum1 = 0.0f;
#pragma unroll
        for (int nt = 0; nt < 4; nt++) {
            float p0 = __expf(s[nt][0] - mn0);
            float p1 = __expf(s[nt][1] - mn0);
            float p2 = __expf(s[nt][2] - mn1);
            float p3 = __expf(s[nt][3] - mn1);
            sum0 += p0 + p1;
            sum1 += p2 + p3;
            plo[nt] = packh2(p0, p1);
            phi[nt] = packh2(p2, p3);
        }
        sum0 += __shfl_xor_sync(0xffffffffu, sum0, 1);
        sum0 += __shfl_xor_sync(0xffffffffu, sum0, 2);
        sum1 += __shfl_xor_sync(0xffffffffu, sum1, 1);
        sum1 += __shfl_xor_sync(0xffffffffu, sum1, 2);
        l0 = l0 * al0 + sum0;
        l1 = l1 * al1 + sum1;

        if (__ballot_sync(0xffffffffu, (al0 != 1.0f) || (al1 != 1.0f))) {
#pragma unroll
            for (int nt = 0; nt < 16; nt++) {
                o[nt][0] *= al0; o[nt][1] *= al0;
                o[nt][2] *= al1; o[nt][3] *= al1;
            }
        }

#pragma unroll
        for (int ks = 0; ks < 2; ks++) {
            unsigned a0 = plo[2 * ks], a1 = phi[2 * ks];
            unsigned a2 = plo[2 * ks + 1], a3 = phi[2 * ks + 1];
#pragma unroll
            for (int nt = 0; nt < 16; nt++) {
                uint2 b = *(const uint2*)(Vbuf + (nt * 8 + g) * VT_LDH + ks * 16 + 4 * c);
                mma_f16(o[nt], a0, a1, a2, a3, b.x, b.y);
            }
        }
    }

    float inv0 = 1.0f / l0;
    float inv1 = 1.0f / l1;
    __half* out0 = attn + (size_t)row0 * HID + h * HD;
    __half* out1 = attn + (size_t)row1 * HID + h * HD;
#pragma unroll
    for (int nt = 0; nt < 16; nt++) {
        *(__half2*)(out0 + nt * 8 + 2 * c) = __floats2half2_rn(o[nt][0] * inv0, o[nt][1] * inv0);
        *(__half2*)(out1 + nt * 8 + 2 * c) = __floats2half2_rn(o[nt][2] * inv1, o[nt][3] * inv1);
    }

    // ---- tail: convert this CTA's slice of Wo to fp16 ----
    {
        int cta = blockIdx.y * gridDim.x + blockIdx.x;   // 0..511
        const float4* src = (const float4*)Wo + (size_t)cta * 8192;
        uint2* dst = (uint2*)wo16 + (size_t)cta * 8192;
        for (int i = tid; i < 8192; i += 256) {
            float4 v = src[i];
            __half2 h0 = __floats2half2_rn(v.x, v.y);
            __half2 h1 = __floats2half2_rn(v.z, v.w);
            uint2 pk;
            pk.x = *(unsigned*)&h0;
            pk.y = *(unsigned*)&h1;
            dst[i] = pk;
        }
    }
}

// ---------------- launch ----------------
extern "C" void kernel_launch(void* const* d_in, const int* in_sizes, int n_in,
                              void* d_out, int out_size) {
    const float* hs   = (const float*)d_in[1];
    const float* Wqkv = (const float*)d_in[2];
    const float* bqkv = (const float*)d_in[3];
    const float* Wo   = (const float*)d_in[4];
    const float* bo   = (const float*)d_in[5];
    float* out = (float*)d_out;

    __half *attn16, *hs16, *wq16, *wo16, *qk16, *vT;
    float2* tab;
    cudaGetSymbolAddress((void**)&attn16, g_attn16);
    cudaGetSymbolAddress((void**)&hs16,   g_hs16);
    cudaGetSymbolAddress((void**)&wq16,   g_wq16);
    cudaGetSymbolAddress((void**)&wo16,   g_wo16);
    cudaGetSymbolAddress((void**)&qk16,   g_qk16);
    cudaGetSymbolAddress((void**)&vT,     g_vT);
    cudaGetSymbolAddress((void**)&tab,    g_tab);

    cudaFuncSetAttribute(flash_kernel, cudaFuncAttributeMaxDynamicSharedMemorySize,
                         FA_SMEM_BYTES);
    cudaFuncSetAttribute(gemm_qkv_fused, cudaFuncAttributeMaxDynamicSharedMemorySize,
                         GEMM_SMEM_BYTES);
    cudaFuncSetAttribute(gemm_f16_bias, cudaFuncAttributeMaxDynamicSharedMemorySize,
                         GEMM_SMEM_BYTES);

    // 0) rope table + fp16 pre-conversion of hs and Wqkv
    tab_kernel<<<(SEQ * 64 + 255) / 256, 256>>>(tab);
    cvt_f16<<<(SEQ * HID / 4 + 255) / 256, 256>>>(hs, hs16, SEQ * HID / 4);
    cvt_f16<<<(int)(((size_t)HID * QKVN / 4 + 255) / 256), 256>>>(Wqkv, wq16,
                                                                  HID * QKVN / 4);

    // 1) QKV GEMM with fused epilogue (grid: M-tiles fast, N-tiles slow)
    gemm_qkv_fused<<<dim3(SEQ / BM, QKVN / BN), 128, GEMM_SMEM_BYTES>>>(
        hs16, wq16, bqkv, qk16, vT, tab);

    // 2) fused flash attention (+ Wo fp16 conversion in tail) -> attn16
    flash_kernel<<<dim3(SEQ / 128, NH), 256, FA_SMEM_BYTES>>>(
        qk16, vT, attn16, Wo, wo16);

    // 3) out = attn @ Wo + bo
    gemm_f16_bias<<<dim3(SEQ / BM, HID / BN), 128, GEMM_SMEM_BYTES>>>(
        attn16, wo16, bo, out, HID, HID);
}

// round 16
// speedup vs baseline: 9.1697x; 1.0553x over previous
#include <cuda_runtime.h>
#include <cuda_fp16.h>
#include <cstdint>
#include <mma.h>
#include <math.h>
#include <float.h>

using namespace nvcuda;

#define SEQ   2048
#define HID   4096
#define NH    32
#define HD    128
#define QKVN  12288   // 3*HID

// ---------------- scratch (no cudaMalloc allowed) ----------------
__device__ __half g_attn16[SEQ * HID];          // flash out, O-proj in
__device__ __half g_hs16[SEQ * HID];            // fp16(hs)
__device__ __half g_wq16[(size_t)HID * QKVN];   // fp16(Wqkv) row-major
__device__ __half g_wo16[(size_t)HID * HID];    // fp16(Wo) row-major (cvt in flash tail)
__device__ __half g_qk16[SEQ * 2 * HID];        // roped q,k fp16 (dim-permuted)
__device__ __half g_vT[(size_t)NH * HD * SEQ];  // V^T per head (key-permuted)
__device__ float2 g_tab[SEQ * 64];              // rope (cos,sin) table

// ---------------- cp.async helpers ----------------
__device__ __forceinline__ void cp_async16(void* smem_dst, const void* gsrc) {
    unsigned s = (unsigned)__cvta_generic_to_shared(smem_dst);
    asm volatile("cp.async.cg.shared.global [%0], [%1], 16;\n" :: "r"(s), "l"(gsrc));
}
__device__ __forceinline__ void cp_commit() {
    asm volatile("cp.async.commit_group;\n");
}
template <int N> __device__ __forceinline__ void cp_wait() {
    asm volatile("cp.async.wait_group %0;\n" :: "n"(N));
}

// permutation within a 16-element chunk: pairs (2c,2c+1,2c+8,2c+9) adjacent
__device__ __forceinline__ constexpr int p16(int h) {
    return (h < 8) ? ((h >> 1) << 2) + (h & 1)
                   : (((h - 8) >> 1) << 2) + 2 + (h & 1);
}
__device__ __forceinline__ int permd(int d) {
    return (d & ~15) + p16(d & 15);
}

// ---------------- merged pre-pass: cvt(Wqkv) + cvt(hs) + rope table ------
#define WQ_BLOCKS 49152   // HID*QKVN/4/256
#define HS_BLOCKS 8192    // SEQ*HID/4/256
#define TAB_BLOCKS 512    // SEQ*64/256
__global__ __launch_bounds__(256)
void pre_kernel(const float* __restrict__ Wqkv, __half* __restrict__ wq16,
                const float* __restrict__ hs, __half* __restrict__ hs16,
                float2* __restrict__ tab) {
    int b = blockIdx.x;
    if (b < WQ_BLOCKS) {
        size_t i = (size_t)b * 256 + threadIdx.x;
        float4 v = ((const float4*)Wqkv)[i];
        __half2 h0 = __floats2half2_rn(v.x, v.y);
        __half2 h1 = __floats2half2_rn(v.z, v.w);
        uint2 pk;
        pk.x = *(unsigned*)&h0;
        pk.y = *(unsigned*)&h1;
        ((uint2*)wq16)[i] = pk;
    } else if (b < WQ_BLOCKS + HS_BLOCKS) {
        size_t i = (size_t)(b - WQ_BLOCKS) * 256 + threadIdx.x;
        float4 v = ((const float4*)hs)[i];
        __half2 h0 = __floats2half2_rn(v.x, v.y);
        __half2 h1 = __floats2half2_rn(v.z, v.w);
        uint2 pk;
        pk.x = *(unsigned*)&h0;
        pk.y = *(unsigned*)&h1;
        ((uint2*)hs16)[i] = pk;
    } else {
        int idx = (b - WQ_BLOCKS - HS_BLOCKS) * 256 + threadIdx.x;
        int s = idx >> 6, i = idx & 63;
        float invf = expf(-0.14391156831212787f * (float)i);
        float f = (float)s * invf;
        tab[idx] = make_float2(cosf(f), sinf(f));
    }
}

// ================= fp16 GEMM core (128x128x64, 4 warps 2x2, 64x64/warp) ==
#define BM 128
#define BN 128
#define BK 64
#define A_LD 72
#define B_LD 136
#define STG 3
#define GEMM_SMEM_BYTES (STG * (BM * A_LD + BK * B_LD) * 2)   // 107520

// ---- QKV GEMM with FUSED rope + V-transpose epilogue ----
__global__ __launch_bounds__(128, 2)
void gemm_qkv_fused(const __half* __restrict__ A, const __half* __restrict__ B,
                    const float* __restrict__ bias,
                    __half* __restrict__ qk16, __half* __restrict__ vT,
                    const float2* __restrict__ tab) {
    extern __shared__ __half gsm[];
    __half* Asm = gsm;
    __half* Bsm = gsm + STG * BM * A_LD;
    const int K = HID, N = QKVN;

    const int tid  = threadIdx.x;
    const int wid  = tid >> 5;
    const int warp_m = (wid & 1) * 64;
    const int warp_n = (wid >> 1) * 64;

    const int by = blockIdx.x;   // M tile (16)
    const int bx = blockIdx.y;   // N tile (96)

    const __half* Ag = A + (size_t)(by * BM) * K;
    const __half* Bg = B + bx * BN;

    auto load_stage = [&](int s, int k0) {
        __half* As_s = Asm + s * BM * A_LD;
        __half* Bs_s = Bsm + s * BK * B_LD;
#pragma unroll
        for (int p = 0; p < 8; p++) {
            int idx = tid + p * 128;
            int ar = idx >> 3, ack = (idx & 7) * 8;
            cp_async16(&As_s[ar * A_LD + ack], Ag + (size_t)ar * K + k0 + ack);
        }
#pragma unroll
        for (int p = 0; p < 8; p++) {
            int idx = tid + p * 128;
            int br = idx >> 4, bck = (idx & 15) * 8;
            cp_async16(&Bs_s[br * B_LD + bck], Bg + (size_t)(k0 + br) * N + bck);
        }
    };

    wmma::fragment<wmma::accumulator, 16, 16, 16, float> acc[4][4];
#pragma unroll
    for (int i = 0; i < 4; i++)
#pragma unroll
        for (int j = 0; j < 4; j++) wmma::fill_fragment(acc[i][j], 0.0f);

    const int T = K / BK;
    load_stage(0, 0);  cp_commit();
    load_stage(1, BK); cp_commit();

    for (int t = 0; t < T; t++) {
        cp_wait<1>();
        __syncthreads();
        if (t + 2 < T) load_stage((t + 2) % 3, (t + 2) * BK);
        cp_commit();

        const int cur = t % 3;
        const __half* At = Asm + cur * BM * A_LD;
        const __half* Bt = Bsm + cur * BK * B_LD;
#pragma unroll
        for (int kk = 0; kk < BK; kk += 16) {
            wmma::fragment<wmma::matrix_a, 16, 16, 16, __half, wmma::row_major> af[4];
#pragma unroll
            for (int i = 0; i < 4; i++)
                wmma::load_matrix_sync(af[i], At + (warp_m + i * 16) * A_LD + kk, A_LD);
            wmma::fragment<wmma::matrix_b, 16, 16, 16, __half, wmma::row_major> bf[2];
            wmma::load_matrix_sync(bf[0], Bt + kk * B_LD + warp_n, B_LD);
#pragma unroll
            for (int j = 0; j < 4; j++) {
                if (j < 3)
                    wmma::load_matrix_sync(bf[(j + 1) & 1],
                                           Bt + kk * B_LD + warp_n + (j + 1) * 16, B_LD);
#pragma unroll
                for (int i = 0; i < 4; i++)
                    wmma::mma_sync(acc[i][j], af[i], bf[j & 1], acc[i][j]);
            }
        }
    }
    __syncthreads();

    // ---- fused epilogue: stage full 128x128 tile fp32 in smem ----
    float* buf = (float*)gsm;   // [128][132]
#pragma unroll
    for (int i = 0; i < 4; i++)
#pragma unroll
        for (int j = 0; j < 4; j++)
            wmma::store_matrix_sync(buf + (warp_m + i * 16) * 132 + warp_n + j * 16,
                                    acc[i][j], 132, wmma::mem_row_major);
    __syncthreads();

    if (bx < 64) {
        const bool isQ = (bx < 32);
        const int h = isQ ? bx : bx - 32;
        const float scale = 0.08838834764831843f;
        int dp  = tid & 63;
        int s0h = tid >> 6;
        const float b1 = bias[bx * 128 + dp];
        const float b2 = bias[bx * 128 + dp + 64];
        const int pd1 = permd(dp), pd2 = permd(dp + 64);
        __half* base = qk16 + (isQ ? 0 : HID) + h * HD;
        for (int s = s0h; s < 128; s += 2) {
            float f1 = buf[s * 132 + dp] + b1;
            float f2 = buf[s * 132 + dp + 64] + b2;
            int row = by * 128 + s;
            float2 cs = tab[row * 64 + dp];
            float o1 = f1 * cs.x - f2 * cs.y;
            float o2 = f2 * cs.x + f1 * cs.y;
            if (isQ) { o1 *= scale; o2 *= scale; }
            __half* dst = base + (size_t)row * 2 * HID;
            dst[pd1] = __float2half(o1);
            dst[pd2] = __float2half(o2);
        }
    } else {
        const int h = bx - 64;
        const int d = tid;
        const float bv = bias[bx * 128 + d];
        __half* dst = vT + (size_t)(h * HD + d) * SEQ + by * 128;
        for (int sb = 0; sb < 128; sb += 16) {
            __align__(16) __half hb[16];
#pragma unroll
            for (int j = 0; j < 16; j++)
                hb[p16(j)] = __float2half(buf[(sb + j) * 132 + d] + bv);
            *(uint4*)(dst + sb)     = *(uint4*)&hb[0];
            *(uint4*)(dst + sb + 8) = *(uint4*)&hb[8];
        }
    }
}

// ---- generic fp16 GEMM + bias (fp32 out) for the O-projection ----
__global__ __launch_bounds__(128, 2)
void gemm_f16_bias(const __half* __restrict__ A, const __half* __restrict__ B,
                   const float* __restrict__ bias, float* __restrict__ C,
                   int K, int N) {
    extern __shared__ __half gsm[];
    __half* Asm = gsm;
    __half* Bsm = gsm + STG * BM * A_LD;

    const int tid  = threadIdx.x;
    const int wid  = tid >> 5;
    const int lane = tid & 31;
    const int warp_m = (wid & 1) * 64;
    const int warp_n = (wid >> 1) * 64;

    const int by = blockIdx.x;   // M tile
    const int bx = blockIdx.y;   // N tile

    const __half* Ag = A + (size_t)(by * BM) * K;
    const __half* Bg = B + bx * BN;

    auto load_stage = [&](int s, int k0) {
        __half* As_s = Asm + s * BM * A_LD;
        __half* Bs_s = Bsm + s * BK * B_LD;
#pragma unroll
        for (int p = 0; p < 8; p++) {
            int idx = tid + p * 128;
            int ar = idx >> 3, ack = (idx & 7) * 8;
            cp_async16(&As_s[ar * A_LD + ack], Ag + (size_t)ar * K + k0 + ack);
        }
#pragma unroll
        for (int p = 0; p < 8; p++) {
            int idx = tid + p * 128;
            int br = idx >> 4, bck = (idx & 15) * 8;
            cp_async16(&Bs_s[br * B_LD + bck], Bg + (size_t)(k0 + br) * N + bck);
        }
    };

    wmma::fragment<wmma::accumulator, 16, 16, 16, float> acc[4][4];
#pragma unroll
    for (int i = 0; i < 4; i++)
#pragma unroll
        for (int j = 0; j < 4; j++) wmma::fill_fragment(acc[i][j], 0.0f);

    const int T = K / BK;
    load_stage(0, 0);  cp_commit();
    load_stage(1, BK); cp_commit();

    for (int t = 0; t < T; t++) {
        cp_wait<1>();
        __syncthreads();
        if (t + 2 < T) load_stage((t + 2) % 3, (t + 2) * BK);
        cp_commit();

        const int cur = t % 3;
        const __half* At = Asm + cur * BM * A_LD;
        const __half* Bt = Bsm + cur * BK * B_LD;
#pragma unroll
        for (int kk = 0; kk < BK; kk += 16) {
            wmma::fragment<wmma::matrix_a, 16, 16, 16, __half, wmma::row_major> af[4];
#pragma unroll
            for (int i = 0; i < 4; i++)
                wmma::load_matrix_sync(af[i], At + (warp_m + i * 16) * A_LD + kk, A_LD);
            wmma::fragment<wmma::matrix_b, 16, 16, 16, __half, wmma::row_major> bf[2];
            wmma::load_matrix_sync(bf[0], Bt + kk * B_LD + warp_n, B_LD);
#pragma unroll
            for (int j = 0; j < 4; j++) {
                if (j < 3)
                    wmma::load_matrix_sync(bf[(j + 1) & 1],
                                           Bt + kk * B_LD + warp_n + (j + 1) * 16, B_LD);
#pragma unroll
                for (int i = 0; i < 4; i++)
                    wmma::mma_sync(acc[i][j], af[i], bf[j & 1], acc[i][j]);
            }
        }
    }
    __syncthreads();

    float* epi = (float*)gsm + wid * 256;
#pragma unroll
    for (int i = 0; i < 4; i++) {
#pragma unroll
        for (int j = 0; j < 4; j++) {
            wmma::store_matrix_sync(epi, acc[i][j], 16, wmma::mem_row_major);
            __syncwarp();
            int r = lane >> 1;
            int c = (lane & 1) * 8;
            int grow = by * BM + warp_m + i * 16 + r;
            int gcol = bx * BN + warp_n + j * 16 + c;
            float4 v0 = *(float4*)&epi[r * 16 + c];
            float4 v1 = *(float4*)&epi[r * 16 + c + 4];
            const float* bp = bias + gcol;
            v0.x += bp[0]; v0.y += bp[1]; v0.z += bp[2]; v0.w += bp[3];
            v1.x += bp[4]; v1.y += bp[5]; v1.z += bp[6]; v1.w += bp[7];
            float* cp = C + (size_t)grow * N + gcol;
            *(float4*)cp = v0;
            *(float4*)(cp + 4) = v1;
            __syncwarp();
        }
    }
}

// ================== fused flash attention (fp16 m16n8k16, register P) ====
// 1D grid of 512: id -> (by = 15 - id/32, h = id%32) so the heaviest tiles
// across ALL heads dispatch first (global heavy-first load balance).
#define KT 32
#define QK_LDH 144
#define VT_LDH 48
#define SM_Q 0
#define SM_K (128 * QK_LDH)
#define SM_V (SM_K + 2 * KT * QK_LDH)
#define FA_SMEM_HALVES (SM_V + 2 * HD * VT_LDH)
#define FA_SMEM_BYTES (FA_SMEM_HALVES * 2)   // 79872

__device__ __forceinline__ void mma_f16(float* d, unsigned a0, unsigned a1,
                                        unsigned a2, unsigned a3,
                                        unsigned b0, unsigned b1) {
    asm volatile(
        "mma.sync.aligned.m16n8k16.row.col.f32.f16.f16.f32 "
        "{%0,%1,%2,%3}, {%4,%5,%6,%7}, {%8,%9}, {%0,%1,%2,%3};\n"
        : "+f"(d[0]), "+f"(d[1]), "+f"(d[2]), "+f"(d[3])
        : "r"(a0), "r"(a1), "r"(a2), "r"(a3), "r"(b0), "r"(b1));
}
__device__ __forceinline__ unsigned packh2(float a, float b) {
    __half2 h = __floats2half2_rn(a, b);
    return *(unsigned*)&h;
}

__global__ __launch_bounds__(256, 2)
void flash_kernel(const __half* __restrict__ qk16, const __half* __restrict__ vT,
                  __half* __restrict__ attn,
                  const float* __restrict__ Wo, __half* __restrict__ wo16) {
    extern __shared__ __half smh[];
    const int id = blockIdx.x;
    const int by = 15 - (id >> 5);
    const int h  = id & 31;
    const int tid  = threadIdx.x;
    const int wid  = tid >> 5;
    const int lane = tid & 31;
    const int g = lane >> 2;
    const int c = lane & 3;

    __half* Qs = smh + SM_Q;
    __half* Ks = smh + SM_K;
    __half* Vs = smh + SM_V;

    const __half* Qg = qk16 + h * HD;
    const __half* Kg = qk16 + HID + h * HD;
    const __half* Vg = vT + (size_t)h * HD * SEQ;

    const int ktmax = 4 * by + 4;

    for (int i = tid; i < 512; i += 256) {
        int r = i >> 4, ch = (i & 15) * 8;
        cp_async16(&Ks[r * QK_LDH + ch], Kg + (size_t)r * 2 * HID + ch);
    }
    for (int i = tid; i < 512; i += 256) {
        int r = i >> 2, ch = (i & 3) * 8;
        cp_async16(&Vs[r * VT_LDH + ch], Vg + (size_t)r * SEQ + ch);
    }
    for (int i = tid; i < 128 * 16; i += 256) {
        int r = i >> 4, ch = (i & 15) * 8;
        cp_async16(&Qs[r * QK_LDH + ch],
                   Qg + (size_t)(by * 128 + r) * 2 * HID + ch);
    }
    cp_commit();

    float o[16][4];
#pragma unroll
    for (int i = 0; i < 16; i++)
#pragma unroll
        for (int j = 0; j < 4; j++) o[i][j] = 0.0f;
    float m0 = -1e30f, m1 = -1e30f, l0 = 0.0f, l1 = 0.0f;

    const int row0 = by * 128 + wid * 16 + g;
    const int row1 = row0 + 8;

    for (int kt = 0; kt < ktmax; kt++) {
        cp_wait<0>();
        __syncthreads();
        if (kt + 1 < ktmax) {
            const int nb   = (kt + 1) & 1;
            const int key0 = (kt + 1) * KT;
            for (int i = tid; i < 512; i += 256) {
                int r = i >> 4, ch = (i & 15) * 8;
                cp_async16(&Ks[nb * KT * QK_LDH + r * QK_LDH + ch],
                           Kg + (size_t)(key0 + r) * 2 * HID + ch);
            }
            for (int i = tid; i < 512; i += 256) {
                int r = i >> 2, ch = (i & 3) * 8;
                cp_async16(&Vs[nb * HD * VT_LDH + r * VT_LDH + ch],
                           Vg + (size_t)r * SEQ + key0 + ch);
            }
        }
        cp_commit();

        const __half* Kbuf = Ks + (kt & 1) * KT * QK_LDH;
        const __half* Vbuf = Vs + (kt & 1) * HD * VT_LDH;
        const int key0 = kt * KT;

        float s[4][4];
#pragma unroll
        for (int i = 0; i < 4; i++)
#pragma unroll
            for (int j = 0; j < 4; j++) s[i][j] = 0.0f;

        const __half* Qr0 = Qs + (wid * 16 + g) * QK_LDH;
        const __half* Qr1 = Qr0 + 8 * QK_LDH;
#pragma unroll
        for (int ks = 0; ks < 8; ks++) {
            uint2 a02 = *(const uint2*)(Qr0 + ks * 16 + 4 * c);
            uint2 a13 = *(const uint2*)(Qr1 + ks * 16 + 4 * c);
#pragma unroll
            for (int nt = 0; nt < 4; nt++) {
                uint2 b = *(const uint2*)(Kbuf + (nt * 8 + g) * QK_LDH + ks * 16 + 4 * c);
                mma_f16(s[nt], a02.x, a13.x, a02.y, a13.y, b.x, b.y);
            }
        }

        if (kt >= 4 * by) {
#pragma unroll
            for (int nt = 0; nt < 4; nt++) {
                int col = key0 + nt * 8 + 2 * c;
                if (col     > row0) s[nt][0] = -1e30f;
                if (col + 1 > row0) s[nt][1] = -1e30f;
                if (col     > row1) s[nt][2] = -1e30f;
                if (col + 1 > row1) s[nt][3] = -1e30f;
            }
        }

        float tm0 = -1e30f, tm1 = -1e30f;
#pragma unroll
        for (int nt = 0; nt < 4; nt++) {
            tm0 = fmaxf(tm0, fmaxf(s[nt][0], s[nt][1]));
            tm1 = fmaxf(tm1, fmaxf(s[nt][2], s[nt][3]));
        }
        tm0 = fmaxf(tm0, __shfl_xor_sync(0xffffffffu, tm0, 1));
        tm0 = fmaxf(tm0, __shfl_xor_sync(0xffffffffu, tm0, 2));
        tm1 = fmaxf(tm1, __shfl_xor_sync(0xffffffffu, tm1, 1));
        tm1 = fmaxf(tm1, __shfl_xor_sync(0xffffffffu, tm1, 2));

        float mn0 = fmaxf(m0, tm0), mn1 = fmaxf(m1, tm1);
        float al0 = __expf(m0 - mn0), al1 = __expf(m1 - mn1);
        m0 = mn0; m1 = mn1;

        unsigned plo[4], phi[4];
        float sum0 = 0.0f, sum1 = 0.0f;
#pragma unroll
        for (int nt = 0; nt < 4; nt++) {
            float p0 = __expf(s[nt][0] - mn0);
            float p1 = __expf(s[nt][1] - mn0);
            float p2 = __expf(s[nt][2] - mn1);
            float p3 = __expf(s[nt][3] - mn1);
            sum0 += p0 + p1;
            sum1 += p2 + p3;
            plo[nt] = packh2(p0, p1);
            phi[nt] = packh2(p2, p3);
        }
        sum0 += __shfl_xor_sync(0xffffffffu, sum0, 1);
        sum0 += __shfl_xor_sync(0xffffffffu, sum0, 2);
        sum1 += __shfl_xor_sync(0xffffffffu, sum1, 1);
        sum1 += __shfl_xor_sync(0xffffffffu, sum1, 2);
        l0 = l0 * al0 + sum0;
        l1 = l1 * al1 + sum1;

        if (__ballot_sync(0xffffffffu, (al0 != 1.0f) || (al1 != 1.0f))) {
#pragma unroll
            for (int nt = 0; nt < 16; nt++) {
                o[nt][0] *= al0; o[nt][1] *= al0;
                o[nt][2] *= al1; o[nt][3] *= al1;
            }
        }

#pragma unroll
        for (int ks = 0; ks < 2; ks++) {
            unsigned a0 = plo[2 * ks], a1 = phi[2 * ks];
            unsigned a2 = plo[2 * ks + 1], a3 = phi[2 * ks + 1];
#pragma unroll
            for (int nt = 0; nt < 16; nt++) {
                uint2 b = *(const uint2*)(Vbuf + (nt * 8 + g) * VT_LDH + ks * 16 + 4 * c);
                mma_f16(o[nt], a0, a1, a2, a3, b.x, b.y);
            }
        }
    }

    float inv0 = 1.0f / l0;
    float inv1 = 1.0f / l1;
    __half* out0 = attn + (size_t)row0 * HID + h * HD;
    __half* out1 = attn + (size_t)row1 * HID + h * HD;
#pragma unroll
    for (int nt = 0; nt < 16; nt++) {
        *(__half2*)(out0 + nt * 8 + 2 * c) = __floats2half2_rn(o[nt][0] * inv0, o[nt][1] * inv0);
        *(__half2*)(out1 + nt * 8 + 2 * c) = __floats2half2_rn(o[nt][2] * inv1, o[nt][3] * inv1);
    }

    // ---- tail: convert this CTA's slice of Wo to fp16 ----
    {
        const float4* src = (const float4*)Wo + (size_t)id * 8192;
        uint2* dst = (uint2*)wo16 + (size_t)id * 8192;
        for (int i = tid; i < 8192; i += 256) {
            float4 v = src[i];
            __half2 h0 = __floats2half2_rn(v.x, v.y);
            __half2 h1 = __floats2half2_rn(v.z, v.w);
            uint2 pk;
            pk.x = *(unsigned*)&h0;
            pk.y = *(unsigned*)&h1;
            dst[i] = pk;
        }
    }
}

// ---------------- launch ----------------
extern "C" void kernel_launch(void* const* d_in, const int* in_sizes, int n_in,
                              void* d_out, int out_size) {
    const float* hs   = (const float*)d_in[1];
    const float* Wqkv = (const float*)d_in[2];
    const float* bqkv = (const float*)d_in[3];
    const float* Wo   = (const float*)d_in[4];
    const float* bo   = (const float*)d_in[5];
    float* out = (float*)d_out;

    __half *attn16, *hs16, *wq16, *wo16, *qk16, *vT;
    float2* tab;
    cudaGetSymbolAddress((void**)&attn16, g_attn16);
    cudaGetSymbolAddress((void**)&hs16,   g_hs16);
    cudaGetSymbolAddress((void**)&wq16,   g_wq16);
    cudaGetSymbolAddress((void**)&wo16,   g_wo16);
    cudaGetSymbolAddress((void**)&qk16,   g_qk16);
    cudaGetSymbolAddress((void**)&vT,     g_vT);
    cudaGetSymbolAddress((void**)&tab,    g_tab);

    cudaFuncSetAttribute(flash_kernel, cudaFuncAttributeMaxDynamicSharedMemorySize,
                         FA_SMEM_BYTES);
    cudaFuncSetAttribute(gemm_qkv_fused, cudaFuncAttributeMaxDynamicSharedMemorySize,
                         GEMM_SMEM_BYTES);
    cudaFuncSetAttribute(gemm_f16_bias, cudaFuncAttributeMaxDynamicSharedMemorySize,
                         GEMM_SMEM_BYTES);

    // 0) merged pre-pass: cvt(Wqkv), cvt(hs), rope table
    pre_kernel<<<WQ_BLOCKS + HS_BLOCKS + TAB_BLOCKS, 256>>>(Wqkv, wq16, hs, hs16, tab);

    // 1) QKV GEMM with fused epilogue (grid: M-tiles fast, N-tiles slow)
    gemm_qkv_fused<<<dim3(SEQ / BM, QKVN / BN), 128, GEMM_SMEM_BYTES>>>(
        hs16, wq16, bqkv, qk16, vT, tab);

    // 2) fused flash attention, global heavy-first 1D grid (+ Wo cvt in tail)
    flash_kernel<<<512, 256, FA_SMEM_BYTES>>>(qk16, vT, attn16, Wo, wo16);

    // 3) out = attn @ Wo + bo
    gemm_f16_bias<<<dim3(SEQ / BM, HID / BN), 128, GEMM_SMEM_BYTES>>>(
        attn16, wo16, bo, out, HID, HID);
}